// round 1
// baseline (speedup 1.0000x reference)
#include <cuda_runtime.h>
#include <cstdint>
#include <cstddef>

// Problem constants
#define BB    2
#define SS    2048
#define DD    768
#define HH    12
#define HDD   64
#define DFF   3072
#define NROW  4096            // B*S

// ---------------------------------------------------------------------------
// Scratch (device globals: no allocation allowed)
// ---------------------------------------------------------------------------
__device__ float g_q[BB * HH * SS * HDD];     // head-major (b,h,s,hd)
__device__ float g_k[BB * HH * SS * HDD];
__device__ float g_v[BB * HH * SS * HDD];
__device__ float g_attn[NROW * DD];           // (row, d) layout
__device__ float g_res1[NROW * DD];
__device__ float g_y[NROW * DD];
__device__ float g_h1[NROW * DFF];
__device__ float g_z[NROW * DD];

// ---------------------------------------------------------------------------
// Tiled SGEMM: C[M,N] = A[M,K] @ B[K,N] + bias (+res) (+relu)
// 128x128 block tile, BK=8, 256 threads, 8x8 per thread.
// QKV=true reroutes output to head-major q/k/v layout.
// ---------------------------------------------------------------------------
template <bool RELU, bool QKV>
__global__ void __launch_bounds__(256) gemm_kernel(
    const float* __restrict__ A, const float* __restrict__ B,
    const float* __restrict__ bias, const float* __restrict__ res,
    float* __restrict__ C, int M, int N, int K)
{
    __shared__ float As[8][128];
    __shared__ float Bs[8][128];

    const int t  = threadIdx.x;
    const int bm = blockIdx.y * 128;
    const int bn = blockIdx.x * 128;

    const int arow = t >> 1;            // 0..127
    const int ak   = (t & 1) * 4;       // 0 or 4
    const int brow = t >> 5;            // 0..7
    const int bc   = (t & 31) * 4;      // 0..124

    const int tr = (t >> 4) << 3;       // 0..120
    const int tc = (t & 15) << 3;       // 0..120

    float acc[8][8];
#pragma unroll
    for (int i = 0; i < 8; i++)
#pragma unroll
        for (int j = 0; j < 8; j++) acc[i][j] = 0.f;

    for (int k0 = 0; k0 < K; k0 += 8) {
        float4 av = *(const float4*)(A + (size_t)(bm + arow) * K + k0 + ak);
        As[ak + 0][arow] = av.x;
        As[ak + 1][arow] = av.y;
        As[ak + 2][arow] = av.z;
        As[ak + 3][arow] = av.w;
        *(float4*)(&Bs[brow][bc]) =
            *(const float4*)(B + (size_t)(k0 + brow) * N + bn + bc);
        __syncthreads();

#pragma unroll
        for (int kk = 0; kk < 8; kk++) {
            float a[8], b[8];
            *(float4*)(a)     = *(const float4*)(&As[kk][tr]);
            *(float4*)(a + 4) = *(const float4*)(&As[kk][tr + 4]);
            *(float4*)(b)     = *(const float4*)(&Bs[kk][tc]);
            *(float4*)(b + 4) = *(const float4*)(&Bs[kk][tc + 4]);
#pragma unroll
            for (int i = 0; i < 8; i++)
#pragma unroll
                for (int j = 0; j < 8; j++)
                    acc[i][j] = fmaf(a[i], b[j], acc[i][j]);
        }
        __syncthreads();
    }

#pragma unroll
    for (int i = 0; i < 8; i++) {
        const int gr = bm + tr + i;
#pragma unroll
        for (int j = 0; j < 8; j++) {
            const int gc = bn + tc + j;
            float v = acc[i][j] + bias[gc];
            if (RELU) v = fmaxf(v, 0.f);
            if (res != nullptr) v += res[(size_t)gr * N + gc];
            if (QKV) {
                // row gr = b*S + s ; col gc = h*64 + hd -> (b,h,s,hd)
                const int b_  = gr >> 11;        // /S (S=2048)
                const int s_  = gr & 2047;
                const int h_  = gc >> 6;
                const int hd_ = gc & 63;
                C[(((size_t)(b_ * HH + h_) * SS) + s_) * HDD + hd_] = v;
            } else {
                C[(size_t)gr * N + gc] = v;
            }
        }
    }
}

// ---------------------------------------------------------------------------
// Flash attention: per (q-tile 64, h, b). 64 threads; each thread owns one
// q row (64 regs q + 64 regs o). k/v/alibi staged in dynamic smem.
// Causal: key tiles 0..qt only; diagonal tile masked j>t.
// ---------------------------------------------------------------------------
#define ATTN_SMEM ((4096 + 4096 + 64 * 68) * 4)   // 50176 bytes

__global__ void __launch_bounds__(64) attn_kernel(const float* __restrict__ alibi)
{
    extern __shared__ float sm[];
    float* sk = sm;              // 64x64 k tile
    float* sv = sm + 4096;       // 64x64 v tile
    float* ss = sm + 8192;       // 64x68 scores/alibi (padded)

    const int t  = threadIdx.x;
    const int qt = blockIdx.x;
    const int h  = blockIdx.y;
    const int b  = blockIdx.z;
    const int q0 = qt * 64;

    const float* qb = g_q + ((size_t)(b * HH + h) * SS + q0) * HDD;
    const float* kb = g_k + (size_t)(b * HH + h) * SS * HDD;
    const float* vb = g_v + (size_t)(b * HH + h) * SS * HDD;

    // stage q tile coalesced, then pull own row into registers
#pragma unroll
    for (int i = 0; i < 16; i++)
        ((float4*)sk)[i * 64 + t] = ((const float4*)qb)[i * 64 + t];
    __syncthreads();
    float4 q[16];
#pragma unroll
    for (int i = 0; i < 16; i++) q[i] = ((float4*)sk)[t * 16 + i];
    __syncthreads();

    float o[64];
#pragma unroll
    for (int d = 0; d < 64; d++) o[d] = 0.f;
    float m = -1e30f, l = 0.f;

    for (int kt = 0; kt <= qt; kt++) {
        const int k0 = kt * 64;
        const float4* kg = (const float4*)(kb + (size_t)k0 * HDD);
        const float4* vg = (const float4*)(vb + (size_t)k0 * HDD);
#pragma unroll
        for (int i = 0; i < 16; i++) {
            ((float4*)sk)[i * 64 + t] = kg[i * 64 + t];
            ((float4*)sv)[i * 64 + t] = vg[i * 64 + t];
        }
        const float* ab = alibi + ((size_t)h * SS + q0) * SS + k0;
#pragma unroll
        for (int i = 0; i < 16; i++) {
            const int f = i * 64 + t;
            const int r = f >> 4, c4 = f & 15;
            *(float4*)(ss + r * 68 + c4 * 4) =
                *(const float4*)(ab + (size_t)r * SS + c4 * 4);
        }
        __syncthreads();

        const bool diag = (kt == qt);
        float mt = -1e30f;
        float* srow = ss + t * 68;
        for (int j = 0; j < 64; j++) {
            const float4* kj = (const float4*)(sk + j * 64);
            float acc = 0.f;
#pragma unroll
            for (int i = 0; i < 16; i++) {
                const float4 kv = kj[i];
                acc = fmaf(q[i].x, kv.x, acc);
                acc = fmaf(q[i].y, kv.y, acc);
                acc = fmaf(q[i].z, kv.z, acc);
                acc = fmaf(q[i].w, kv.w, acc);
            }
            float sval = fmaf(acc, 0.125f, srow[j]);   // scale = 1/sqrt(64)
            if (diag && j > t) sval = -1e30f;
            srow[j] = sval;
            mt = fmaxf(mt, sval);
        }

        const float mn   = fmaxf(m, mt);
        const float corr = __expf(m - mn);
        l *= corr;
#pragma unroll
        for (int d = 0; d < 64; d++) o[d] *= corr;

        for (int j = 0; j < 64; j++) {
            const float p = __expf(srow[j] - mn);
            l += p;
            const float4* vj = (const float4*)(sv + j * 64);
#pragma unroll
            for (int i = 0; i < 16; i++) {
                const float4 vv = vj[i];
                o[4 * i + 0] = fmaf(p, vv.x, o[4 * i + 0]);
                o[4 * i + 1] = fmaf(p, vv.y, o[4 * i + 1]);
                o[4 * i + 2] = fmaf(p, vv.z, o[4 * i + 2]);
                o[4 * i + 3] = fmaf(p, vv.w, o[4 * i + 3]);
            }
        }
        m = mn;
        __syncthreads();
    }

    const float invl = 1.f / l;
#pragma unroll
    for (int i = 0; i < 16; i++)
        ((float4*)sk)[t * 16 + i] =
            make_float4(o[4 * i] * invl, o[4 * i + 1] * invl,
                        o[4 * i + 2] * invl, o[4 * i + 3] * invl);
    __syncthreads();

    float* ob = g_attn + ((size_t)b * SS + q0) * DD + h * HDD;
#pragma unroll
    for (int i = 0; i < 16; i++) {
        const int f = i * 64 + t;
        const int r = f >> 4, c4 = f & 15;
        *(float4*)(ob + (size_t)r * DD + c4 * 4) = ((float4*)sk)[f];
    }
}

// ---------------------------------------------------------------------------
// LayerNorm over last dim (768). One block (256 thr) per row.
// ---------------------------------------------------------------------------
__global__ void __launch_bounds__(256) ln_kernel(
    const float* __restrict__ in, const float* __restrict__ gw,
    const float* __restrict__ bw, float* __restrict__ out)
{
    const int row = blockIdx.x;
    const int t   = threadIdx.x;
    const float* p = in + (size_t)row * DD;

    const float v0 = p[t], v1 = p[t + 256], v2 = p[t + 512];
    float s  = v0 + v1 + v2;
    float sq = fmaf(v0, v0, fmaf(v1, v1, v2 * v2));

#pragma unroll
    for (int off = 16; off; off >>= 1) {
        s  += __shfl_down_sync(0xffffffffu, s, off);
        sq += __shfl_down_sync(0xffffffffu, sq, off);
    }
    __shared__ float rs[8], rq[8];
    __shared__ float mean_s, inv_s;
    const int w = t >> 5, lane = t & 31;
    if (lane == 0) { rs[w] = s; rq[w] = sq; }
    __syncthreads();
    if (t == 0) {
        float S = 0.f, Q = 0.f;
#pragma unroll
        for (int i = 0; i < 8; i++) { S += rs[i]; Q += rq[i]; }
        const float mean = S * (1.f / 768.f);
        const float var  = Q * (1.f / 768.f) - mean * mean;
        mean_s = mean;
        inv_s  = rsqrtf(var + 1e-5f);
    }
    __syncthreads();
    const float mean = mean_s, inv = inv_s;
    float* po = out + (size_t)row * DD;
    po[t]       = fmaf((v0 - mean) * inv, gw[t],       bw[t]);
    po[t + 256] = fmaf((v1 - mean) * inv, gw[t + 256], bw[t + 256]);
    po[t + 512] = fmaf((v2 - mean) * inv, gw[t + 512], bw[t + 512]);
}

// ---------------------------------------------------------------------------
// Launcher
// ---------------------------------------------------------------------------
extern "C" void kernel_launch(void* const* d_in, const int* in_sizes, int n_in,
                              void* d_out, int out_size)
{
    (void)in_sizes; (void)n_in; (void)out_size;
    const float* x     = (const float*)d_in[0];
    const float* alibi = (const float*)d_in[1];
    const float* Wq = (const float*)d_in[2];  const float* bq = (const float*)d_in[3];
    const float* Wk = (const float*)d_in[4];  const float* bk = (const float*)d_in[5];
    const float* Wv = (const float*)d_in[6];  const float* bv = (const float*)d_in[7];
    const float* Wo = (const float*)d_in[8];  const float* bo = (const float*)d_in[9];
    const float* W1 = (const float*)d_in[10]; const float* b1 = (const float*)d_in[11];
    const float* W2 = (const float*)d_in[12]; const float* b2 = (const float*)d_in[13];
    const float* g1w = (const float*)d_in[14]; const float* be1 = (const float*)d_in[15];
    const float* g2w = (const float*)d_in[16]; const float* be2 = (const float*)d_in[17];
    float* out = (float*)d_out;

    float *q, *k, *v, *at, *r1, *y, *h1, *z;
    cudaGetSymbolAddress((void**)&q,  g_q);
    cudaGetSymbolAddress((void**)&k,  g_k);
    cudaGetSymbolAddress((void**)&v,  g_v);
    cudaGetSymbolAddress((void**)&at, g_attn);
    cudaGetSymbolAddress((void**)&r1, g_res1);
    cudaGetSymbolAddress((void**)&y,  g_y);
    cudaGetSymbolAddress((void**)&h1, g_h1);
    cudaGetSymbolAddress((void**)&z,  g_z);

    cudaFuncSetAttribute(attn_kernel,
                         cudaFuncAttributeMaxDynamicSharedMemorySize, ATTN_SMEM);

    const dim3 blk(256);
    const dim3 gD(DD / 128, NROW / 128);      // (6, 32)
    const dim3 gF(DFF / 128, NROW / 128);     // (24, 32)

    // QKV projections -> head-major scratch
    gemm_kernel<false, true><<<gD, blk>>>(x, Wq, bq, nullptr, q, NROW, DD, DD);
    gemm_kernel<false, true><<<gD, blk>>>(x, Wk, bk, nullptr, k, NROW, DD, DD);
    gemm_kernel<false, true><<<gD, blk>>>(x, Wv, bv, nullptr, v, NROW, DD, DD);

    // causal flash attention with alibi
    attn_kernel<<<dim3(SS / 64, HH, BB), 64, ATTN_SMEM>>>(alibi);

    // output projection + residual, LN1
    gemm_kernel<false, false><<<gD, blk>>>(at, Wo, bo, x, r1, NROW, DD, DD);
    ln_kernel<<<NROW, 256>>>(r1, g1w, be1, y);

    // FFN: relu(y@W1+b1)@W2+b2 + y, LN2 -> out
    gemm_kernel<true,  false><<<gF, blk>>>(y, W1, b1, nullptr, h1, NROW, DFF, DD);
    gemm_kernel<false, false><<<gD, blk>>>(h1, W2, b2, y, z, NROW, DD, DFF);
    ln_kernel<<<NROW, 256>>>(z, g2w, be2, out);
}

// round 3
// speedup vs baseline: 1.7191x; 1.7191x over previous
#include <cuda_runtime.h>
#include <cuda_bf16.h>
#include <cstdint>
#include <cstddef>

// Problem constants
#define BB    2
#define SS    2048
#define DD    768
#define HH    12
#define HDD   64
#define DFF   3072
#define NROW  4096            // B*S

#define PADH  72              // smem row pitch in bf16 halfwords (conflict-free frags)

// ---------------------------------------------------------------------------
// Scratch (device globals: no allocation allowed)
// ---------------------------------------------------------------------------
__device__ float g_q[BB * HH * SS * HDD];
__device__ float g_k[BB * HH * SS * HDD];
__device__ float g_v[BB * HH * SS * HDD];
__device__ float g_attn[NROW * DD];
__device__ float g_res1[NROW * DD];
__device__ float g_y[NROW * DD];
__device__ float g_z[NROW * DD];

// bf16 hi/lo split activations
__device__ __nv_bfloat16 g_xhi[NROW * DD],  g_xlo[NROW * DD];
__device__ __nv_bfloat16 g_athi[NROW * DD], g_atlo[NROW * DD];
__device__ __nv_bfloat16 g_yhi[NROW * DD],  g_ylo[NROW * DD];
__device__ __nv_bfloat16 g_h1hi[NROW * DFF], g_h1lo[NROW * DFF];

// transposed bf16 hi/lo weights: [N, K] (K contiguous per output column)
__device__ __nv_bfloat16 g_wqThi[DD * DD],  g_wqTlo[DD * DD];
__device__ __nv_bfloat16 g_wkThi[DD * DD],  g_wkTlo[DD * DD];
__device__ __nv_bfloat16 g_wvThi[DD * DD],  g_wvTlo[DD * DD];
__device__ __nv_bfloat16 g_woThi[DD * DD],  g_woTlo[DD * DD];
__device__ __nv_bfloat16 g_w1Thi[DFF * DD], g_w1Tlo[DFF * DD];   // [3072, 768]
__device__ __nv_bfloat16 g_w2Thi[DD * DFF], g_w2Tlo[DD * DFF];   // [768, 3072]

// ---------------------------------------------------------------------------
// warp mma.sync m16n8k16 bf16 (non-'a' feature: legal on compute_103 PTX)
// ---------------------------------------------------------------------------
__device__ __forceinline__ void mma16816(float* d, const uint32_t* a,
                                         uint32_t b0, uint32_t b1) {
    asm volatile(
        "mma.sync.aligned.m16n8k16.row.col.f32.bf16.bf16.f32 "
        "{%0,%1,%2,%3}, {%4,%5,%6,%7}, {%8,%9}, {%0,%1,%2,%3};"
        : "+f"(d[0]), "+f"(d[1]), "+f"(d[2]), "+f"(d[3])
        : "r"(a[0]), "r"(a[1]), "r"(a[2]), "r"(a[3]), "r"(b0), "r"(b1));
}

// ---------------------------------------------------------------------------
// fp32 -> bf16 hi/lo split (vectorized x4)
// ---------------------------------------------------------------------------
__global__ void __launch_bounds__(256) convert_split(
    const float* __restrict__ in, __nv_bfloat16* __restrict__ hi,
    __nv_bfloat16* __restrict__ lo)
{
    const int i = blockIdx.x * 256 + threadIdx.x;
    float4 v = ((const float4*)in)[i];
    float f[4] = {v.x, v.y, v.z, v.w};
    __nv_bfloat16 h[4], l[4];
#pragma unroll
    for (int j = 0; j < 4; j++) {
        h[j] = __float2bfloat16(f[j]);
        l[j] = __float2bfloat16(f[j] - __bfloat162float(h[j]));
    }
    ((uint2*)hi)[i] = *(uint2*)h;
    ((uint2*)lo)[i] = *(uint2*)l;
}

// ---------------------------------------------------------------------------
// W[K,N] fp32 -> Wt[N,K] bf16 hi/lo (tiled transpose)
// ---------------------------------------------------------------------------
__global__ void __launch_bounds__(256) transpose_split(
    const float* __restrict__ W, __nv_bfloat16* __restrict__ Thi,
    __nv_bfloat16* __restrict__ Tlo, int K, int N)
{
    __shared__ float tile[32][33];
    const int k0 = blockIdx.y * 32, n0 = blockIdx.x * 32;
    const int tx = threadIdx.x, ty = threadIdx.y;   // (32, 8)
#pragma unroll
    for (int i = 0; i < 4; i++)
        tile[ty + 8 * i][tx] = W[(size_t)(k0 + ty + 8 * i) * N + n0 + tx];
    __syncthreads();
#pragma unroll
    for (int i = 0; i < 4; i++) {
        const float vv = tile[tx][ty + 8 * i];
        const __nv_bfloat16 h = __float2bfloat16(vv);
        const size_t o = (size_t)(n0 + ty + 8 * i) * K + k0 + tx;
        Thi[o] = h;
        Tlo[o] = __float2bfloat16(vv - __bfloat162float(h));
    }
}

// ---------------------------------------------------------------------------
// mma.sync GEMM: C[M,N] = A[M,K] @ Bt[N,K]^T, bf16 hi/lo 3-pass accumulation.
// 128x128 CTA tile, 8 warps (4x2), each warp 32x64, BK=64 single buffer.
// ---------------------------------------------------------------------------
#define M_QKV 0
#define M_WO  1
#define M_FF1 2
#define M_FF2 3

template <int MODE>
__global__ void __launch_bounds__(256) mma_gemm(
    const __nv_bfloat16* __restrict__ Ahi, const __nv_bfloat16* __restrict__ Alo,
    const __nv_bfloat16* __restrict__ Bhi, const __nv_bfloat16* __restrict__ Blo,
    const float* __restrict__ bias, const float* __restrict__ res,
    float* __restrict__ Cf, __nv_bfloat16* __restrict__ Chi,
    __nv_bfloat16* __restrict__ Clo, int M, int N, int K)
{
    __shared__ __nv_bfloat16 As[128 * PADH];
    __shared__ __nv_bfloat16 Bs[128 * PADH];

    const int t    = threadIdx.x;
    const int lane = t & 31, wid = t >> 5;
    const int wm   = (wid & 3) * 32;            // warp M offset (4 warps)
    const int wn   = (wid >> 2) * 64;           // warp N offset (2 warps)
    const int bm   = blockIdx.y * 128, bn = blockIdx.x * 128;
    const int g    = lane >> 2, tig = lane & 3;

    float acc[2][8][4];
#pragma unroll
    for (int i = 0; i < 2; i++)
#pragma unroll
        for (int j = 0; j < 8; j++)
#pragma unroll
            for (int c = 0; c < 4; c++) acc[i][j][c] = 0.f;

    const int KCN = K >> 6;                     // 64-wide K chunks per pass
    for (int it = 0; it < 3 * KCN; it++) {
        const int pass = it / KCN;
        const int k0   = (it - pass * KCN) << 6;
        const __nv_bfloat16* Ap = (pass == 2) ? Alo : Ahi;
        const __nv_bfloat16* Bp = (pass == 1) ? Blo : Bhi;

        __syncthreads();
#pragma unroll
        for (int i = 0; i < 4; i++) {
            const int f = t + 256 * i;          // 0..1023
            const int r = f >> 3, c8 = (f & 7) * 8;
            *(uint4*)(As + r * PADH + c8) =
                *(const uint4*)(Ap + (size_t)(bm + r) * K + k0 + c8);
            *(uint4*)(Bs + r * PADH + c8) =
                *(const uint4*)(Bp + (size_t)(bn + r) * K + k0 + c8);
        }
        __syncthreads();

#pragma unroll
        for (int kk = 0; kk < 64; kk += 16) {
            uint32_t a[2][4];
#pragma unroll
            for (int mt = 0; mt < 2; mt++) {
                const int row = wm + mt * 16 + g;
                a[mt][0] = *(const uint32_t*)(As + row * PADH + kk + 2 * tig);
                a[mt][1] = *(const uint32_t*)(As + (row + 8) * PADH + kk + 2 * tig);
                a[mt][2] = *(const uint32_t*)(As + row * PADH + kk + 8 + 2 * tig);
                a[mt][3] = *(const uint32_t*)(As + (row + 8) * PADH + kk + 8 + 2 * tig);
            }
#pragma unroll
            for (int nt = 0; nt < 8; nt++) {
                const int nrow = wn + nt * 8 + g;
                const uint32_t b0 =
                    *(const uint32_t*)(Bs + nrow * PADH + kk + 2 * tig);
                const uint32_t b1 =
                    *(const uint32_t*)(Bs + nrow * PADH + kk + 8 + 2 * tig);
                mma16816(acc[0][nt], a[0], b0, b1);
                mma16816(acc[1][nt], a[1], b0, b1);
            }
        }
    }

    // Epilogue straight from accum regs (fragment mapping known)
#pragma unroll
    for (int mt = 0; mt < 2; mt++) {
#pragma unroll
        for (int nt = 0; nt < 8; nt++) {
#pragma unroll
            for (int half = 0; half < 2; half++) {
                const int grow = bm + wm + mt * 16 + g + half * 8;
                const int gcol = bn + wn + nt * 8 + 2 * tig;
                float v0 = acc[mt][nt][half * 2 + 0] + bias[gcol];
                float v1 = acc[mt][nt][half * 2 + 1] + bias[gcol + 1];
                if (MODE == M_FF1) {
                    v0 = fmaxf(v0, 0.f);
                    v1 = fmaxf(v1, 0.f);
                    const __nv_bfloat16 h0 = __float2bfloat16(v0);
                    const __nv_bfloat16 h1 = __float2bfloat16(v1);
                    __nv_bfloat16 hh[2] = {h0, h1};
                    __nv_bfloat16 ll[2] = {
                        __float2bfloat16(v0 - __bfloat162float(h0)),
                        __float2bfloat16(v1 - __bfloat162float(h1))};
                    *(uint32_t*)(Chi + (size_t)grow * N + gcol) = *(uint32_t*)hh;
                    *(uint32_t*)(Clo + (size_t)grow * N + gcol) = *(uint32_t*)ll;
                } else if (MODE == M_QKV) {
                    const int b_ = grow >> 11, s_ = grow & 2047;
                    const int h_ = gcol >> 6,  hd = gcol & 63;
                    float* dst = Cf + (((size_t)(b_ * HH + h_) * SS) + s_) * HDD + hd;
                    dst[0] = v0;
                    dst[1] = v1;
                } else {
                    const size_t o = (size_t)grow * N + gcol;
                    v0 += res[o];
                    v1 += res[o + 1];
                    *(float2*)(Cf + o) = make_float2(v0, v1);
                }
            }
        }
    }
}

// ---------------------------------------------------------------------------
// Flash attention (unchanged from R1 — round-3 target)
// ---------------------------------------------------------------------------
#define ATTN_SMEM ((4096 + 4096 + 64 * 68) * 4)

__global__ void __launch_bounds__(64) attn_kernel(const float* __restrict__ alibi)
{
    extern __shared__ float sm[];
    float* sk = sm;
    float* sv = sm + 4096;
    float* ss = sm + 8192;

    const int t  = threadIdx.x;
    const int qt = blockIdx.x;
    const int h  = blockIdx.y;
    const int b  = blockIdx.z;
    const int q0 = qt * 64;

    const float* qb = g_q + ((size_t)(b * HH + h) * SS + q0) * HDD;
    const float* kb = g_k + (size_t)(b * HH + h) * SS * HDD;
    const float* vb = g_v + (size_t)(b * HH + h) * SS * HDD;

#pragma unroll
    for (int i = 0; i < 16; i++)
        ((float4*)sk)[i * 64 + t] = ((const float4*)qb)[i * 64 + t];
    __syncthreads();
    float4 q[16];
#pragma unroll
    for (int i = 0; i < 16; i++) q[i] = ((float4*)sk)[t * 16 + i];
    __syncthreads();

    float o[64];
#pragma unroll
    for (int d = 0; d < 64; d++) o[d] = 0.f;
    float m = -1e30f, l = 0.f;

    for (int kt = 0; kt <= qt; kt++) {
        const int k0 = kt * 64;
        const float4* kg = (const float4*)(kb + (size_t)k0 * HDD);
        const float4* vg = (const float4*)(vb + (size_t)k0 * HDD);
#pragma unroll
        for (int i = 0; i < 16; i++) {
            ((float4*)sk)[i * 64 + t] = kg[i * 64 + t];
            ((float4*)sv)[i * 64 + t] = vg[i * 64 + t];
        }
        const float* ab = alibi + ((size_t)h * SS + q0) * SS + k0;
#pragma unroll
        for (int i = 0; i < 16; i++) {
            const int f = i * 64 + t;
            const int r = f >> 4, c4 = f & 15;
            *(float4*)(ss + r * 68 + c4 * 4) =
                *(const float4*)(ab + (size_t)r * SS + c4 * 4);
        }
        __syncthreads();

        const bool diag = (kt == qt);
        float mt = -1e30f;
        float* srow = ss + t * 68;
        for (int j = 0; j < 64; j++) {
            const float4* kj = (const float4*)(sk + j * 64);
            float acc = 0.f;
#pragma unroll
            for (int i = 0; i < 16; i++) {
                const float4 kv = kj[i];
                acc = fmaf(q[i].x, kv.x, acc);
                acc = fmaf(q[i].y, kv.y, acc);
                acc = fmaf(q[i].z, kv.z, acc);
                acc = fmaf(q[i].w, kv.w, acc);
            }
            float sval = fmaf(acc, 0.125f, srow[j]);
            if (diag && j > t) sval = -1e30f;
            srow[j] = sval;
            mt = fmaxf(mt, sval);
        }

        const float mn   = fmaxf(m, mt);
        const float corr = __expf(m - mn);
        l *= corr;
#pragma unroll
        for (int d = 0; d < 64; d++) o[d] *= corr;

        for (int j = 0; j < 64; j++) {
            const float p = __expf(srow[j] - mn);
            l += p;
            const float4* vj = (const float4*)(sv + j * 64);
#pragma unroll
            for (int i = 0; i < 16; i++) {
                const float4 vv = vj[i];
                o[4 * i + 0] = fmaf(p, vv.x, o[4 * i + 0]);
                o[4 * i + 1] = fmaf(p, vv.y, o[4 * i + 1]);
                o[4 * i + 2] = fmaf(p, vv.z, o[4 * i + 2]);
                o[4 * i + 3] = fmaf(p, vv.w, o[4 * i + 3]);
            }
        }
        m = mn;
        __syncthreads();
    }

    const float invl = 1.f / l;
#pragma unroll
    for (int i = 0; i < 16; i++)
        ((float4*)sk)[t * 16 + i] =
            make_float4(o[4 * i] * invl, o[4 * i + 1] * invl,
                        o[4 * i + 2] * invl, o[4 * i + 3] * invl);
    __syncthreads();

    float* ob = g_attn + ((size_t)b * SS + q0) * DD + h * HDD;
#pragma unroll
    for (int i = 0; i < 16; i++) {
        const int f = i * 64 + t;
        const int r = f >> 4, c4 = f & 15;
        *(float4*)(ob + (size_t)r * DD + c4 * 4) = ((float4*)sk)[f];
    }
}

// ---------------------------------------------------------------------------
// LayerNorm; SPLIT additionally emits bf16 hi/lo of the output
// ---------------------------------------------------------------------------
template <bool SPLIT>
__global__ void __launch_bounds__(256) ln_kernel(
    const float* __restrict__ in, const float* __restrict__ gw,
    const float* __restrict__ bw, float* __restrict__ out,
    __nv_bfloat16* __restrict__ ohi, __nv_bfloat16* __restrict__ olo)
{
    const int row = blockIdx.x;
    const int t   = threadIdx.x;
    const float* p = in + (size_t)row * DD;

    const float v0 = p[t], v1 = p[t + 256], v2 = p[t + 512];
    float s  = v0 + v1 + v2;
    float sq = fmaf(v0, v0, fmaf(v1, v1, v2 * v2));

#pragma unroll
    for (int off = 16; off; off >>= 1) {
        s  += __shfl_down_sync(0xffffffffu, s, off);
        sq += __shfl_down_sync(0xffffffffu, sq, off);
    }
    __shared__ float rs[8], rq[8];
    __shared__ float mean_s, inv_s;
    const int w = t >> 5, lane = t & 31;
    if (lane == 0) { rs[w] = s; rq[w] = sq; }
    __syncthreads();
    if (t == 0) {
        float S = 0.f, Q = 0.f;
#pragma unroll
        for (int i = 0; i < 8; i++) { S += rs[i]; Q += rq[i]; }
        const float mean = S * (1.f / 768.f);
        const float var  = Q * (1.f / 768.f) - mean * mean;
        mean_s = mean;
        inv_s  = rsqrtf(var + 1e-5f);
    }
    __syncthreads();
    const float mean = mean_s, inv = inv_s;
    float* po = out + (size_t)row * DD;
#pragma unroll
    for (int j = 0; j < 3; j++) {
        const int  c = t + 256 * j;
        const float vj = (j == 0) ? v0 : (j == 1) ? v1 : v2;
        const float r = fmaf((vj - mean) * inv, gw[c], bw[c]);
        po[c] = r;
        if (SPLIT) {
            const __nv_bfloat16 h = __float2bfloat16(r);
            ohi[(size_t)row * DD + c] = h;
            olo[(size_t)row * DD + c] = __float2bfloat16(r - __bfloat162float(h));
        }
    }
}

// ---------------------------------------------------------------------------
// Launcher
// ---------------------------------------------------------------------------
extern "C" void kernel_launch(void* const* d_in, const int* in_sizes, int n_in,
                              void* d_out, int out_size)
{
    (void)in_sizes; (void)n_in; (void)out_size;
    const float* x     = (const float*)d_in[0];
    const float* alibi = (const float*)d_in[1];
    const float* Wq = (const float*)d_in[2];  const float* bq = (const float*)d_in[3];
    const float* Wk = (const float*)d_in[4];  const float* bk = (const float*)d_in[5];
    const float* Wv = (const float*)d_in[6];  const float* bv = (const float*)d_in[7];
    const float* Wo = (const float*)d_in[8];  const float* bo = (const float*)d_in[9];
    const float* W1 = (const float*)d_in[10]; const float* b1 = (const float*)d_in[11];
    const float* W2 = (const float*)d_in[12]; const float* b2 = (const float*)d_in[13];
    const float* g1w = (const float*)d_in[14]; const float* be1 = (const float*)d_in[15];
    const float* g2w = (const float*)d_in[16]; const float* be2 = (const float*)d_in[17];
    float* out = (float*)d_out;

    float *q, *k, *v, *at, *r1, *y, *z;
    cudaGetSymbolAddress((void**)&q,  g_q);
    cudaGetSymbolAddress((void**)&k,  g_k);
    cudaGetSymbolAddress((void**)&v,  g_v);
    cudaGetSymbolAddress((void**)&at, g_attn);
    cudaGetSymbolAddress((void**)&r1, g_res1);
    cudaGetSymbolAddress((void**)&y,  g_y);
    cudaGetSymbolAddress((void**)&z,  g_z);

    __nv_bfloat16 *xhi, *xlo, *athi, *atlo, *yhi, *ylo, *h1hi, *h1lo;
    __nv_bfloat16 *wqh, *wql, *wkh, *wkl, *wvh, *wvl, *woh, *wol, *w1h, *w1l, *w2h, *w2l;
    cudaGetSymbolAddress((void**)&xhi,  g_xhi);  cudaGetSymbolAddress((void**)&xlo,  g_xlo);
    cudaGetSymbolAddress((void**)&athi, g_athi); cudaGetSymbolAddress((void**)&atlo, g_atlo);
    cudaGetSymbolAddress((void**)&yhi,  g_yhi);  cudaGetSymbolAddress((void**)&ylo,  g_ylo);
    cudaGetSymbolAddress((void**)&h1hi, g_h1hi); cudaGetSymbolAddress((void**)&h1lo, g_h1lo);
    cudaGetSymbolAddress((void**)&wqh, g_wqThi); cudaGetSymbolAddress((void**)&wql, g_wqTlo);
    cudaGetSymbolAddress((void**)&wkh, g_wkThi); cudaGetSymbolAddress((void**)&wkl, g_wkTlo);
    cudaGetSymbolAddress((void**)&wvh, g_wvThi); cudaGetSymbolAddress((void**)&wvl, g_wvTlo);
    cudaGetSymbolAddress((void**)&woh, g_woThi); cudaGetSymbolAddress((void**)&wol, g_woTlo);
    cudaGetSymbolAddress((void**)&w1h, g_w1Thi); cudaGetSymbolAddress((void**)&w1l, g_w1Tlo);
    cudaGetSymbolAddress((void**)&w2h, g_w2Thi); cudaGetSymbolAddress((void**)&w2l, g_w2Tlo);

    cudaFuncSetAttribute(attn_kernel,
                         cudaFuncAttributeMaxDynamicSharedMemorySize, ATTN_SMEM);

    const dim3 tb(32, 8);

    // input conversion + weight transpose/convert
    convert_split<<<3072, 256>>>(x, xhi, xlo);
    transpose_split<<<dim3(24, 24), tb>>>(Wq, wqh, wql, DD, DD);
    transpose_split<<<dim3(24, 24), tb>>>(Wk, wkh, wkl, DD, DD);
    transpose_split<<<dim3(24, 24), tb>>>(Wv, wvh, wvl, DD, DD);
    transpose_split<<<dim3(24, 24), tb>>>(Wo, woh, wol, DD, DD);
    transpose_split<<<dim3(96, 24), tb>>>(W1, w1h, w1l, DD, DFF);
    transpose_split<<<dim3(24, 96), tb>>>(W2, w2h, w2l, DFF, DD);

    // QKV projections (tensor core) -> head-major scratch
    mma_gemm<M_QKV><<<dim3(6, 32), 256>>>(
        xhi, xlo, wqh, wql, bq, nullptr, q, nullptr, nullptr, NROW, DD, DD);
    mma_gemm<M_QKV><<<dim3(6, 32), 256>>>(
        xhi, xlo, wkh, wkl, bk, nullptr, k, nullptr, nullptr, NROW, DD, DD);
    mma_gemm<M_QKV><<<dim3(6, 32), 256>>>(
        xhi, xlo, wvh, wvl, bv, nullptr, v, nullptr, nullptr, NROW, DD, DD);

    // causal flash attention with alibi
    attn_kernel<<<dim3(SS / 64, HH, BB), 64, ATTN_SMEM>>>(alibi);
    convert_split<<<3072, 256>>>(at, athi, atlo);

    // output projection + residual, LN1
    mma_gemm<M_WO><<<dim3(6, 32), 256>>>(
        athi, atlo, woh, wol, bo, x, r1, nullptr, nullptr, NROW, DD, DD);
    ln_kernel<true><<<NROW, 256>>>(r1, g1w, be1, y, yhi, ylo);

    // FFN
    mma_gemm<M_FF1><<<dim3(24, 32), 256>>>(
        yhi, ylo, w1h, w1l, b1, nullptr, nullptr, h1hi, h1lo, NROW, DFF, DD);
    mma_gemm<M_FF2><<<dim3(6, 32), 256>>>(
        h1hi, h1lo, w2h, w2l, b2, y, z, nullptr, nullptr, NROW, DD, DFF);
    ln_kernel<false><<<NROW, 256>>>(z, g2w, be2, out, nullptr, nullptr);
}

// round 4
// speedup vs baseline: 2.6402x; 1.5358x over previous
#include <cuda_runtime.h>
#include <cuda_bf16.h>
#include <cstdint>
#include <cstddef>

// Problem constants
#define BB    2
#define SS    2048
#define DD    768
#define HH    12
#define HDD   64
#define DFF   3072
#define NROW  4096            // B*S

#define PADH  72              // smem row pitch in bf16 (conflict-free frags)

// ---------------------------------------------------------------------------
// Scratch (device globals: no allocation allowed)
// ---------------------------------------------------------------------------
__device__ float g_res1[NROW * DD];
__device__ float g_y[NROW * DD];
__device__ float g_z[NROW * DD];

// bf16 hi/lo split activations
__device__ __nv_bfloat16 g_xhi[NROW * DD],  g_xlo[NROW * DD];
__device__ __nv_bfloat16 g_athi[NROW * DD], g_atlo[NROW * DD];
__device__ __nv_bfloat16 g_yhi[NROW * DD],  g_ylo[NROW * DD];
__device__ __nv_bfloat16 g_h1hi[NROW * DFF], g_h1lo[NROW * DFF];

// head-major q/k/v bf16 hi/lo: [b,h,s,hd]
__device__ __nv_bfloat16 g_qhi[BB*HH*SS*HDD], g_qlo[BB*HH*SS*HDD];
__device__ __nv_bfloat16 g_khi[BB*HH*SS*HDD], g_klo[BB*HH*SS*HDD];
__device__ __nv_bfloat16 g_vhi[BB*HH*SS*HDD], g_vlo[BB*HH*SS*HDD];
// V transposed per head: [b,h,hd,s]
__device__ __nv_bfloat16 g_vthi[BB*HH*SS*HDD], g_vtlo[BB*HH*SS*HDD];

// transposed bf16 hi/lo weights: [N, K]
__device__ __nv_bfloat16 g_wqThi[DD * DD],  g_wqTlo[DD * DD];
__device__ __nv_bfloat16 g_wkThi[DD * DD],  g_wkTlo[DD * DD];
__device__ __nv_bfloat16 g_wvThi[DD * DD],  g_wvTlo[DD * DD];
__device__ __nv_bfloat16 g_woThi[DD * DD],  g_woTlo[DD * DD];
__device__ __nv_bfloat16 g_w1Thi[DFF * DD], g_w1Tlo[DFF * DD];
__device__ __nv_bfloat16 g_w2Thi[DD * DFF], g_w2Tlo[DD * DFF];

// ---------------------------------------------------------------------------
// helpers
// ---------------------------------------------------------------------------
__device__ __forceinline__ void mma16816(float* d, const uint32_t* a,
                                         uint32_t b0, uint32_t b1) {
    asm volatile(
        "mma.sync.aligned.m16n8k16.row.col.f32.bf16.bf16.f32 "
        "{%0,%1,%2,%3}, {%4,%5,%6,%7}, {%8,%9}, {%0,%1,%2,%3};"
        : "+f"(d[0]), "+f"(d[1]), "+f"(d[2]), "+f"(d[3])
        : "r"(a[0]), "r"(a[1]), "r"(a[2]), "r"(a[3]), "r"(b0), "r"(b1));
}
// pack {lo, hi} floats -> bf16x2 (lo in bits 0..15)
__device__ __forceinline__ uint32_t pack_bf16(float lo, float hi) {
    uint32_t r;
    asm("cvt.rn.bf16x2.f32 %0, %1, %2;" : "=r"(r) : "f"(hi), "f"(lo));
    return r;
}

// ---------------------------------------------------------------------------
// fp32 -> bf16 hi/lo split
// ---------------------------------------------------------------------------
__global__ void __launch_bounds__(256) convert_split(
    const float* __restrict__ in, __nv_bfloat16* __restrict__ hi,
    __nv_bfloat16* __restrict__ lo)
{
    const int i = blockIdx.x * 256 + threadIdx.x;
    float4 v = ((const float4*)in)[i];
    float f[4] = {v.x, v.y, v.z, v.w};
    __nv_bfloat16 h[4], l[4];
#pragma unroll
    for (int j = 0; j < 4; j++) {
        h[j] = __float2bfloat16(f[j]);
        l[j] = __float2bfloat16(f[j] - __bfloat162float(h[j]));
    }
    ((uint2*)hi)[i] = *(uint2*)h;
    ((uint2*)lo)[i] = *(uint2*)l;
}

// ---------------------------------------------------------------------------
// W[K,N] fp32 -> Wt[N,K] bf16 hi/lo
// ---------------------------------------------------------------------------
__global__ void __launch_bounds__(256) transpose_split(
    const float* __restrict__ W, __nv_bfloat16* __restrict__ Thi,
    __nv_bfloat16* __restrict__ Tlo, int K, int N)
{
    __shared__ float tile[32][33];
    const int k0 = blockIdx.y * 32, n0 = blockIdx.x * 32;
    const int tx = threadIdx.x, ty = threadIdx.y;   // (32, 8)
#pragma unroll
    for (int i = 0; i < 4; i++)
        tile[ty + 8 * i][tx] = W[(size_t)(k0 + ty + 8 * i) * N + n0 + tx];
    __syncthreads();
#pragma unroll
    for (int i = 0; i < 4; i++) {
        const float vv = tile[tx][ty + 8 * i];
        const __nv_bfloat16 h = __float2bfloat16(vv);
        const size_t o = (size_t)(n0 + ty + 8 * i) * K + k0 + tx;
        Thi[o] = h;
        Tlo[o] = __float2bfloat16(vv - __bfloat162float(h));
    }
}

// ---------------------------------------------------------------------------
// per-head V transpose: [s, hd] -> [hd, s] (bf16)
// ---------------------------------------------------------------------------
__global__ void __launch_bounds__(256) vtrans(
    const __nv_bfloat16* __restrict__ in, __nv_bfloat16* __restrict__ out)
{
    __shared__ __nv_bfloat16 sm[64][72];
    const int s0 = blockIdx.x * 64;
    const size_t bh = blockIdx.y;
    const __nv_bfloat16* src = in + bh * SS * HDD;
    __nv_bfloat16* dst = out + bh * (size_t)HDD * SS;
    const int t = threadIdx.x;
    const int r = t >> 2, cq = (t & 3) * 16;
    *(uint4*)(&sm[r][cq])     = *(const uint4*)(src + (size_t)(s0 + r) * HDD + cq);
    *(uint4*)(&sm[r][cq + 8]) = *(const uint4*)(src + (size_t)(s0 + r) * HDD + cq + 8);
    __syncthreads();
    uint32_t w[8];
#pragma unroll
    for (int j = 0; j < 8; j++) {
        const __nv_bfloat16 a = sm[cq + 2 * j][r], b = sm[cq + 2 * j + 1][r];
        w[j] = ((uint32_t)(*(const uint16_t*)&b) << 16) | *(const uint16_t*)&a;
    }
#pragma unroll
    for (int j = 0; j < 4; j++)
        *(uint2*)(dst + (size_t)r * SS + s0 + cq + 4 * j) =
            make_uint2(w[2 * j], w[2 * j + 1]);
}

// ---------------------------------------------------------------------------
// mma.sync GEMM (unchanged core from R3)
// ---------------------------------------------------------------------------
#define M_QKV 0
#define M_WO  1
#define M_FF1 2
#define M_FF2 3

template <int MODE>
__global__ void __launch_bounds__(256) mma_gemm(
    const __nv_bfloat16* __restrict__ Ahi, const __nv_bfloat16* __restrict__ Alo,
    const __nv_bfloat16* __restrict__ Bhi, const __nv_bfloat16* __restrict__ Blo,
    const float* __restrict__ bias, const float* __restrict__ res,
    float* __restrict__ Cf, __nv_bfloat16* __restrict__ Chi,
    __nv_bfloat16* __restrict__ Clo, int M, int N, int K)
{
    __shared__ __nv_bfloat16 As[128 * PADH];
    __shared__ __nv_bfloat16 Bs[128 * PADH];

    const int t    = threadIdx.x;
    const int lane = t & 31, wid = t >> 5;
    const int wm   = (wid & 3) * 32;
    const int wn   = (wid >> 2) * 64;
    const int bm   = blockIdx.y * 128, bn = blockIdx.x * 128;
    const int g    = lane >> 2, tig = lane & 3;

    float acc[2][8][4];
#pragma unroll
    for (int i = 0; i < 2; i++)
#pragma unroll
        for (int j = 0; j < 8; j++)
#pragma unroll
            for (int c = 0; c < 4; c++) acc[i][j][c] = 0.f;

    const int KCN = K >> 6;
    for (int it = 0; it < 3 * KCN; it++) {
        const int pass = it / KCN;
        const int k0   = (it - pass * KCN) << 6;
        const __nv_bfloat16* Ap = (pass == 2) ? Alo : Ahi;
        const __nv_bfloat16* Bp = (pass == 1) ? Blo : Bhi;

        __syncthreads();
#pragma unroll
        for (int i = 0; i < 4; i++) {
            const int f = t + 256 * i;
            const int r = f >> 3, c8 = (f & 7) * 8;
            *(uint4*)(As + r * PADH + c8) =
                *(const uint4*)(Ap + (size_t)(bm + r) * K + k0 + c8);
            *(uint4*)(Bs + r * PADH + c8) =
                *(const uint4*)(Bp + (size_t)(bn + r) * K + k0 + c8);
        }
        __syncthreads();

#pragma unroll
        for (int kk = 0; kk < 64; kk += 16) {
            uint32_t a[2][4];
#pragma unroll
            for (int mt = 0; mt < 2; mt++) {
                const int row = wm + mt * 16 + g;
                a[mt][0] = *(const uint32_t*)(As + row * PADH + kk + 2 * tig);
                a[mt][1] = *(const uint32_t*)(As + (row + 8) * PADH + kk + 2 * tig);
                a[mt][2] = *(const uint32_t*)(As + row * PADH + kk + 8 + 2 * tig);
                a[mt][3] = *(const uint32_t*)(As + (row + 8) * PADH + kk + 8 + 2 * tig);
            }
#pragma unroll
            for (int nt = 0; nt < 8; nt++) {
                const int nrow = wn + nt * 8 + g;
                const uint32_t b0 =
                    *(const uint32_t*)(Bs + nrow * PADH + kk + 2 * tig);
                const uint32_t b1 =
                    *(const uint32_t*)(Bs + nrow * PADH + kk + 8 + 2 * tig);
                mma16816(acc[0][nt], a[0], b0, b1);
                mma16816(acc[1][nt], a[1], b0, b1);
            }
        }
    }

#pragma unroll
    for (int mt = 0; mt < 2; mt++) {
#pragma unroll
        for (int nt = 0; nt < 8; nt++) {
#pragma unroll
            for (int half = 0; half < 2; half++) {
                const int grow = bm + wm + mt * 16 + g + half * 8;
                const int gcol = bn + wn + nt * 8 + 2 * tig;
                float v0 = acc[mt][nt][half * 2 + 0] + bias[gcol];
                float v1 = acc[mt][nt][half * 2 + 1] + bias[gcol + 1];
                if (MODE == M_FF1) {
                    v0 = fmaxf(v0, 0.f);
                    v1 = fmaxf(v1, 0.f);
                    const float h0 = __bfloat162float(__float2bfloat16(v0));
                    const float h1 = __bfloat162float(__float2bfloat16(v1));
                    *(uint32_t*)(Chi + (size_t)grow * N + gcol) = pack_bf16(h0, h1);
                    *(uint32_t*)(Clo + (size_t)grow * N + gcol) =
                        pack_bf16(v0 - h0, v1 - h1);
                } else if (MODE == M_QKV) {
                    const int b_ = grow >> 11, s_ = grow & 2047;
                    const int h_ = gcol >> 6,  hd = gcol & 63;
                    const size_t oo =
                        (((size_t)(b_ * HH + h_) * SS) + s_) * HDD + hd;
                    const float h0 = __bfloat162float(__float2bfloat16(v0));
                    const float h1 = __bfloat162float(__float2bfloat16(v1));
                    *(uint32_t*)(Chi + oo) = pack_bf16(h0, h1);
                    *(uint32_t*)(Clo + oo) = pack_bf16(v0 - h0, v1 - h1);
                } else {
                    const size_t o = (size_t)grow * N + gcol;
                    v0 += res[o];
                    v1 += res[o + 1];
                    *(float2*)(Cf + o) = make_float2(v0, v1);
                }
            }
        }
    }
}

// ---------------------------------------------------------------------------
// Tensor-core flash attention.
// Block: (q-tile 128, h, b); 4 warps, warp = 32 q-rows x full 64 key-cols.
// S = Q@K^T (3-pass hi/lo), online softmax, O += P@V (3-pass hi/lo).
// ---------------------------------------------------------------------------
__global__ void __launch_bounds__(128) attn_tc(
    const float* __restrict__ alibi,
    const __nv_bfloat16* __restrict__ Qhi, const __nv_bfloat16* __restrict__ Qlo,
    const __nv_bfloat16* __restrict__ Khi, const __nv_bfloat16* __restrict__ Klo,
    const __nv_bfloat16* __restrict__ Vthi, const __nv_bfloat16* __restrict__ Vtlo,
    __nv_bfloat16* __restrict__ Ohi, __nv_bfloat16* __restrict__ Olo)
{
    __shared__ __nv_bfloat16 skh[64 * 72], skl[64 * 72];
    __shared__ __nv_bfloat16 svh[64 * 72], svl[64 * 72];

    const int t = threadIdx.x, lane = t & 31, wid = t >> 5;
    const int g = lane >> 2, tig = lane & 3;
    const int qt = (int)(gridDim.x - 1) - (int)blockIdx.x;   // big tiles first
    const int h = blockIdx.y, b = blockIdx.z;
    const int q0 = qt * 128, wm = wid * 32;
    const size_t bh = (size_t)(b * HH + h);

    const __nv_bfloat16* qh = Qhi + (bh * SS + q0) * HDD;
    const __nv_bfloat16* ql = Qlo + (bh * SS + q0) * HDD;
    const __nv_bfloat16* kh = Khi + bh * SS * HDD;
    const __nv_bfloat16* kl = Klo + bh * SS * HDD;
    const __nv_bfloat16* vh = Vthi + bh * (size_t)HDD * SS;
    const __nv_bfloat16* vl = Vtlo + bh * (size_t)HDD * SS;
    const float* ab = alibi + (size_t)h * SS * SS;

    float o[2][8][4];
#pragma unroll
    for (int i = 0; i < 2; i++)
#pragma unroll
        for (int j = 0; j < 8; j++)
#pragma unroll
            for (int c = 0; c < 4; c++) o[i][j][c] = 0.f;
    float mrow[2][2] = {{-1e30f, -1e30f}, {-1e30f, -1e30f}};
    float lrow[2][2] = {{0.f, 0.f}, {0.f, 0.f}};

    const int nkt = 2 * qt + 2;
    for (int kt = 0; kt < nkt; kt++) {
        const int k0 = kt * 64;
        __syncthreads();
#pragma unroll
        for (int i = 0; i < 4; i++) {
            const int f = t + 128 * i;          // 512 uint4 slots
            const int r = f >> 3, c8 = (f & 7) * 8;
            *(uint4*)(skh + r * 72 + c8) =
                *(const uint4*)(kh + (size_t)(k0 + r) * HDD + c8);
            *(uint4*)(skl + r * 72 + c8) =
                *(const uint4*)(kl + (size_t)(k0 + r) * HDD + c8);
            *(uint4*)(svh + r * 72 + c8) =
                *(const uint4*)(vh + (size_t)r * SS + k0 + c8);
            *(uint4*)(svl + r * 72 + c8) =
                *(const uint4*)(vl + (size_t)r * SS + k0 + c8);
        }
        __syncthreads();

        // ---- S = Q@K^T, 3-pass hi/lo ----
        float sacc[2][8][4];
#pragma unroll
        for (int i = 0; i < 2; i++)
#pragma unroll
            for (int j = 0; j < 8; j++)
#pragma unroll
                for (int c = 0; c < 4; c++) sacc[i][j][c] = 0.f;

#pragma unroll
        for (int kc = 0; kc < 4; kc++) {
            uint32_t a[2][4];
#pragma unroll
            for (int mt = 0; mt < 2; mt++) {
                const int row = wm + mt * 16 + g;
                a[mt][0] = *(const uint32_t*)(qh + (size_t)row * HDD + kc * 16 + 2 * tig);
                a[mt][1] = *(const uint32_t*)(qh + (size_t)(row + 8) * HDD + kc * 16 + 2 * tig);
                a[mt][2] = *(const uint32_t*)(qh + (size_t)row * HDD + kc * 16 + 8 + 2 * tig);
                a[mt][3] = *(const uint32_t*)(qh + (size_t)(row + 8) * HDD + kc * 16 + 8 + 2 * tig);
            }
#pragma unroll
            for (int nt = 0; nt < 8; nt++) {      // Qhi * Khi
                const __nv_bfloat16* kr = skh + (8 * nt + g) * 72 + kc * 16;
                const uint32_t b0 = *(const uint32_t*)(kr + 2 * tig);
                const uint32_t b1 = *(const uint32_t*)(kr + 8 + 2 * tig);
                mma16816(sacc[0][nt], a[0], b0, b1);
                mma16816(sacc[1][nt], a[1], b0, b1);
            }
#pragma unroll
            for (int nt = 0; nt < 8; nt++) {      // Qhi * Klo
                const __nv_bfloat16* kr = skl + (8 * nt + g) * 72 + kc * 16;
                const uint32_t b0 = *(const uint32_t*)(kr + 2 * tig);
                const uint32_t b1 = *(const uint32_t*)(kr + 8 + 2 * tig);
                mma16816(sacc[0][nt], a[0], b0, b1);
                mma16816(sacc[1][nt], a[1], b0, b1);
            }
#pragma unroll
            for (int mt = 0; mt < 2; mt++) {      // reload A from Qlo
                const int row = wm + mt * 16 + g;
                a[mt][0] = *(const uint32_t*)(ql + (size_t)row * HDD + kc * 16 + 2 * tig);
                a[mt][1] = *(const uint32_t*)(ql + (size_t)(row + 8) * HDD + kc * 16 + 2 * tig);
                a[mt][2] = *(const uint32_t*)(ql + (size_t)row * HDD + kc * 16 + 8 + 2 * tig);
                a[mt][3] = *(const uint32_t*)(ql + (size_t)(row + 8) * HDD + kc * 16 + 8 + 2 * tig);
            }
#pragma unroll
            for (int nt = 0; nt < 8; nt++) {      // Qlo * Khi
                const __nv_bfloat16* kr = skh + (8 * nt + g) * 72 + kc * 16;
                const uint32_t b0 = *(const uint32_t*)(kr + 2 * tig);
                const uint32_t b1 = *(const uint32_t*)(kr + 8 + 2 * tig);
                mma16816(sacc[0][nt], a[0], b0, b1);
                mma16816(sacc[1][nt], a[1], b0, b1);
            }
        }

        // ---- alibi + causal mask + online softmax (per row) ----
#pragma unroll
        for (int mt = 0; mt < 2; mt++) {
#pragma unroll
            for (int hf = 0; hf < 2; hf++) {
                const int rowg = q0 + wm + 16 * mt + g + 8 * hf;
                const float* arow = ab + (size_t)rowg * SS + k0;
                float mx = -1e30f;
#pragma unroll
                for (int nt = 0; nt < 8; nt++) {
                    const int col = k0 + 8 * nt + 2 * tig;
                    const float2 al = *(const float2*)(arow + 8 * nt + 2 * tig);
                    float s0 = fmaf(sacc[mt][nt][2 * hf + 0], 0.125f, al.x);
                    float s1 = fmaf(sacc[mt][nt][2 * hf + 1], 0.125f, al.y);
                    if (col > rowg)     s0 = -1e30f;
                    if (col + 1 > rowg) s1 = -1e30f;
                    sacc[mt][nt][2 * hf + 0] = s0;
                    sacc[mt][nt][2 * hf + 1] = s1;
                    mx = fmaxf(mx, fmaxf(s0, s1));
                }
                mx = fmaxf(mx, __shfl_xor_sync(0xffffffffu, mx, 1));
                mx = fmaxf(mx, __shfl_xor_sync(0xffffffffu, mx, 2));
                const float mn = fmaxf(mrow[mt][hf], mx);
                const float corr = __expf(mrow[mt][hf] - mn);
                mrow[mt][hf] = mn;
                lrow[mt][hf] *= corr;
#pragma unroll
                for (int nt = 0; nt < 8; nt++) {
                    o[mt][nt][2 * hf + 0] *= corr;
                    o[mt][nt][2 * hf + 1] *= corr;
                }
                float ls = 0.f;
#pragma unroll
                for (int nt = 0; nt < 8; nt++) {
                    const float p0 = __expf(sacc[mt][nt][2 * hf + 0] - mn);
                    const float p1 = __expf(sacc[mt][nt][2 * hf + 1] - mn);
                    sacc[mt][nt][2 * hf + 0] = p0;
                    sacc[mt][nt][2 * hf + 1] = p1;
                    ls += p0 + p1;
                }
                ls += __shfl_xor_sync(0xffffffffu, ls, 1);
                ls += __shfl_xor_sync(0xffffffffu, ls, 2);
                lrow[mt][hf] += ls;
            }
        }

        // ---- O += P@V, 3-pass hi/lo (P from regs, V^T from smem) ----
#pragma unroll
        for (int kc = 0; kc < 4; kc++) {
            uint32_t aph[2][4], apl[2][4];
#pragma unroll
            for (int mt = 0; mt < 2; mt++) {
#pragma unroll
                for (int q2 = 0; q2 < 2; q2++) {          // ntile 2kc + q2
                    const float p0 = sacc[mt][2 * kc + q2][0];
                    const float p1 = sacc[mt][2 * kc + q2][1];
                    const float p2 = sacc[mt][2 * kc + q2][2];
                    const float p3 = sacc[mt][2 * kc + q2][3];
                    const float h0 = __bfloat162float(__float2bfloat16(p0));
                    const float h1 = __bfloat162float(__float2bfloat16(p1));
                    const float h2 = __bfloat162float(__float2bfloat16(p2));
                    const float h3 = __bfloat162float(__float2bfloat16(p3));
                    aph[mt][2 * q2 + 0] = pack_bf16(h0, h1);
                    aph[mt][2 * q2 + 1] = pack_bf16(h2, h3);
                    apl[mt][2 * q2 + 0] = pack_bf16(p0 - h0, p1 - h1);
                    apl[mt][2 * q2 + 1] = pack_bf16(p2 - h2, p3 - h3);
                }
            }
#pragma unroll
            for (int nt = 0; nt < 8; nt++) {
                const __nv_bfloat16* vrh = svh + (8 * nt + g) * 72 + kc * 16;
                const __nv_bfloat16* vrl = svl + (8 * nt + g) * 72 + kc * 16;
                const uint32_t bh0 = *(const uint32_t*)(vrh + 2 * tig);
                const uint32_t bh1 = *(const uint32_t*)(vrh + 8 + 2 * tig);
                const uint32_t bl0 = *(const uint32_t*)(vrl + 2 * tig);
                const uint32_t bl1 = *(const uint32_t*)(vrl + 8 + 2 * tig);
                mma16816(o[0][nt], aph[0], bh0, bh1);
                mma16816(o[1][nt], aph[1], bh0, bh1);
                mma16816(o[0][nt], apl[0], bh0, bh1);
                mma16816(o[1][nt], apl[1], bh0, bh1);
                mma16816(o[0][nt], aph[0], bl0, bl1);
                mma16816(o[1][nt], aph[1], bl0, bl1);
            }
        }
    }

    // ---- epilogue: normalize, write bf16 hi/lo [b,s,D] ----
#pragma unroll
    for (int mt = 0; mt < 2; mt++) {
#pragma unroll
        for (int hf = 0; hf < 2; hf++) {
            const float inv = 1.f / lrow[mt][hf];
            const int srow = q0 + wm + 16 * mt + g + 8 * hf;
            const size_t base = ((size_t)b * SS + srow) * DD + h * HDD;
#pragma unroll
            for (int nt = 0; nt < 8; nt++) {
                const float v0 = o[mt][nt][2 * hf + 0] * inv;
                const float v1 = o[mt][nt][2 * hf + 1] * inv;
                const float h0 = __bfloat162float(__float2bfloat16(v0));
                const float h1 = __bfloat162float(__float2bfloat16(v1));
                *(uint32_t*)(Ohi + base + 8 * nt + 2 * tig) = pack_bf16(h0, h1);
                *(uint32_t*)(Olo + base + 8 * nt + 2 * tig) =
                    pack_bf16(v0 - h0, v1 - h1);
            }
        }
    }
}

// ---------------------------------------------------------------------------
// LayerNorm; SPLIT additionally emits bf16 hi/lo of the output
// ---------------------------------------------------------------------------
template <bool SPLIT>
__global__ void __launch_bounds__(256) ln_kernel(
    const float* __restrict__ in, const float* __restrict__ gw,
    const float* __restrict__ bw, float* __restrict__ out,
    __nv_bfloat16* __restrict__ ohi, __nv_bfloat16* __restrict__ olo)
{
    const int row = blockIdx.x;
    const int t   = threadIdx.x;
    const float* p = in + (size_t)row * DD;

    const float v0 = p[t], v1 = p[t + 256], v2 = p[t + 512];
    float s  = v0 + v1 + v2;
    float sq = fmaf(v0, v0, fmaf(v1, v1, v2 * v2));

#pragma unroll
    for (int off = 16; off; off >>= 1) {
        s  += __shfl_down_sync(0xffffffffu, s, off);
        sq += __shfl_down_sync(0xffffffffu, sq, off);
    }
    __shared__ float rs[8], rq[8];
    __shared__ float mean_s, inv_s;
    const int w = t >> 5, lane = t & 31;
    if (lane == 0) { rs[w] = s; rq[w] = sq; }
    __syncthreads();
    if (t == 0) {
        float S = 0.f, Q = 0.f;
#pragma unroll
        for (int i = 0; i < 8; i++) { S += rs[i]; Q += rq[i]; }
        const float mean = S * (1.f / 768.f);
        const float var  = Q * (1.f / 768.f) - mean * mean;
        mean_s = mean;
        inv_s  = rsqrtf(var + 1e-5f);
    }
    __syncthreads();
    const float mean = mean_s, inv = inv_s;
    float* po = out + (size_t)row * DD;
#pragma unroll
    for (int j = 0; j < 3; j++) {
        const int  c = t + 256 * j;
        const float vj = (j == 0) ? v0 : (j == 1) ? v1 : v2;
        const float r = fmaf((vj - mean) * inv, gw[c], bw[c]);
        po[c] = r;
        if (SPLIT) {
            const __nv_bfloat16 h = __float2bfloat16(r);
            ohi[(size_t)row * DD + c] = h;
            olo[(size_t)row * DD + c] = __float2bfloat16(r - __bfloat162float(h));
        }
    }
}

// ---------------------------------------------------------------------------
// Launcher
// ---------------------------------------------------------------------------
extern "C" void kernel_launch(void* const* d_in, const int* in_sizes, int n_in,
                              void* d_out, int out_size)
{
    (void)in_sizes; (void)n_in; (void)out_size;
    const float* x     = (const float*)d_in[0];
    const float* alibi = (const float*)d_in[1];
    const float* Wq = (const float*)d_in[2];  const float* bq = (const float*)d_in[3];
    const float* Wk = (const float*)d_in[4];  const float* bk = (const float*)d_in[5];
    const float* Wv = (const float*)d_in[6];  const float* bv = (const float*)d_in[7];
    const float* Wo = (const float*)d_in[8];  const float* bo = (const float*)d_in[9];
    const float* W1 = (const float*)d_in[10]; const float* b1 = (const float*)d_in[11];
    const float* W2 = (const float*)d_in[12]; const float* b2 = (const float*)d_in[13];
    const float* g1w = (const float*)d_in[14]; const float* be1 = (const float*)d_in[15];
    const float* g2w = (const float*)d_in[16]; const float* be2 = (const float*)d_in[17];
    float* out = (float*)d_out;

    float *r1, *y, *z;
    cudaGetSymbolAddress((void**)&r1, g_res1);
    cudaGetSymbolAddress((void**)&y,  g_y);
    cudaGetSymbolAddress((void**)&z,  g_z);

    __nv_bfloat16 *xhi, *xlo, *athi, *atlo, *yhi, *ylo, *h1hi, *h1lo;
    __nv_bfloat16 *qhi, *qlo, *khi, *klo, *vhi, *vlo, *vthi, *vtlo;
    __nv_bfloat16 *wqh, *wql, *wkh, *wkl, *wvh, *wvl, *woh, *wol, *w1h, *w1l, *w2h, *w2l;
    cudaGetSymbolAddress((void**)&xhi,  g_xhi);  cudaGetSymbolAddress((void**)&xlo,  g_xlo);
    cudaGetSymbolAddress((void**)&athi, g_athi); cudaGetSymbolAddress((void**)&atlo, g_atlo);
    cudaGetSymbolAddress((void**)&yhi,  g_yhi);  cudaGetSymbolAddress((void**)&ylo,  g_ylo);
    cudaGetSymbolAddress((void**)&h1hi, g_h1hi); cudaGetSymbolAddress((void**)&h1lo, g_h1lo);
    cudaGetSymbolAddress((void**)&qhi,  g_qhi);  cudaGetSymbolAddress((void**)&qlo,  g_qlo);
    cudaGetSymbolAddress((void**)&khi,  g_khi);  cudaGetSymbolAddress((void**)&klo,  g_klo);
    cudaGetSymbolAddress((void**)&vhi,  g_vhi);  cudaGetSymbolAddress((void**)&vlo,  g_vlo);
    cudaGetSymbolAddress((void**)&vthi, g_vthi); cudaGetSymbolAddress((void**)&vtlo, g_vtlo);
    cudaGetSymbolAddress((void**)&wqh, g_wqThi); cudaGetSymbolAddress((void**)&wql, g_wqTlo);
    cudaGetSymbolAddress((void**)&wkh, g_wkThi); cudaGetSymbolAddress((void**)&wkl, g_wkTlo);
    cudaGetSymbolAddress((void**)&wvh, g_wvThi); cudaGetSymbolAddress((void**)&wvl, g_wvTlo);
    cudaGetSymbolAddress((void**)&woh, g_woThi); cudaGetSymbolAddress((void**)&wol, g_woTlo);
    cudaGetSymbolAddress((void**)&w1h, g_w1Thi); cudaGetSymbolAddress((void**)&w1l, g_w1Tlo);
    cudaGetSymbolAddress((void**)&w2h, g_w2Thi); cudaGetSymbolAddress((void**)&w2l, g_w2Tlo);

    const dim3 tb(32, 8);

    convert_split<<<3072, 256>>>(x, xhi, xlo);
    transpose_split<<<dim3(24, 24), tb>>>(Wq, wqh, wql, DD, DD);
    transpose_split<<<dim3(24, 24), tb>>>(Wk, wkh, wkl, DD, DD);
    transpose_split<<<dim3(24, 24), tb>>>(Wv, wvh, wvl, DD, DD);
    transpose_split<<<dim3(24, 24), tb>>>(Wo, woh, wol, DD, DD);
    transpose_split<<<dim3(96, 24), tb>>>(W1, w1h, w1l, DD, DFF);
    transpose_split<<<dim3(24, 96), tb>>>(W2, w2h, w2l, DFF, DD);

    // QKV projections -> head-major bf16 hi/lo
    mma_gemm<M_QKV><<<dim3(6, 32), 256>>>(
        xhi, xlo, wqh, wql, bq, nullptr, nullptr, qhi, qlo, NROW, DD, DD);
    mma_gemm<M_QKV><<<dim3(6, 32), 256>>>(
        xhi, xlo, wkh, wkl, bk, nullptr, nullptr, khi, klo, NROW, DD, DD);
    mma_gemm<M_QKV><<<dim3(6, 32), 256>>>(
        xhi, xlo, wvh, wvl, bv, nullptr, nullptr, vhi, vlo, NROW, DD, DD);

    // V -> V^T per head
    vtrans<<<dim3(32, 24), 256>>>(vhi, vthi);
    vtrans<<<dim3(32, 24), 256>>>(vlo, vtlo);

    // tensor-core flash attention (writes athi/atlo directly)
    attn_tc<<<dim3(16, 12, 2), 128>>>(alibi, qhi, qlo, khi, klo,
                                      vthi, vtlo, athi, atlo);

    // output projection + residual, LN1
    mma_gemm<M_WO><<<dim3(6, 32), 256>>>(
        athi, atlo, woh, wol, bo, x, r1, nullptr, nullptr, NROW, DD, DD);
    ln_kernel<true><<<NROW, 256>>>(r1, g1w, be1, y, yhi, ylo);

    // FFN
    mma_gemm<M_FF1><<<dim3(24, 32), 256>>>(
        yhi, ylo, w1h, w1l, b1, nullptr, nullptr, h1hi, h1lo, NROW, DFF, DD);
    mma_gemm<M_FF2><<<dim3(6, 32), 256>>>(
        h1hi, h1lo, w2h, w2l, b2, y, z, nullptr, nullptr, NROW, DD, DFF);
    ln_kernel<false><<<NROW, 256>>>(z, g2w, be2, out, nullptr, nullptr);
}

// round 5
// speedup vs baseline: 2.6811x; 1.0155x over previous
#include <cuda_runtime.h>
#include <cuda_bf16.h>
#include <cstdint>
#include <cstddef>

// Problem constants
#define BB    2
#define SS    2048
#define DD    768
#define HH    12
#define HDD   64
#define DFF   3072
#define NROW  4096            // B*S

// GEMM tiling
#define CH     32             // K elements per pipeline chunk
#define PADC   40             // smem row pitch (bf16) for GEMM tiles
#define TILE_B (128 * PADC * 2)            // 10240 bytes per tile
#define STAGE_B (4 * TILE_B)               // 40960 bytes per stage
#define GEMM_SMEM (2 * STAGE_B)            // 81920

#define PADH  72              // attn smem pitch (unchanged, proven)

// ---------------------------------------------------------------------------
// Scratch (device globals: no allocation allowed)
// ---------------------------------------------------------------------------
__device__ float g_res1[NROW * DD];
__device__ float g_y[NROW * DD];
__device__ float g_z[NROW * DD];

__device__ __nv_bfloat16 g_xhi[NROW * DD],  g_xlo[NROW * DD];
__device__ __nv_bfloat16 g_athi[NROW * DD], g_atlo[NROW * DD];
__device__ __nv_bfloat16 g_yhi[NROW * DD],  g_ylo[NROW * DD];
__device__ __nv_bfloat16 g_h1hi[NROW * DFF], g_h1lo[NROW * DFF];

__device__ __nv_bfloat16 g_qhi[BB*HH*SS*HDD], g_qlo[BB*HH*SS*HDD];
__device__ __nv_bfloat16 g_khi[BB*HH*SS*HDD], g_klo[BB*HH*SS*HDD];
__device__ __nv_bfloat16 g_vhi[BB*HH*SS*HDD], g_vlo[BB*HH*SS*HDD];
__device__ __nv_bfloat16 g_vthi[BB*HH*SS*HDD], g_vtlo[BB*HH*SS*HDD];

__device__ __nv_bfloat16 g_wqThi[DD * DD],  g_wqTlo[DD * DD];
__device__ __nv_bfloat16 g_wkThi[DD * DD],  g_wkTlo[DD * DD];
__device__ __nv_bfloat16 g_wvThi[DD * DD],  g_wvTlo[DD * DD];
__device__ __nv_bfloat16 g_woThi[DD * DD],  g_woTlo[DD * DD];
__device__ __nv_bfloat16 g_w1Thi[DFF * DD], g_w1Tlo[DFF * DD];
__device__ __nv_bfloat16 g_w2Thi[DD * DFF], g_w2Tlo[DD * DFF];

// ---------------------------------------------------------------------------
// helpers
// ---------------------------------------------------------------------------
__device__ __forceinline__ uint32_t smem_u32(const void* p) {
    uint32_t a;
    asm("{ .reg .u64 t; cvta.to.shared.u64 t, %1; cvt.u32.u64 %0, t; }"
        : "=r"(a) : "l"(p));
    return a;
}
__device__ __forceinline__ void mma16816(float* d, const uint32_t* a,
                                         uint32_t b0, uint32_t b1) {
    asm volatile(
        "mma.sync.aligned.m16n8k16.row.col.f32.bf16.bf16.f32 "
        "{%0,%1,%2,%3}, {%4,%5,%6,%7}, {%8,%9}, {%0,%1,%2,%3};"
        : "+f"(d[0]), "+f"(d[1]), "+f"(d[2]), "+f"(d[3])
        : "r"(a[0]), "r"(a[1]), "r"(a[2]), "r"(a[3]), "r"(b0), "r"(b1));
}
__device__ __forceinline__ uint32_t pack_bf16(float lo, float hi) {
    uint32_t r;
    asm("cvt.rn.bf16x2.f32 %0, %1, %2;" : "=r"(r) : "f"(hi), "f"(lo));
    return r;
}
__device__ __forceinline__ void ldmx4(uint32_t* r, uint32_t addr) {
    asm volatile("ldmatrix.sync.aligned.m8n8.x4.shared.b16 {%0,%1,%2,%3}, [%4];"
                 : "=r"(r[0]), "=r"(r[1]), "=r"(r[2]), "=r"(r[3]) : "r"(addr));
}
__device__ __forceinline__ void cp16(uint32_t dst, const void* src) {
    asm volatile("cp.async.cg.shared.global [%0], [%1], 16;"
                 :: "r"(dst), "l"(src));
}
__device__ __forceinline__ void cp_commit() {
    asm volatile("cp.async.commit_group;");
}
__device__ __forceinline__ void cp_wait0() {
    asm volatile("cp.async.wait_group 0;");
}
__device__ __forceinline__ void cp_wait1() {
    asm volatile("cp.async.wait_group 1;");
}

// ---------------------------------------------------------------------------
// fp32 -> bf16 hi/lo split
// ---------------------------------------------------------------------------
__global__ void __launch_bounds__(256) convert_split(
    const float* __restrict__ in, __nv_bfloat16* __restrict__ hi,
    __nv_bfloat16* __restrict__ lo)
{
    const int i = blockIdx.x * 256 + threadIdx.x;
    float4 v = ((const float4*)in)[i];
    float f[4] = {v.x, v.y, v.z, v.w};
    __nv_bfloat16 h[4], l[4];
#pragma unroll
    for (int j = 0; j < 4; j++) {
        h[j] = __float2bfloat16(f[j]);
        l[j] = __float2bfloat16(f[j] - __bfloat162float(h[j]));
    }
    ((uint2*)hi)[i] = *(uint2*)h;
    ((uint2*)lo)[i] = *(uint2*)l;
}

// ---------------------------------------------------------------------------
// W[K,N] fp32 -> Wt[N,K] bf16 hi/lo
// ---------------------------------------------------------------------------
__global__ void __launch_bounds__(256) transpose_split(
    const float* __restrict__ W, __nv_bfloat16* __restrict__ Thi,
    __nv_bfloat16* __restrict__ Tlo, int K, int N)
{
    __shared__ float tile[32][33];
    const int k0 = blockIdx.y * 32, n0 = blockIdx.x * 32;
    const int tx = threadIdx.x, ty = threadIdx.y;   // (32, 8)
#pragma unroll
    for (int i = 0; i < 4; i++)
        tile[ty + 8 * i][tx] = W[(size_t)(k0 + ty + 8 * i) * N + n0 + tx];
    __syncthreads();
#pragma unroll
    for (int i = 0; i < 4; i++) {
        const float vv = tile[tx][ty + 8 * i];
        const __nv_bfloat16 h = __float2bfloat16(vv);
        const size_t o = (size_t)(n0 + ty + 8 * i) * K + k0 + tx;
        Thi[o] = h;
        Tlo[o] = __float2bfloat16(vv - __bfloat162float(h));
    }
}

// ---------------------------------------------------------------------------
// per-head V transpose: [s, hd] -> [hd, s] (bf16)
// ---------------------------------------------------------------------------
__global__ void __launch_bounds__(256) vtrans(
    const __nv_bfloat16* __restrict__ in, __nv_bfloat16* __restrict__ out)
{
    __shared__ __nv_bfloat16 sm[64][72];
    const int s0 = blockIdx.x * 64;
    const size_t bh = blockIdx.y;
    const __nv_bfloat16* src = in + bh * SS * HDD;
    __nv_bfloat16* dst = out + bh * (size_t)HDD * SS;
    const int t = threadIdx.x;
    const int r = t >> 2, cq = (t & 3) * 16;
    *(uint4*)(&sm[r][cq])     = *(const uint4*)(src + (size_t)(s0 + r) * HDD + cq);
    *(uint4*)(&sm[r][cq + 8]) = *(const uint4*)(src + (size_t)(s0 + r) * HDD + cq + 8);
    __syncthreads();
    uint32_t w[8];
#pragma unroll
    for (int j = 0; j < 8; j++) {
        const __nv_bfloat16 a = sm[cq + 2 * j][r], b = sm[cq + 2 * j + 1][r];
        w[j] = ((uint32_t)(*(const uint16_t*)&b) << 16) | *(const uint16_t*)&a;
    }
#pragma unroll
    for (int j = 0; j < 4; j++)
        *(uint2*)(dst + (size_t)r * SS + s0 + cq + 4 * j) =
            make_uint2(w[2 * j], w[2 * j + 1]);
}

// ---------------------------------------------------------------------------
// mma.sync GEMM v2: fused hi/lo sweep + cp.async double buffer + ldmatrix.
// C[M,N] = A[M,K] @ Bt[N,K]^T. 128x128 CTA tile, 8 warps (4x2).
// ---------------------------------------------------------------------------
#define M_QKV 0
#define M_WO  1
#define M_FF1 2
#define M_FF2 3

struct Ptr3 {
    const __nv_bfloat16 *bh, *bl;
    const float* bias;
    __nv_bfloat16 *ch, *cl;
};
struct Qkv3 { Ptr3 p[3]; };

template <int MODE>
__global__ void __launch_bounds__(256) mma_gemm(
    const __nv_bfloat16* __restrict__ Ahi, const __nv_bfloat16* __restrict__ Alo,
    const __nv_bfloat16* __restrict__ Bhi_, const __nv_bfloat16* __restrict__ Blo_,
    const float* __restrict__ bias_, const float* __restrict__ res,
    float* __restrict__ Cf, __nv_bfloat16* __restrict__ Chi_,
    __nv_bfloat16* __restrict__ Clo_, Qkv3 qkv, int M, int N, int K)
{
    extern __shared__ char smem[];
    const uint32_t sb = smem_u32(smem);

    const int t    = threadIdx.x;
    const int lane = t & 31, wid = t >> 5;
    const int wm   = (wid & 3) * 32;
    const int wn   = (wid >> 2) * 64;
    const int bm   = blockIdx.y * 128, bn = blockIdx.x * 128;
    const int g    = lane >> 2, tig = lane & 3;

    const __nv_bfloat16* Bhi;
    const __nv_bfloat16* Blo;
    const float* bias;
    __nv_bfloat16 *Chi, *Clo;
    if (MODE == M_QKV) {
        const Ptr3& p = qkv.p[blockIdx.z];
        Bhi = p.bh; Blo = p.bl; bias = p.bias; Chi = p.ch; Clo = p.cl;
    } else {
        Bhi = Bhi_; Blo = Blo_; bias = bias_; Chi = Chi_; Clo = Clo_;
    }

    float acc[2][8][4];
#pragma unroll
    for (int i = 0; i < 2; i++)
#pragma unroll
        for (int j = 0; j < 8; j++)
#pragma unroll
            for (int c = 0; c < 4; c++) acc[i][j][c] = 0.f;

    // per-thread copy indices: 2 x (row, col16) covering 512 slots of 16B/tile
    const int i0 = t, i1 = t + 256;
    const int r0c = i0 >> 2, c0c = (i0 & 3) * 8;
    const int r1c = i1 >> 2, c1c = (i1 & 3) * 8;

    auto prefetch = [&](int k0, int stage) {
        const uint32_t sbase = sb + stage * STAGE_B;
        const uint32_t d0 = (uint32_t)(r0c * PADC + c0c) * 2;
        const uint32_t d1 = (uint32_t)(r1c * PADC + c1c) * 2;
        cp16(sbase + d0,              Ahi + (size_t)(bm + r0c) * K + k0 + c0c);
        cp16(sbase + d1,              Ahi + (size_t)(bm + r1c) * K + k0 + c1c);
        cp16(sbase + TILE_B + d0,     Alo + (size_t)(bm + r0c) * K + k0 + c0c);
        cp16(sbase + TILE_B + d1,     Alo + (size_t)(bm + r1c) * K + k0 + c1c);
        cp16(sbase + 2 * TILE_B + d0, Bhi + (size_t)(bn + r0c) * K + k0 + c0c);
        cp16(sbase + 2 * TILE_B + d1, Bhi + (size_t)(bn + r1c) * K + k0 + c1c);
        cp16(sbase + 3 * TILE_B + d0, Blo + (size_t)(bn + r0c) * K + k0 + c0c);
        cp16(sbase + 3 * TILE_B + d1, Blo + (size_t)(bn + r1c) * K + k0 + c1c);
        cp_commit();
    };

    const int KCN = K / CH;
    prefetch(0, 0);

    const uint32_t lrow = (uint32_t)(lane & 15);
    const uint32_t lcol = (uint32_t)((lane >> 4) * 8);

    for (int c = 0; c < KCN; c++) {
        if (c + 1 < KCN) { prefetch((c + 1) * CH, (c + 1) & 1); cp_wait1(); }
        else             { cp_wait0(); }
        __syncthreads();

        const uint32_t sbase = sb + (c & 1) * STAGE_B;
        const uint32_t sAhi = sbase;
        const uint32_t sAlo = sbase + TILE_B;
        const uint32_t sBhi = sbase + 2 * TILE_B;
        const uint32_t sBlo = sbase + 3 * TILE_B;

#pragma unroll
        for (int kk = 0; kk < CH; kk += 16) {
            uint32_t ah[2][4], al[2][4];
            ldmx4(ah[0], sAhi + ((wm + lrow) * PADC + kk + lcol) * 2);
            ldmx4(ah[1], sAhi + ((wm + 16 + lrow) * PADC + kk + lcol) * 2);
            ldmx4(al[0], sAlo + ((wm + lrow) * PADC + kk + lcol) * 2);
            ldmx4(al[1], sAlo + ((wm + 16 + lrow) * PADC + kk + lcol) * 2);
#pragma unroll
            for (int p = 0; p < 4; p++) {
                uint32_t bh[4], bl[4];
                ldmx4(bh, sBhi + ((wn + 16 * p + lrow) * PADC + kk + lcol) * 2);
                ldmx4(bl, sBlo + ((wn + 16 * p + lrow) * PADC + kk + lcol) * 2);
#pragma unroll
                for (int q = 0; q < 2; q++) {
                    const int nt = 2 * p + q;
                    const uint32_t bh0 = bh[q], bh1 = bh[q + 2];
                    const uint32_t bl0 = bl[q], bl1 = bl[q + 2];
                    mma16816(acc[0][nt], ah[0], bh0, bh1);
                    mma16816(acc[1][nt], ah[1], bh0, bh1);
                    mma16816(acc[0][nt], ah[0], bl0, bl1);
                    mma16816(acc[1][nt], ah[1], bl0, bl1);
                    mma16816(acc[0][nt], al[0], bh0, bh1);
                    mma16816(acc[1][nt], al[1], bh0, bh1);
                }
            }
        }
        __syncthreads();
    }

    // Epilogue straight from accum regs
#pragma unroll
    for (int mt = 0; mt < 2; mt++) {
#pragma unroll
        for (int nt = 0; nt < 8; nt++) {
#pragma unroll
            for (int half = 0; half < 2; half++) {
                const int grow = bm + wm + mt * 16 + g + half * 8;
                const int gcol = bn + wn + nt * 8 + 2 * tig;
                float v0 = acc[mt][nt][half * 2 + 0] + bias[gcol];
                float v1 = acc[mt][nt][half * 2 + 1] + bias[gcol + 1];
                if (MODE == M_FF1) {
                    v0 = fmaxf(v0, 0.f);
                    v1 = fmaxf(v1, 0.f);
                    const float h0 = __bfloat162float(__float2bfloat16(v0));
                    const float h1 = __bfloat162float(__float2bfloat16(v1));
                    *(uint32_t*)(Chi + (size_t)grow * N + gcol) = pack_bf16(h0, h1);
                    *(uint32_t*)(Clo + (size_t)grow * N + gcol) =
                        pack_bf16(v0 - h0, v1 - h1);
                } else if (MODE == M_QKV) {
                    const int b_ = grow >> 11, s_ = grow & 2047;
                    const int h_ = gcol >> 6,  hd = gcol & 63;
                    const size_t oo =
                        (((size_t)(b_ * HH + h_) * SS) + s_) * HDD + hd;
                    const float h0 = __bfloat162float(__float2bfloat16(v0));
                    const float h1 = __bfloat162float(__float2bfloat16(v1));
                    *(uint32_t*)(Chi + oo) = pack_bf16(h0, h1);
                    *(uint32_t*)(Clo + oo) = pack_bf16(v0 - h0, v1 - h1);
                } else {
                    const size_t o = (size_t)grow * N + gcol;
                    v0 += res[o];
                    v1 += res[o + 1];
                    *(float2*)(Cf + o) = make_float2(v0, v1);
                }
            }
        }
    }
}

// ---------------------------------------------------------------------------
// Tensor-core flash attention (unchanged from R4)
// ---------------------------------------------------------------------------
__global__ void __launch_bounds__(128) attn_tc(
    const float* __restrict__ alibi,
    const __nv_bfloat16* __restrict__ Qhi, const __nv_bfloat16* __restrict__ Qlo,
    const __nv_bfloat16* __restrict__ Khi, const __nv_bfloat16* __restrict__ Klo,
    const __nv_bfloat16* __restrict__ Vthi, const __nv_bfloat16* __restrict__ Vtlo,
    __nv_bfloat16* __restrict__ Ohi, __nv_bfloat16* __restrict__ Olo)
{
    __shared__ __nv_bfloat16 skh[64 * 72], skl[64 * 72];
    __shared__ __nv_bfloat16 svh[64 * 72], svl[64 * 72];

    const int t = threadIdx.x, lane = t & 31, wid = t >> 5;
    const int g = lane >> 2, tig = lane & 3;
    const int qt = (int)(gridDim.x - 1) - (int)blockIdx.x;
    const int h = blockIdx.y, b = blockIdx.z;
    const int q0 = qt * 128, wm = wid * 32;
    const size_t bh = (size_t)(b * HH + h);

    const __nv_bfloat16* qh = Qhi + (bh * SS + q0) * HDD;
    const __nv_bfloat16* ql = Qlo + (bh * SS + q0) * HDD;
    const __nv_bfloat16* kh = Khi + bh * SS * HDD;
    const __nv_bfloat16* kl = Klo + bh * SS * HDD;
    const __nv_bfloat16* vh = Vthi + bh * (size_t)HDD * SS;
    const __nv_bfloat16* vl = Vtlo + bh * (size_t)HDD * SS;
    const float* ab = alibi + (size_t)h * SS * SS;

    float o[2][8][4];
#pragma unroll
    for (int i = 0; i < 2; i++)
#pragma unroll
        for (int j = 0; j < 8; j++)
#pragma unroll
            for (int c = 0; c < 4; c++) o[i][j][c] = 0.f;
    float mrow[2][2] = {{-1e30f, -1e30f}, {-1e30f, -1e30f}};
    float lrow[2][2] = {{0.f, 0.f}, {0.f, 0.f}};

    const int nkt = 2 * qt + 2;
    for (int kt = 0; kt < nkt; kt++) {
        const int k0 = kt * 64;
        __syncthreads();
#pragma unroll
        for (int i = 0; i < 4; i++) {
            const int f = t + 128 * i;
            const int r = f >> 3, c8 = (f & 7) * 8;
            *(uint4*)(skh + r * 72 + c8) =
                *(const uint4*)(kh + (size_t)(k0 + r) * HDD + c8);
            *(uint4*)(skl + r * 72 + c8) =
                *(const uint4*)(kl + (size_t)(k0 + r) * HDD + c8);
            *(uint4*)(svh + r * 72 + c8) =
                *(const uint4*)(vh + (size_t)r * SS + k0 + c8);
            *(uint4*)(svl + r * 72 + c8) =
                *(const uint4*)(vl + (size_t)r * SS + k0 + c8);
        }
        __syncthreads();

        float sacc[2][8][4];
#pragma unroll
        for (int i = 0; i < 2; i++)
#pragma unroll
            for (int j = 0; j < 8; j++)
#pragma unroll
                for (int c = 0; c < 4; c++) sacc[i][j][c] = 0.f;

#pragma unroll
        for (int kc = 0; kc < 4; kc++) {
            uint32_t a[2][4];
#pragma unroll
            for (int mt = 0; mt < 2; mt++) {
                const int row = wm + mt * 16 + g;
                a[mt][0] = *(const uint32_t*)(qh + (size_t)row * HDD + kc * 16 + 2 * tig);
                a[mt][1] = *(const uint32_t*)(qh + (size_t)(row + 8) * HDD + kc * 16 + 2 * tig);
                a[mt][2] = *(const uint32_t*)(qh + (size_t)row * HDD + kc * 16 + 8 + 2 * tig);
                a[mt][3] = *(const uint32_t*)(qh + (size_t)(row + 8) * HDD + kc * 16 + 8 + 2 * tig);
            }
#pragma unroll
            for (int nt = 0; nt < 8; nt++) {
                const __nv_bfloat16* kr = skh + (8 * nt + g) * 72 + kc * 16;
                const uint32_t b0 = *(const uint32_t*)(kr + 2 * tig);
                const uint32_t b1 = *(const uint32_t*)(kr + 8 + 2 * tig);
                mma16816(sacc[0][nt], a[0], b0, b1);
                mma16816(sacc[1][nt], a[1], b0, b1);
            }
#pragma unroll
            for (int nt = 0; nt < 8; nt++) {
                const __nv_bfloat16* kr = skl + (8 * nt + g) * 72 + kc * 16;
                const uint32_t b0 = *(const uint32_t*)(kr + 2 * tig);
                const uint32_t b1 = *(const uint32_t*)(kr + 8 + 2 * tig);
                mma16816(sacc[0][nt], a[0], b0, b1);
                mma16816(sacc[1][nt], a[1], b0, b1);
            }
#pragma unroll
            for (int mt = 0; mt < 2; mt++) {
                const int row = wm + mt * 16 + g;
                a[mt][0] = *(const uint32_t*)(ql + (size_t)row * HDD + kc * 16 + 2 * tig);
                a[mt][1] = *(const uint32_t*)(ql + (size_t)(row + 8) * HDD + kc * 16 + 2 * tig);
                a[mt][2] = *(const uint32_t*)(ql + (size_t)row * HDD + kc * 16 + 8 + 2 * tig);
                a[mt][3] = *(const uint32_t*)(ql + (size_t)(row + 8) * HDD + kc * 16 + 8 + 2 * tig);
            }
#pragma unroll
            for (int nt = 0; nt < 8; nt++) {
                const __nv_bfloat16* kr = skh + (8 * nt + g) * 72 + kc * 16;
                const uint32_t b0 = *(const uint32_t*)(kr + 2 * tig);
                const uint32_t b1 = *(const uint32_t*)(kr + 8 + 2 * tig);
                mma16816(sacc[0][nt], a[0], b0, b1);
                mma16816(sacc[1][nt], a[1], b0, b1);
            }
        }

#pragma unroll
        for (int mt = 0; mt < 2; mt++) {
#pragma unroll
            for (int hf = 0; hf < 2; hf++) {
                const int rowg = q0 + wm + 16 * mt + g + 8 * hf;
                const float* arow = ab + (size_t)rowg * SS + k0;
                float mx = -1e30f;
#pragma unroll
                for (int nt = 0; nt < 8; nt++) {
                    const int col = k0 + 8 * nt + 2 * tig;
                    const float2 al2 = *(const float2*)(arow + 8 * nt + 2 * tig);
                    float s0 = fmaf(sacc[mt][nt][2 * hf + 0], 0.125f, al2.x);
                    float s1 = fmaf(sacc[mt][nt][2 * hf + 1], 0.125f, al2.y);
                    if (col > rowg)     s0 = -1e30f;
                    if (col + 1 > rowg) s1 = -1e30f;
                    sacc[mt][nt][2 * hf + 0] = s0;
                    sacc[mt][nt][2 * hf + 1] = s1;
                    mx = fmaxf(mx, fmaxf(s0, s1));
                }
                mx = fmaxf(mx, __shfl_xor_sync(0xffffffffu, mx, 1));
                mx = fmaxf(mx, __shfl_xor_sync(0xffffffffu, mx, 2));
                const float mn = fmaxf(mrow[mt][hf], mx);
                const float corr = __expf(mrow[mt][hf] - mn);
                mrow[mt][hf] = mn;
                lrow[mt][hf] *= corr;
#pragma unroll
                for (int nt = 0; nt < 8; nt++) {
                    o[mt][nt][2 * hf + 0] *= corr;
                    o[mt][nt][2 * hf + 1] *= corr;
                }
                float ls = 0.f;
#pragma unroll
                for (int nt = 0; nt < 8; nt++) {
                    const float p0 = __expf(sacc[mt][nt][2 * hf + 0] - mn);
                    const float p1 = __expf(sacc[mt][nt][2 * hf + 1] - mn);
                    sacc[mt][nt][2 * hf + 0] = p0;
                    sacc[mt][nt][2 * hf + 1] = p1;
                    ls += p0 + p1;
                }
                ls += __shfl_xor_sync(0xffffffffu, ls, 1);
                ls += __shfl_xor_sync(0xffffffffu, ls, 2);
                lrow[mt][hf] += ls;
            }
        }

#pragma unroll
        for (int kc = 0; kc < 4; kc++) {
            uint32_t aph[2][4], apl[2][4];
#pragma unroll
            for (int mt = 0; mt < 2; mt++) {
#pragma unroll
                for (int q2 = 0; q2 < 2; q2++) {
                    const float p0 = sacc[mt][2 * kc + q2][0];
                    const float p1 = sacc[mt][2 * kc + q2][1];
                    const float p2 = sacc[mt][2 * kc + q2][2];
                    const float p3 = sacc[mt][2 * kc + q2][3];
                    const float h0 = __bfloat162float(__float2bfloat16(p0));
                    const float h1 = __bfloat162float(__float2bfloat16(p1));
                    const float h2 = __bfloat162float(__float2bfloat16(p2));
                    const float h3 = __bfloat162float(__float2bfloat16(p3));
                    aph[mt][2 * q2 + 0] = pack_bf16(h0, h1);
                    aph[mt][2 * q2 + 1] = pack_bf16(h2, h3);
                    apl[mt][2 * q2 + 0] = pack_bf16(p0 - h0, p1 - h1);
                    apl[mt][2 * q2 + 1] = pack_bf16(p2 - h2, p3 - h3);
                }
            }
#pragma unroll
            for (int nt = 0; nt < 8; nt++) {
                const __nv_bfloat16* vrh = svh + (8 * nt + g) * 72 + kc * 16;
                const __nv_bfloat16* vrl = svl + (8 * nt + g) * 72 + kc * 16;
                const uint32_t bh0 = *(const uint32_t*)(vrh + 2 * tig);
                const uint32_t bh1 = *(const uint32_t*)(vrh + 8 + 2 * tig);
                const uint32_t bl0 = *(const uint32_t*)(vrl + 2 * tig);
                const uint32_t bl1 = *(const uint32_t*)(vrl + 8 + 2 * tig);
                mma16816(o[0][nt], aph[0], bh0, bh1);
                mma16816(o[1][nt], aph[1], bh0, bh1);
                mma16816(o[0][nt], apl[0], bh0, bh1);
                mma16816(o[1][nt], apl[1], bh0, bh1);
                mma16816(o[0][nt], aph[0], bl0, bl1);
                mma16816(o[1][nt], aph[1], bl0, bl1);
            }
        }
    }

#pragma unroll
    for (int mt = 0; mt < 2; mt++) {
#pragma unroll
        for (int hf = 0; hf < 2; hf++) {
            const float inv = 1.f / lrow[mt][hf];
            const int srow = q0 + wm + 16 * mt + g + 8 * hf;
            const size_t base = ((size_t)b * SS + srow) * DD + h * HDD;
#pragma unroll
            for (int nt = 0; nt < 8; nt++) {
                const float v0 = o[mt][nt][2 * hf + 0] * inv;
                const float v1 = o[mt][nt][2 * hf + 1] * inv;
                const float h0 = __bfloat162float(__float2bfloat16(v0));
                const float h1 = __bfloat162float(__float2bfloat16(v1));
                *(uint32_t*)(Ohi + base + 8 * nt + 2 * tig) = pack_bf16(h0, h1);
                *(uint32_t*)(Olo + base + 8 * nt + 2 * tig) =
                    pack_bf16(v0 - h0, v1 - h1);
            }
        }
    }
}

// ---------------------------------------------------------------------------
// LayerNorm; SPLIT additionally emits bf16 hi/lo of the output
// ---------------------------------------------------------------------------
template <bool SPLIT>
__global__ void __launch_bounds__(256) ln_kernel(
    const float* __restrict__ in, const float* __restrict__ gw,
    const float* __restrict__ bw, float* __restrict__ out,
    __nv_bfloat16* __restrict__ ohi, __nv_bfloat16* __restrict__ olo)
{
    const int row = blockIdx.x;
    const int t   = threadIdx.x;
    const float* p = in + (size_t)row * DD;

    const float v0 = p[t], v1 = p[t + 256], v2 = p[t + 512];
    float s  = v0 + v1 + v2;
    float sq = fmaf(v0, v0, fmaf(v1, v1, v2 * v2));

#pragma unroll
    for (int off = 16; off; off >>= 1) {
        s  += __shfl_down_sync(0xffffffffu, s, off);
        sq += __shfl_down_sync(0xffffffffu, sq, off);
    }
    __shared__ float rs[8], rq[8];
    __shared__ float mean_s, inv_s;
    const int w = t >> 5, lane = t & 31;
    if (lane == 0) { rs[w] = s; rq[w] = sq; }
    __syncthreads();
    if (t == 0) {
        float S = 0.f, Q = 0.f;
#pragma unroll
        for (int i = 0; i < 8; i++) { S += rs[i]; Q += rq[i]; }
        const float mean = S * (1.f / 768.f);
        const float var  = Q * (1.f / 768.f) - mean * mean;
        mean_s = mean;
        inv_s  = rsqrtf(var + 1e-5f);
    }
    __syncthreads();
    const float mean = mean_s, inv = inv_s;
    float* po = out + (size_t)row * DD;
#pragma unroll
    for (int j = 0; j < 3; j++) {
        const int  c = t + 256 * j;
        const float vj = (j == 0) ? v0 : (j == 1) ? v1 : v2;
        const float r = fmaf((vj - mean) * inv, gw[c], bw[c]);
        po[c] = r;
        if (SPLIT) {
            const __nv_bfloat16 h = __float2bfloat16(r);
            ohi[(size_t)row * DD + c] = h;
            olo[(size_t)row * DD + c] = __float2bfloat16(r - __bfloat162float(h));
        }
    }
}

// ---------------------------------------------------------------------------
// Launcher
// ---------------------------------------------------------------------------
extern "C" void kernel_launch(void* const* d_in, const int* in_sizes, int n_in,
                              void* d_out, int out_size)
{
    (void)in_sizes; (void)n_in; (void)out_size;
    const float* x     = (const float*)d_in[0];
    const float* alibi = (const float*)d_in[1];
    const float* Wq = (const float*)d_in[2];  const float* bq = (const float*)d_in[3];
    const float* Wk = (const float*)d_in[4];  const float* bk = (const float*)d_in[5];
    const float* Wv = (const float*)d_in[6];  const float* bv = (const float*)d_in[7];
    const float* Wo = (const float*)d_in[8];  const float* bo = (const float*)d_in[9];
    const float* W1 = (const float*)d_in[10]; const float* b1 = (const float*)d_in[11];
    const float* W2 = (const float*)d_in[12]; const float* b2 = (const float*)d_in[13];
    const float* g1w = (const float*)d_in[14]; const float* be1 = (const float*)d_in[15];
    const float* g2w = (const float*)d_in[16]; const float* be2 = (const float*)d_in[17];
    float* out = (float*)d_out;

    float *r1, *y, *z;
    cudaGetSymbolAddress((void**)&r1, g_res1);
    cudaGetSymbolAddress((void**)&y,  g_y);
    cudaGetSymbolAddress((void**)&z,  g_z);

    __nv_bfloat16 *xhi, *xlo, *athi, *atlo, *yhi, *ylo, *h1hi, *h1lo;
    __nv_bfloat16 *qhi, *qlo, *khi, *klo, *vhi, *vlo, *vthi, *vtlo;
    __nv_bfloat16 *wqh, *wql, *wkh, *wkl, *wvh, *wvl, *woh, *wol, *w1h, *w1l, *w2h, *w2l;
    cudaGetSymbolAddress((void**)&xhi,  g_xhi);  cudaGetSymbolAddress((void**)&xlo,  g_xlo);
    cudaGetSymbolAddress((void**)&athi, g_athi); cudaGetSymbolAddress((void**)&atlo, g_atlo);
    cudaGetSymbolAddress((void**)&yhi,  g_yhi);  cudaGetSymbolAddress((void**)&ylo,  g_ylo);
    cudaGetSymbolAddress((void**)&h1hi, g_h1hi); cudaGetSymbolAddress((void**)&h1lo, g_h1lo);
    cudaGetSymbolAddress((void**)&qhi,  g_qhi);  cudaGetSymbolAddress((void**)&qlo,  g_qlo);
    cudaGetSymbolAddress((void**)&khi,  g_khi);  cudaGetSymbolAddress((void**)&klo,  g_klo);
    cudaGetSymbolAddress((void**)&vhi,  g_vhi);  cudaGetSymbolAddress((void**)&vlo,  g_vlo);
    cudaGetSymbolAddress((void**)&vthi, g_vthi); cudaGetSymbolAddress((void**)&vtlo, g_vtlo);
    cudaGetSymbolAddress((void**)&wqh, g_wqThi); cudaGetSymbolAddress((void**)&wql, g_wqTlo);
    cudaGetSymbolAddress((void**)&wkh, g_wkThi); cudaGetSymbolAddress((void**)&wkl, g_wkTlo);
    cudaGetSymbolAddress((void**)&wvh, g_wvThi); cudaGetSymbolAddress((void**)&wvl, g_wvTlo);
    cudaGetSymbolAddress((void**)&woh, g_woThi); cudaGetSymbolAddress((void**)&wol, g_woTlo);
    cudaGetSymbolAddress((void**)&w1h, g_w1Thi); cudaGetSymbolAddress((void**)&w1l, g_w1Tlo);
    cudaGetSymbolAddress((void**)&w2h, g_w2Thi); cudaGetSymbolAddress((void**)&w2l, g_w2Tlo);

    cudaFuncSetAttribute(mma_gemm<M_QKV>, cudaFuncAttributeMaxDynamicSharedMemorySize, GEMM_SMEM);
    cudaFuncSetAttribute(mma_gemm<M_WO>,  cudaFuncAttributeMaxDynamicSharedMemorySize, GEMM_SMEM);
    cudaFuncSetAttribute(mma_gemm<M_FF1>, cudaFuncAttributeMaxDynamicSharedMemorySize, GEMM_SMEM);
    cudaFuncSetAttribute(mma_gemm<M_FF2>, cudaFuncAttributeMaxDynamicSharedMemorySize, GEMM_SMEM);

    const dim3 tb(32, 8);

    convert_split<<<3072, 256>>>(x, xhi, xlo);
    transpose_split<<<dim3(24, 24), tb>>>(Wq, wqh, wql, DD, DD);
    transpose_split<<<dim3(24, 24), tb>>>(Wk, wkh, wkl, DD, DD);
    transpose_split<<<dim3(24, 24), tb>>>(Wv, wvh, wvl, DD, DD);
    transpose_split<<<dim3(24, 24), tb>>>(Wo, woh, wol, DD, DD);
    transpose_split<<<dim3(96, 24), tb>>>(W1, w1h, w1l, DD, DFF);
    transpose_split<<<dim3(24, 96), tb>>>(W2, w2h, w2l, DFF, DD);

    Qkv3 qkv;
    qkv.p[0] = {wqh, wql, bq, qhi, qlo};
    qkv.p[1] = {wkh, wkl, bk, khi, klo};
    qkv.p[2] = {wvh, wvl, bv, vhi, vlo};
    Qkv3 dummy = qkv;   // unused by non-QKV modes

    // fused QKV projections -> head-major bf16 hi/lo (grid.z selects weight)
    mma_gemm<M_QKV><<<dim3(6, 32, 3), 256, GEMM_SMEM>>>(
        xhi, xlo, nullptr, nullptr, nullptr, nullptr, nullptr, nullptr, nullptr,
        qkv, NROW, DD, DD);

    // V -> V^T per head
    vtrans<<<dim3(32, 24), 256>>>(vhi, vthi);
    vtrans<<<dim3(32, 24), 256>>>(vlo, vtlo);

    // tensor-core flash attention
    attn_tc<<<dim3(16, 12, 2), 128>>>(alibi, qhi, qlo, khi, klo,
                                      vthi, vtlo, athi, atlo);

    // output projection + residual, LN1
    mma_gemm<M_WO><<<dim3(6, 32), 256, GEMM_SMEM>>>(
        athi, atlo, woh, wol, bo, x, r1, nullptr, nullptr, dummy, NROW, DD, DD);
    ln_kernel<true><<<NROW, 256>>>(r1, g1w, be1, y, yhi, ylo);

    // FFN
    mma_gemm<M_FF1><<<dim3(24, 32), 256, GEMM_SMEM>>>(
        yhi, ylo, w1h, w1l, b1, nullptr, nullptr, h1hi, h1lo, dummy, NROW, DFF, DD);
    mma_gemm<M_FF2><<<dim3(6, 32), 256, GEMM_SMEM>>>(
        h1hi, h1lo, w2h, w2l, b2, y, z, nullptr, nullptr, dummy, NROW, DD, DFF);
    ln_kernel<false><<<NROW, 256>>>(z, g2w, be2, out, nullptr, nullptr);
}

// round 6
// speedup vs baseline: 3.1086x; 1.1594x over previous
#include <cuda_runtime.h>
#include <cuda_bf16.h>
#include <cstdint>
#include <cstddef>

// Problem constants
#define BB    2
#define SS    2048
#define DD    768
#define HH    12
#define HDD   64
#define DFF   3072
#define NROW  4096            // B*S

// GEMM tiling: 128x128 CTA tile, K chunks of 32, tiled global layout.
// One tile = 128 rows x 40 bf16 (32 valid + 8 pad) = 5120 halfwords = 10240 B.
#define CH     32
#define PADC   40
#define TILE_HW 5120                       // halfwords per tile
#define TILE_B  10240                      // bytes per tile
#define STAGE_B (4 * TILE_B)               // 40960 bytes per stage
#define GEMM_SMEM (2 * STAGE_B + 32)       // + mbarriers

// tiled array element count for an [R, K] matrix
#define TSZ(R, K) ((size_t)(R) * (K) / 32 * 40)

// ---------------------------------------------------------------------------
// Scratch (device globals: no allocation allowed)
// ---------------------------------------------------------------------------
__device__ float g_res1[NROW * DD];
__device__ float g_y[NROW * DD];
__device__ float g_z[NROW * DD];

// tiled bf16 hi/lo activations
__device__ __nv_bfloat16 g_xhi[TSZ(NROW, DD)],  g_xlo[TSZ(NROW, DD)];
__device__ __nv_bfloat16 g_athi[TSZ(NROW, DD)], g_atlo[TSZ(NROW, DD)];
__device__ __nv_bfloat16 g_yhi[TSZ(NROW, DD)],  g_ylo[TSZ(NROW, DD)];
__device__ __nv_bfloat16 g_h1hi[TSZ(NROW, DFF)], g_h1lo[TSZ(NROW, DFF)];

// head-major q/k/v bf16 hi/lo (linear, for attention)
__device__ __nv_bfloat16 g_qhi[BB*HH*SS*HDD], g_qlo[BB*HH*SS*HDD];
__device__ __nv_bfloat16 g_khi[BB*HH*SS*HDD], g_klo[BB*HH*SS*HDD];
__device__ __nv_bfloat16 g_vhi[BB*HH*SS*HDD], g_vlo[BB*HH*SS*HDD];
__device__ __nv_bfloat16 g_vthi[BB*HH*SS*HDD], g_vtlo[BB*HH*SS*HDD];

// tiled bf16 hi/lo transposed weights [N, K]
__device__ __nv_bfloat16 g_wqThi[TSZ(DD, DD)],  g_wqTlo[TSZ(DD, DD)];
__device__ __nv_bfloat16 g_wkThi[TSZ(DD, DD)],  g_wkTlo[TSZ(DD, DD)];
__device__ __nv_bfloat16 g_wvThi[TSZ(DD, DD)],  g_wvTlo[TSZ(DD, DD)];
__device__ __nv_bfloat16 g_woThi[TSZ(DD, DD)],  g_woTlo[TSZ(DD, DD)];
__device__ __nv_bfloat16 g_w1Thi[TSZ(DFF, DD)], g_w1Tlo[TSZ(DFF, DD)];
__device__ __nv_bfloat16 g_w2Thi[TSZ(DD, DFF)], g_w2Tlo[TSZ(DD, DFF)];

// ---------------------------------------------------------------------------
// helpers
// ---------------------------------------------------------------------------
__device__ __forceinline__ uint32_t smem_u32(const void* p) {
    uint32_t a;
    asm("{ .reg .u64 t; cvta.to.shared.u64 t, %1; cvt.u32.u64 %0, t; }"
        : "=r"(a) : "l"(p));
    return a;
}
__device__ __forceinline__ void mma16816(float* d, const uint32_t* a,
                                         uint32_t b0, uint32_t b1) {
    asm volatile(
        "mma.sync.aligned.m16n8k16.row.col.f32.bf16.bf16.f32 "
        "{%0,%1,%2,%3}, {%4,%5,%6,%7}, {%8,%9}, {%0,%1,%2,%3};"
        : "+f"(d[0]), "+f"(d[1]), "+f"(d[2]), "+f"(d[3])
        : "r"(a[0]), "r"(a[1]), "r"(a[2]), "r"(a[3]), "r"(b0), "r"(b1));
}
__device__ __forceinline__ uint32_t pack_bf16(float lo, float hi) {
    uint32_t r;
    asm("cvt.rn.bf16x2.f32 %0, %1, %2;" : "=r"(r) : "f"(hi), "f"(lo));
    return r;
}
__device__ __forceinline__ void ldmx4(uint32_t* r, uint32_t addr) {
    asm volatile("ldmatrix.sync.aligned.m8n8.x4.shared.b16 {%0,%1,%2,%3}, [%4];"
                 : "=r"(r[0]), "=r"(r[1]), "=r"(r[2]), "=r"(r[3]) : "r"(addr));
}
__device__ __forceinline__ void mbar_init(uint32_t mbar, uint32_t cnt) {
    asm volatile("mbarrier.init.shared.b64 [%0], %1;" :: "r"(mbar), "r"(cnt) : "memory");
}
__device__ __forceinline__ void mbar_wait(uint32_t mbar, uint32_t parity) {
    asm volatile(
        "{\n\t.reg .pred P;\n\t"
        "WL_%=:\n\t"
        "mbarrier.try_wait.parity.acquire.cta.shared::cta.b64 P, [%0], %1, 0x989680;\n\t"
        "@P bra.uni WD_%=;\n\t"
        "bra.uni WL_%=;\n\t"
        "WD_%=:\n\t}"
        :: "r"(mbar), "r"(parity) : "memory");
}
__device__ __forceinline__ void mbar_expect_tx(uint32_t mbar, uint32_t bytes) {
    asm volatile("mbarrier.arrive.expect_tx.shared.b64 _, [%0], %1;"
                 :: "r"(mbar), "r"(bytes) : "memory");
}
__device__ __forceinline__ void bulkcp(uint32_t dst, const void* src,
                                       uint32_t bytes, uint32_t mbar) {
    asm volatile(
        "cp.async.bulk.shared::cta.global.mbarrier::complete_tx::bytes "
        "[%0], [%1], %2, [%3];"
        :: "r"(dst), "l"(src), "r"(bytes), "r"(mbar) : "memory");
}
// tiled layout offset: matrix [R, K] -> tile (r>>7, k>>5), pitch 40
__device__ __forceinline__ size_t toff(int row, int col, int kcn) {
    return (size_t)((row >> 7) * kcn + (col >> 5)) * TILE_HW +
           (row & 127) * PADC + (col & 31);
}

// ---------------------------------------------------------------------------
// fp32 [4096,768] -> tiled bf16 hi/lo
// ---------------------------------------------------------------------------
__global__ void __launch_bounds__(256) convert_split(
    const float* __restrict__ in, __nv_bfloat16* __restrict__ hi,
    __nv_bfloat16* __restrict__ lo)
{
    const int i = blockIdx.x * 256 + threadIdx.x;
    const int e = 4 * i;
    const int row = e / DD, col = e - row * DD;
    float4 v = ((const float4*)in)[i];
    float f[4] = {v.x, v.y, v.z, v.w};
    __nv_bfloat16 h[4], l[4];
#pragma unroll
    for (int j = 0; j < 4; j++) {
        h[j] = __float2bfloat16(f[j]);
        l[j] = __float2bfloat16(f[j] - __bfloat162float(h[j]));
    }
    const size_t o = toff(row, col, DD / 32);
    *(uint2*)(hi + o) = *(uint2*)h;
    *(uint2*)(lo + o) = *(uint2*)l;
}

// ---------------------------------------------------------------------------
// W[K,N] fp32 -> tiled Wt[N,K] bf16 hi/lo
// ---------------------------------------------------------------------------
__global__ void __launch_bounds__(256) transpose_split(
    const float* __restrict__ W, __nv_bfloat16* __restrict__ Thi,
    __nv_bfloat16* __restrict__ Tlo, int K, int N)
{
    __shared__ float tile[32][33];
    const int k0 = blockIdx.y * 32, n0 = blockIdx.x * 32;
    const int tx = threadIdx.x, ty = threadIdx.y;   // (32, 8)
#pragma unroll
    for (int i = 0; i < 4; i++)
        tile[ty + 8 * i][tx] = W[(size_t)(k0 + ty + 8 * i) * N + n0 + tx];
    __syncthreads();
    const int kcn = K >> 5;
#pragma unroll
    for (int i = 0; i < 4; i++) {
        const float vv = tile[tx][ty + 8 * i];
        const __nv_bfloat16 h = __float2bfloat16(vv);
        const size_t o = toff(n0 + ty + 8 * i, k0 + tx, kcn);
        Thi[o] = h;
        Tlo[o] = __float2bfloat16(vv - __bfloat162float(h));
    }
}

// ---------------------------------------------------------------------------
// per-head V transpose: [s, hd] -> [hd, s] (bf16, linear)
// ---------------------------------------------------------------------------
__global__ void __launch_bounds__(256) vtrans(
    const __nv_bfloat16* __restrict__ in, __nv_bfloat16* __restrict__ out)
{
    __shared__ __nv_bfloat16 sm[64][72];
    const int s0 = blockIdx.x * 64;
    const size_t bh = blockIdx.y;
    const __nv_bfloat16* src = in + bh * SS * HDD;
    __nv_bfloat16* dst = out + bh * (size_t)HDD * SS;
    const int t = threadIdx.x;
    const int r = t >> 2, cq = (t & 3) * 16;
    *(uint4*)(&sm[r][cq])     = *(const uint4*)(src + (size_t)(s0 + r) * HDD + cq);
    *(uint4*)(&sm[r][cq + 8]) = *(const uint4*)(src + (size_t)(s0 + r) * HDD + cq + 8);
    __syncthreads();
    uint32_t w[8];
#pragma unroll
    for (int j = 0; j < 8; j++) {
        const __nv_bfloat16 a = sm[cq + 2 * j][r], b = sm[cq + 2 * j + 1][r];
        w[j] = ((uint32_t)(*(const uint16_t*)&b) << 16) | *(const uint16_t*)&a;
    }
#pragma unroll
    for (int j = 0; j < 4; j++)
        *(uint2*)(dst + (size_t)r * SS + s0 + cq + 4 * j) =
            make_uint2(w[2 * j], w[2 * j + 1]);
}

// ---------------------------------------------------------------------------
// mma.sync GEMM v3: tiled operands + cp.async.bulk double buffer + mbarrier.
// ---------------------------------------------------------------------------
#define M_QKV 0
#define M_WO  1
#define M_FF1 2
#define M_FF2 3

struct Ptr3 {
    const __nv_bfloat16 *bh, *bl;
    const float* bias;
    __nv_bfloat16 *ch, *cl;
};
struct Qkv3 { Ptr3 p[3]; };

template <int MODE>
__global__ void __launch_bounds__(256) mma_gemm(
    const __nv_bfloat16* __restrict__ Ahi, const __nv_bfloat16* __restrict__ Alo,
    const __nv_bfloat16* __restrict__ Bhi_, const __nv_bfloat16* __restrict__ Blo_,
    const float* __restrict__ bias_, const float* __restrict__ res,
    float* __restrict__ Cf, __nv_bfloat16* __restrict__ Chi_,
    __nv_bfloat16* __restrict__ Clo_, Qkv3 qkv, int M, int N, int K)
{
    extern __shared__ char smem[];
    const uint32_t sb = smem_u32(smem);
    const uint32_t mbb = sb + 2 * STAGE_B;

    const int t    = threadIdx.x;
    const int lane = t & 31, wid = t >> 5;
    const int wm   = (wid & 3) * 32;
    const int wn   = (wid >> 2) * 64;
    const int bm   = blockIdx.y * 128, bn = blockIdx.x * 128;
    const int g    = lane >> 2, tig = lane & 3;

    const __nv_bfloat16* Bhi;
    const __nv_bfloat16* Blo;
    const float* bias;
    __nv_bfloat16 *Chi, *Clo;
    if (MODE == M_QKV) {
        const Ptr3& p = qkv.p[blockIdx.z];
        Bhi = p.bh; Blo = p.bl; bias = p.bias; Chi = p.ch; Clo = p.cl;
    } else {
        Bhi = Bhi_; Blo = Blo_; bias = bias_; Chi = Chi_; Clo = Clo_;
    }

    if (t == 0) { mbar_init(mbb, 1); mbar_init(mbb + 8, 1); }
    __syncthreads();

    float acc[2][8][4];
#pragma unroll
    for (int i = 0; i < 2; i++)
#pragma unroll
        for (int j = 0; j < 8; j++)
#pragma unroll
            for (int c = 0; c < 4; c++) acc[i][j][c] = 0.f;

    const int KCN = K >> 5;
    const int arb = bm >> 7, brb = bn >> 7;

    auto issue = [&](int c, int stage) {
        if (t == 0) {
            const uint32_t mbar = mbb + stage * 8;
            mbar_expect_tx(mbar, STAGE_B);
            const uint32_t d = sb + stage * STAGE_B;
            bulkcp(d,              Ahi + ((size_t)arb * KCN + c) * TILE_HW, TILE_B, mbar);
            bulkcp(d + TILE_B,     Alo + ((size_t)arb * KCN + c) * TILE_HW, TILE_B, mbar);
            bulkcp(d + 2 * TILE_B, Bhi + ((size_t)brb * KCN + c) * TILE_HW, TILE_B, mbar);
            bulkcp(d + 3 * TILE_B, Blo + ((size_t)brb * KCN + c) * TILE_HW, TILE_B, mbar);
        }
    };

    uint32_t ph[2] = {0, 0};
    issue(0, 0);

    const uint32_t lrow = (uint32_t)(lane & 15);
    const uint32_t lcol = (uint32_t)((lane >> 4) * 8);

    for (int c = 0; c < KCN; c++) {
        if (c + 1 < KCN) issue(c + 1, (c + 1) & 1);
        const int st = c & 1;
        mbar_wait(mbb + st * 8, ph[st]);
        ph[st] ^= 1;

        const uint32_t sbase = sb + st * STAGE_B;
        const uint32_t sAhi = sbase;
        const uint32_t sAlo = sbase + TILE_B;
        const uint32_t sBhi = sbase + 2 * TILE_B;
        const uint32_t sBlo = sbase + 3 * TILE_B;

#pragma unroll
        for (int kk = 0; kk < CH; kk += 16) {
            uint32_t ah[2][4], al[2][4];
            ldmx4(ah[0], sAhi + ((wm + lrow) * PADC + kk + lcol) * 2);
            ldmx4(ah[1], sAhi + ((wm + 16 + lrow) * PADC + kk + lcol) * 2);
            ldmx4(al[0], sAlo + ((wm + lrow) * PADC + kk + lcol) * 2);
            ldmx4(al[1], sAlo + ((wm + 16 + lrow) * PADC + kk + lcol) * 2);
#pragma unroll
            for (int p = 0; p < 4; p++) {
                uint32_t bh[4], bl[4];
                ldmx4(bh, sBhi + ((wn + 16 * p + lrow) * PADC + kk + lcol) * 2);
                ldmx4(bl, sBlo + ((wn + 16 * p + lrow) * PADC + kk + lcol) * 2);
#pragma unroll
                for (int q = 0; q < 2; q++) {
                    const int nt = 2 * p + q;
                    const uint32_t bh0 = bh[q], bh1 = bh[q + 2];
                    const uint32_t bl0 = bl[q], bl1 = bl[q + 2];
                    mma16816(acc[0][nt], ah[0], bh0, bh1);
                    mma16816(acc[1][nt], ah[1], bh0, bh1);
                    mma16816(acc[0][nt], ah[0], bl0, bl1);
                    mma16816(acc[1][nt], ah[1], bl0, bl1);
                    mma16816(acc[0][nt], al[0], bh0, bh1);
                    mma16816(acc[1][nt], al[1], bh0, bh1);
                }
            }
        }
        __syncthreads();
    }

    // Epilogue straight from accum regs
    const int okcn = N >> 5;
#pragma unroll
    for (int mt = 0; mt < 2; mt++) {
#pragma unroll
        for (int nt = 0; nt < 8; nt++) {
#pragma unroll
            for (int half = 0; half < 2; half++) {
                const int grow = bm + wm + mt * 16 + g + half * 8;
                const int gcol = bn + wn + nt * 8 + 2 * tig;
                float v0 = acc[mt][nt][half * 2 + 0] + bias[gcol];
                float v1 = acc[mt][nt][half * 2 + 1] + bias[gcol + 1];
                if (MODE == M_FF1) {
                    v0 = fmaxf(v0, 0.f);
                    v1 = fmaxf(v1, 0.f);
                    const float h0 = __bfloat162float(__float2bfloat16(v0));
                    const float h1 = __bfloat162float(__float2bfloat16(v1));
                    const size_t o = toff(grow, gcol, okcn);
                    *(uint32_t*)(Chi + o) = pack_bf16(h0, h1);
                    *(uint32_t*)(Clo + o) = pack_bf16(v0 - h0, v1 - h1);
                } else if (MODE == M_QKV) {
                    const int b_ = grow >> 11, s_ = grow & 2047;
                    const int h_ = gcol >> 6,  hd = gcol & 63;
                    const size_t oo =
                        (((size_t)(b_ * HH + h_) * SS) + s_) * HDD + hd;
                    const float h0 = __bfloat162float(__float2bfloat16(v0));
                    const float h1 = __bfloat162float(__float2bfloat16(v1));
                    *(uint32_t*)(Chi + oo) = pack_bf16(h0, h1);
                    *(uint32_t*)(Clo + oo) = pack_bf16(v0 - h0, v1 - h1);
                } else {
                    const size_t o = (size_t)grow * N + gcol;
                    v0 += res[o];
                    v1 += res[o + 1];
                    *(float2*)(Cf + o) = make_float2(v0, v1);
                }
            }
        }
    }
}

// ---------------------------------------------------------------------------
// Tensor-core flash attention (R4 core; epilogue writes TILED athi/atlo)
// ---------------------------------------------------------------------------
__global__ void __launch_bounds__(128) attn_tc(
    const float* __restrict__ alibi,
    const __nv_bfloat16* __restrict__ Qhi, const __nv_bfloat16* __restrict__ Qlo,
    const __nv_bfloat16* __restrict__ Khi, const __nv_bfloat16* __restrict__ Klo,
    const __nv_bfloat16* __restrict__ Vthi, const __nv_bfloat16* __restrict__ Vtlo,
    __nv_bfloat16* __restrict__ Ohi, __nv_bfloat16* __restrict__ Olo)
{
    __shared__ __nv_bfloat16 skh[64 * 72], skl[64 * 72];
    __shared__ __nv_bfloat16 svh[64 * 72], svl[64 * 72];

    const int t = threadIdx.x, lane = t & 31, wid = t >> 5;
    const int g = lane >> 2, tig = lane & 3;
    const int qt = (int)(gridDim.x - 1) - (int)blockIdx.x;
    const int h = blockIdx.y, b = blockIdx.z;
    const int q0 = qt * 128, wm = wid * 32;
    const size_t bh = (size_t)(b * HH + h);

    const __nv_bfloat16* qh = Qhi + (bh * SS + q0) * HDD;
    const __nv_bfloat16* ql = Qlo + (bh * SS + q0) * HDD;
    const __nv_bfloat16* kh = Khi + bh * SS * HDD;
    const __nv_bfloat16* kl = Klo + bh * SS * HDD;
    const __nv_bfloat16* vh = Vthi + bh * (size_t)HDD * SS;
    const __nv_bfloat16* vl = Vtlo + bh * (size_t)HDD * SS;
    const float* ab = alibi + (size_t)h * SS * SS;

    float o[2][8][4];
#pragma unroll
    for (int i = 0; i < 2; i++)
#pragma unroll
        for (int j = 0; j < 8; j++)
#pragma unroll
            for (int c = 0; c < 4; c++) o[i][j][c] = 0.f;
    float mrow[2][2] = {{-1e30f, -1e30f}, {-1e30f, -1e30f}};
    float lrow[2][2] = {{0.f, 0.f}, {0.f, 0.f}};

    const int nkt = 2 * qt + 2;
    for (int kt = 0; kt < nkt; kt++) {
        const int k0 = kt * 64;
        __syncthreads();
#pragma unroll
        for (int i = 0; i < 4; i++) {
            const int f = t + 128 * i;
            const int r = f >> 3, c8 = (f & 7) * 8;
            *(uint4*)(skh + r * 72 + c8) =
                *(const uint4*)(kh + (size_t)(k0 + r) * HDD + c8);
            *(uint4*)(skl + r * 72 + c8) =
                *(const uint4*)(kl + (size_t)(k0 + r) * HDD + c8);
            *(uint4*)(svh + r * 72 + c8) =
                *(const uint4*)(vh + (size_t)r * SS + k0 + c8);
            *(uint4*)(svl + r * 72 + c8) =
                *(const uint4*)(vl + (size_t)r * SS + k0 + c8);
        }
        __syncthreads();

        float sacc[2][8][4];
#pragma unroll
        for (int i = 0; i < 2; i++)
#pragma unroll
            for (int j = 0; j < 8; j++)
#pragma unroll
                for (int c = 0; c < 4; c++) sacc[i][j][c] = 0.f;

#pragma unroll
        for (int kc = 0; kc < 4; kc++) {
            uint32_t a[2][4];
#pragma unroll
            for (int mt = 0; mt < 2; mt++) {
                const int row = wm + mt * 16 + g;
                a[mt][0] = *(const uint32_t*)(qh + (size_t)row * HDD + kc * 16 + 2 * tig);
                a[mt][1] = *(const uint32_t*)(qh + (size_t)(row + 8) * HDD + kc * 16 + 2 * tig);
                a[mt][2] = *(const uint32_t*)(qh + (size_t)row * HDD + kc * 16 + 8 + 2 * tig);
                a[mt][3] = *(const uint32_t*)(qh + (size_t)(row + 8) * HDD + kc * 16 + 8 + 2 * tig);
            }
#pragma unroll
            for (int nt = 0; nt < 8; nt++) {
                const __nv_bfloat16* kr = skh + (8 * nt + g) * 72 + kc * 16;
                const uint32_t b0 = *(const uint32_t*)(kr + 2 * tig);
                const uint32_t b1 = *(const uint32_t*)(kr + 8 + 2 * tig);
                mma16816(sacc[0][nt], a[0], b0, b1);
                mma16816(sacc[1][nt], a[1], b0, b1);
            }
#pragma unroll
            for (int nt = 0; nt < 8; nt++) {
                const __nv_bfloat16* kr = skl + (8 * nt + g) * 72 + kc * 16;
                const uint32_t b0 = *(const uint32_t*)(kr + 2 * tig);
                const uint32_t b1 = *(const uint32_t*)(kr + 8 + 2 * tig);
                mma16816(sacc[0][nt], a[0], b0, b1);
                mma16816(sacc[1][nt], a[1], b0, b1);
            }
#pragma unroll
            for (int mt = 0; mt < 2; mt++) {
                const int row = wm + mt * 16 + g;
                a[mt][0] = *(const uint32_t*)(ql + (size_t)row * HDD + kc * 16 + 2 * tig);
                a[mt][1] = *(const uint32_t*)(ql + (size_t)(row + 8) * HDD + kc * 16 + 2 * tig);
                a[mt][2] = *(const uint32_t*)(ql + (size_t)row * HDD + kc * 16 + 8 + 2 * tig);
                a[mt][3] = *(const uint32_t*)(ql + (size_t)(row + 8) * HDD + kc * 16 + 8 + 2 * tig);
            }
#pragma unroll
            for (int nt = 0; nt < 8; nt++) {
                const __nv_bfloat16* kr = skh + (8 * nt + g) * 72 + kc * 16;
                const uint32_t b0 = *(const uint32_t*)(kr + 2 * tig);
                const uint32_t b1 = *(const uint32_t*)(kr + 8 + 2 * tig);
                mma16816(sacc[0][nt], a[0], b0, b1);
                mma16816(sacc[1][nt], a[1], b0, b1);
            }
        }

#pragma unroll
        for (int mt = 0; mt < 2; mt++) {
#pragma unroll
            for (int hf = 0; hf < 2; hf++) {
                const int rowg = q0 + wm + 16 * mt + g + 8 * hf;
                const float* arow = ab + (size_t)rowg * SS + k0;
                float mx = -1e30f;
#pragma unroll
                for (int nt = 0; nt < 8; nt++) {
                    const int col = k0 + 8 * nt + 2 * tig;
                    const float2 al2 = *(const float2*)(arow + 8 * nt + 2 * tig);
                    float s0 = fmaf(sacc[mt][nt][2 * hf + 0], 0.125f, al2.x);
                    float s1 = fmaf(sacc[mt][nt][2 * hf + 1], 0.125f, al2.y);
                    if (col > rowg)     s0 = -1e30f;
                    if (col + 1 > rowg) s1 = -1e30f;
                    sacc[mt][nt][2 * hf + 0] = s0;
                    sacc[mt][nt][2 * hf + 1] = s1;
                    mx = fmaxf(mx, fmaxf(s0, s1));
                }
                mx = fmaxf(mx, __shfl_xor_sync(0xffffffffu, mx, 1));
                mx = fmaxf(mx, __shfl_xor_sync(0xffffffffu, mx, 2));
                const float mn = fmaxf(mrow[mt][hf], mx);
                const float corr = __expf(mrow[mt][hf] - mn);
                mrow[mt][hf] = mn;
                lrow[mt][hf] *= corr;
#pragma unroll
                for (int nt = 0; nt < 8; nt++) {
                    o[mt][nt][2 * hf + 0] *= corr;
                    o[mt][nt][2 * hf + 1] *= corr;
                }
                float ls = 0.f;
#pragma unroll
                for (int nt = 0; nt < 8; nt++) {
                    const float p0 = __expf(sacc[mt][nt][2 * hf + 0] - mn);
                    const float p1 = __expf(sacc[mt][nt][2 * hf + 1] - mn);
                    sacc[mt][nt][2 * hf + 0] = p0;
                    sacc[mt][nt][2 * hf + 1] = p1;
                    ls += p0 + p1;
                }
                ls += __shfl_xor_sync(0xffffffffu, ls, 1);
                ls += __shfl_xor_sync(0xffffffffu, ls, 2);
                lrow[mt][hf] += ls;
            }
        }

#pragma unroll
        for (int kc = 0; kc < 4; kc++) {
            uint32_t aph[2][4], apl[2][4];
#pragma unroll
            for (int mt = 0; mt < 2; mt++) {
#pragma unroll
                for (int q2 = 0; q2 < 2; q2++) {
                    const float p0 = sacc[mt][2 * kc + q2][0];
                    const float p1 = sacc[mt][2 * kc + q2][1];
                    const float p2 = sacc[mt][2 * kc + q2][2];
                    const float p3 = sacc[mt][2 * kc + q2][3];
                    const float h0 = __bfloat162float(__float2bfloat16(p0));
                    const float h1 = __bfloat162float(__float2bfloat16(p1));
                    const float h2 = __bfloat162float(__float2bfloat16(p2));
                    const float h3 = __bfloat162float(__float2bfloat16(p3));
                    aph[mt][2 * q2 + 0] = pack_bf16(h0, h1);
                    aph[mt][2 * q2 + 1] = pack_bf16(h2, h3);
                    apl[mt][2 * q2 + 0] = pack_bf16(p0 - h0, p1 - h1);
                    apl[mt][2 * q2 + 1] = pack_bf16(p2 - h2, p3 - h3);
                }
            }
#pragma unroll
            for (int nt = 0; nt < 8; nt++) {
                const __nv_bfloat16* vrh = svh + (8 * nt + g) * 72 + kc * 16;
                const __nv_bfloat16* vrl = svl + (8 * nt + g) * 72 + kc * 16;
                const uint32_t bh0 = *(const uint32_t*)(vrh + 2 * tig);
                const uint32_t bh1 = *(const uint32_t*)(vrh + 8 + 2 * tig);
                const uint32_t bl0 = *(const uint32_t*)(vrl + 2 * tig);
                const uint32_t bl1 = *(const uint32_t*)(vrl + 8 + 2 * tig);
                mma16816(o[0][nt], aph[0], bh0, bh1);
                mma16816(o[1][nt], aph[1], bh0, bh1);
                mma16816(o[0][nt], apl[0], bh0, bh1);
                mma16816(o[1][nt], apl[1], bh0, bh1);
                mma16816(o[0][nt], aph[0], bl0, bl1);
                mma16816(o[1][nt], aph[1], bl0, bl1);
            }
        }
    }

    // epilogue: normalize, write TILED bf16 hi/lo (row-major [b*S+s, D] tiles)
#pragma unroll
    for (int mt = 0; mt < 2; mt++) {
#pragma unroll
        for (int hf = 0; hf < 2; hf++) {
            const float inv = 1.f / lrow[mt][hf];
            const int srow = q0 + wm + 16 * mt + g + 8 * hf;
            const int rowg = b * SS + srow;
#pragma unroll
            for (int nt = 0; nt < 8; nt++) {
                const int col = h * HDD + 8 * nt + 2 * tig;
                const float v0 = o[mt][nt][2 * hf + 0] * inv;
                const float v1 = o[mt][nt][2 * hf + 1] * inv;
                const float h0 = __bfloat162float(__float2bfloat16(v0));
                const float h1 = __bfloat162float(__float2bfloat16(v1));
                const size_t oo = toff(rowg, col, DD / 32);
                *(uint32_t*)(Ohi + oo) = pack_bf16(h0, h1);
                *(uint32_t*)(Olo + oo) = pack_bf16(v0 - h0, v1 - h1);
            }
        }
    }
}

// ---------------------------------------------------------------------------
// LayerNorm; SPLIT emits tiled bf16 hi/lo
// ---------------------------------------------------------------------------
template <bool SPLIT>
__global__ void __launch_bounds__(256) ln_kernel(
    const float* __restrict__ in, const float* __restrict__ gw,
    const float* __restrict__ bw, float* __restrict__ out,
    __nv_bfloat16* __restrict__ ohi, __nv_bfloat16* __restrict__ olo)
{
    const int row = blockIdx.x;
    const int t   = threadIdx.x;
    const float* p = in + (size_t)row * DD;

    const float v0 = p[t], v1 = p[t + 256], v2 = p[t + 512];
    float s  = v0 + v1 + v2;
    float sq = fmaf(v0, v0, fmaf(v1, v1, v2 * v2));

#pragma unroll
    for (int off = 16; off; off >>= 1) {
        s  += __shfl_down_sync(0xffffffffu, s, off);
        sq += __shfl_down_sync(0xffffffffu, sq, off);
    }
    __shared__ float rs[8], rq[8];
    __shared__ float mean_s, inv_s;
    const int w = t >> 5, lane = t & 31;
    if (lane == 0) { rs[w] = s; rq[w] = sq; }
    __syncthreads();
    if (t == 0) {
        float S = 0.f, Q = 0.f;
#pragma unroll
        for (int i = 0; i < 8; i++) { S += rs[i]; Q += rq[i]; }
        const float mean = S * (1.f / 768.f);
        const float var  = Q * (1.f / 768.f) - mean * mean;
        mean_s = mean;
        inv_s  = rsqrtf(var + 1e-5f);
    }
    __syncthreads();
    const float mean = mean_s, inv = inv_s;
    float* po = out + (size_t)row * DD;
#pragma unroll
    for (int j = 0; j < 3; j++) {
        const int  c = t + 256 * j;
        const float vj = (j == 0) ? v0 : (j == 1) ? v1 : v2;
        const float r = fmaf((vj - mean) * inv, gw[c], bw[c]);
        po[c] = r;
        if (SPLIT) {
            const __nv_bfloat16 h = __float2bfloat16(r);
            const size_t o = toff(row, c, DD / 32);
            ohi[o] = h;
            olo[o] = __float2bfloat16(r - __bfloat162float(h));
        }
    }
}

// ---------------------------------------------------------------------------
// Launcher
// ---------------------------------------------------------------------------
extern "C" void kernel_launch(void* const* d_in, const int* in_sizes, int n_in,
                              void* d_out, int out_size)
{
    (void)in_sizes; (void)n_in; (void)out_size;
    const float* x     = (const float*)d_in[0];
    const float* alibi = (const float*)d_in[1];
    const float* Wq = (const float*)d_in[2];  const float* bq = (const float*)d_in[3];
    const float* Wk = (const float*)d_in[4];  const float* bk = (const float*)d_in[5];
    const float* Wv = (const float*)d_in[6];  const float* bv = (const float*)d_in[7];
    const float* Wo = (const float*)d_in[8];  const float* bo = (const float*)d_in[9];
    const float* W1 = (const float*)d_in[10]; const float* b1 = (const float*)d_in[11];
    const float* W2 = (const float*)d_in[12]; const float* b2 = (const float*)d_in[13];
    const float* g1w = (const float*)d_in[14]; const float* be1 = (const float*)d_in[15];
    const float* g2w = (const float*)d_in[16]; const float* be2 = (const float*)d_in[17];
    float* out = (float*)d_out;

    float *r1, *y, *z;
    cudaGetSymbolAddress((void**)&r1, g_res1);
    cudaGetSymbolAddress((void**)&y,  g_y);
    cudaGetSymbolAddress((void**)&z,  g_z);

    __nv_bfloat16 *xhi, *xlo, *athi, *atlo, *yhi, *ylo, *h1hi, *h1lo;
    __nv_bfloat16 *qhi, *qlo, *khi, *klo, *vhi, *vlo, *vthi, *vtlo;
    __nv_bfloat16 *wqh, *wql, *wkh, *wkl, *wvh, *wvl, *woh, *wol, *w1h, *w1l, *w2h, *w2l;
    cudaGetSymbolAddress((void**)&xhi,  g_xhi);  cudaGetSymbolAddress((void**)&xlo,  g_xlo);
    cudaGetSymbolAddress((void**)&athi, g_athi); cudaGetSymbolAddress((void**)&atlo, g_atlo);
    cudaGetSymbolAddress((void**)&yhi,  g_yhi);  cudaGetSymbolAddress((void**)&ylo,  g_ylo);
    cudaGetSymbolAddress((void**)&h1hi, g_h1hi); cudaGetSymbolAddress((void**)&h1lo, g_h1lo);
    cudaGetSymbolAddress((void**)&qhi,  g_qhi);  cudaGetSymbolAddress((void**)&qlo,  g_qlo);
    cudaGetSymbolAddress((void**)&khi,  g_khi);  cudaGetSymbolAddress((void**)&klo,  g_klo);
    cudaGetSymbolAddress((void**)&vhi,  g_vhi);  cudaGetSymbolAddress((void**)&vlo,  g_vlo);
    cudaGetSymbolAddress((void**)&vthi, g_vthi); cudaGetSymbolAddress((void**)&vtlo, g_vtlo);
    cudaGetSymbolAddress((void**)&wqh, g_wqThi); cudaGetSymbolAddress((void**)&wql, g_wqTlo);
    cudaGetSymbolAddress((void**)&wkh, g_wkThi); cudaGetSymbolAddress((void**)&wkl, g_wkTlo);
    cudaGetSymbolAddress((void**)&wvh, g_wvThi); cudaGetSymbolAddress((void**)&wvl, g_wvTlo);
    cudaGetSymbolAddress((void**)&woh, g_woThi); cudaGetSymbolAddress((void**)&wol, g_woTlo);
    cudaGetSymbolAddress((void**)&w1h, g_w1Thi); cudaGetSymbolAddress((void**)&w1l, g_w1Tlo);
    cudaGetSymbolAddress((void**)&w2h, g_w2Thi); cudaGetSymbolAddress((void**)&w2l, g_w2Tlo);

    cudaFuncSetAttribute(mma_gemm<M_QKV>, cudaFuncAttributeMaxDynamicSharedMemorySize, GEMM_SMEM);
    cudaFuncSetAttribute(mma_gemm<M_WO>,  cudaFuncAttributeMaxDynamicSharedMemorySize, GEMM_SMEM);
    cudaFuncSetAttribute(mma_gemm<M_FF1>, cudaFuncAttributeMaxDynamicSharedMemorySize, GEMM_SMEM);
    cudaFuncSetAttribute(mma_gemm<M_FF2>, cudaFuncAttributeMaxDynamicSharedMemorySize, GEMM_SMEM);

    const dim3 tb(32, 8);

    Qkv3 qkv;
    qkv.p[0] = {wqh, wql, bq, qhi, qlo};
    qkv.p[1] = {wkh, wkl, bk, khi, klo};
    qkv.p[2] = {wvh, wvl, bv, vhi, vlo};
    Qkv3 dummy = qkv;

    // launches 1-5: prep needed by QKV (+Wo, as filler so launch #6 = QKV gemm
    // and gets captured by ncu's -s 5 -c 1)
    convert_split<<<3072, 256>>>(x, xhi, xlo);
    transpose_split<<<dim3(24, 24), tb>>>(Wq, wqh, wql, DD, DD);
    transpose_split<<<dim3(24, 24), tb>>>(Wk, wkh, wkl, DD, DD);
    transpose_split<<<dim3(24, 24), tb>>>(Wv, wvh, wvl, DD, DD);
    transpose_split<<<dim3(24, 24), tb>>>(Wo, woh, wol, DD, DD);

    // launch #6: fused QKV projections (profiled)
    mma_gemm<M_QKV><<<dim3(6, 32, 3), 256, GEMM_SMEM>>>(
        xhi, xlo, nullptr, nullptr, nullptr, nullptr, nullptr, nullptr, nullptr,
        qkv, NROW, DD, DD);

    // remaining weight prep
    transpose_split<<<dim3(96, 24), tb>>>(W1, w1h, w1l, DD, DFF);
    transpose_split<<<dim3(24, 96), tb>>>(W2, w2h, w2l, DFF, DD);

    // V -> V^T per head
    vtrans<<<dim3(32, 24), 256>>>(vhi, vthi);
    vtrans<<<dim3(32, 24), 256>>>(vlo, vtlo);

    // tensor-core flash attention (writes tiled athi/atlo)
    attn_tc<<<dim3(16, 12, 2), 128>>>(alibi, qhi, qlo, khi, klo,
                                      vthi, vtlo, athi, atlo);

    // output projection + residual, LN1
    mma_gemm<M_WO><<<dim3(6, 32), 256, GEMM_SMEM>>>(
        athi, atlo, woh, wol, bo, x, r1, nullptr, nullptr, dummy, NROW, DD, DD);
    ln_kernel<true><<<NROW, 256>>>(r1, g1w, be1, y, yhi, ylo);

    // FFN
    mma_gemm<M_FF1><<<dim3(24, 32), 256, GEMM_SMEM>>>(
        yhi, ylo, w1h, w1l, b1, nullptr, nullptr, h1hi, h1lo, dummy, NROW, DFF, DD);
    mma_gemm<M_FF2><<<dim3(6, 32), 256, GEMM_SMEM>>>(
        h1hi, h1lo, w2h, w2l, b2, y, z, nullptr, nullptr, dummy, NROW, DD, DFF);
    ln_kernel<false><<<NROW, 256>>>(z, g2w, be2, out, nullptr, nullptr);
}

// round 7
// speedup vs baseline: 3.8021x; 1.2231x over previous
#include <cuda_runtime.h>
#include <cuda_bf16.h>
#include <cuda_fp16.h>
#include <cstdint>
#include <cstddef>

// Problem constants
#define BB    2
#define SS    2048
#define DD    768
#define HH    12
#define HDD   64
#define DFF   3072
#define NROW  4096            // B*S

// GEMM tiling: 128x128 CTA tile, K chunks of 32, tiled global layout.
#define CH     32
#define PADC   40
#define TILE_HW 5120                       // halfwords per tile
#define TILE_B  10240                      // bytes per tile
#define STAGE_B (4 * TILE_B)               // bf16 gemm: 4 tiles/stage
#define GEMM_SMEM (2 * STAGE_B + 32)
#define FF_STAGE_B (3 * TILE_B)            // ff gemm: A + Bhi + Blo
#define FF_SMEM (3 * FF_STAGE_B + 64)      // 3 stages + mbarriers

#define TSZ(R, K) ((size_t)(R) * (K) / 32 * 40)

// ---------------------------------------------------------------------------
// Scratch (device globals)
// ---------------------------------------------------------------------------
__device__ float g_res1[NROW * DD];
__device__ float g_y[NROW * DD];
__device__ float g_z[NROW * DD];

// tiled bf16 hi/lo activations (QKV / WO path)
__device__ __nv_bfloat16 g_xhi[TSZ(NROW, DD)],  g_xlo[TSZ(NROW, DD)];
__device__ __nv_bfloat16 g_athi[TSZ(NROW, DD)], g_atlo[TSZ(NROW, DD)];

// tiled fp16 activations (FF path, single precision-split level)
__device__ __half g_yh[TSZ(NROW, DD)];
__device__ __half g_h1h[TSZ(NROW, DFF)];

// head-major q/k/v bf16 hi/lo (linear, for attention)
__device__ __nv_bfloat16 g_qhi[BB*HH*SS*HDD], g_qlo[BB*HH*SS*HDD];
__device__ __nv_bfloat16 g_khi[BB*HH*SS*HDD], g_klo[BB*HH*SS*HDD];
__device__ __nv_bfloat16 g_vhi[BB*HH*SS*HDD], g_vlo[BB*HH*SS*HDD];
__device__ __nv_bfloat16 g_vthi[BB*HH*SS*HDD], g_vtlo[BB*HH*SS*HDD];

// tiled transposed weights [N, K]
__device__ __nv_bfloat16 g_wqThi[TSZ(DD, DD)],  g_wqTlo[TSZ(DD, DD)];
__device__ __nv_bfloat16 g_wkThi[TSZ(DD, DD)],  g_wkTlo[TSZ(DD, DD)];
__device__ __nv_bfloat16 g_wvThi[TSZ(DD, DD)],  g_wvTlo[TSZ(DD, DD)];
__device__ __nv_bfloat16 g_woThi[TSZ(DD, DD)],  g_woTlo[TSZ(DD, DD)];
__device__ __half g_w1Thi[TSZ(DFF, DD)], g_w1Tlo[TSZ(DFF, DD)];
__device__ __half g_w2Thi[TSZ(DD, DFF)], g_w2Tlo[TSZ(DD, DFF)];

// ---------------------------------------------------------------------------
// helpers
// ---------------------------------------------------------------------------
__device__ __forceinline__ uint32_t smem_u32(const void* p) {
    uint32_t a;
    asm("{ .reg .u64 t; cvta.to.shared.u64 t, %1; cvt.u32.u64 %0, t; }"
        : "=r"(a) : "l"(p));
    return a;
}
__device__ __forceinline__ void mma16816(float* d, const uint32_t* a,
                                         uint32_t b0, uint32_t b1) {
    asm volatile(
        "mma.sync.aligned.m16n8k16.row.col.f32.bf16.bf16.f32 "
        "{%0,%1,%2,%3}, {%4,%5,%6,%7}, {%8,%9}, {%0,%1,%2,%3};"
        : "+f"(d[0]), "+f"(d[1]), "+f"(d[2]), "+f"(d[3])
        : "r"(a[0]), "r"(a[1]), "r"(a[2]), "r"(a[3]), "r"(b0), "r"(b1));
}
__device__ __forceinline__ void mma16816h(float* d, const uint32_t* a,
                                          uint32_t b0, uint32_t b1) {
    asm volatile(
        "mma.sync.aligned.m16n8k16.row.col.f32.f16.f16.f32 "
        "{%0,%1,%2,%3}, {%4,%5,%6,%7}, {%8,%9}, {%0,%1,%2,%3};"
        : "+f"(d[0]), "+f"(d[1]), "+f"(d[2]), "+f"(d[3])
        : "r"(a[0]), "r"(a[1]), "r"(a[2]), "r"(a[3]), "r"(b0), "r"(b1));
}
__device__ __forceinline__ uint32_t pack_bf16(float lo, float hi) {
    uint32_t r;
    asm("cvt.rn.bf16x2.f32 %0, %1, %2;" : "=r"(r) : "f"(hi), "f"(lo));
    return r;
}
__device__ __forceinline__ uint32_t pack_f16(float lo, float hi) {
    uint32_t r;
    asm("cvt.rn.f16x2.f32 %0, %1, %2;" : "=r"(r) : "f"(hi), "f"(lo));
    return r;
}
__device__ __forceinline__ void ldmx4(uint32_t* r, uint32_t addr) {
    asm volatile("ldmatrix.sync.aligned.m8n8.x4.shared.b16 {%0,%1,%2,%3}, [%4];"
                 : "=r"(r[0]), "=r"(r[1]), "=r"(r[2]), "=r"(r[3]) : "r"(addr));
}
__device__ __forceinline__ void mbar_init(uint32_t mbar, uint32_t cnt) {
    asm volatile("mbarrier.init.shared.b64 [%0], %1;" :: "r"(mbar), "r"(cnt) : "memory");
}
__device__ __forceinline__ void mbar_wait(uint32_t mbar, uint32_t parity) {
    asm volatile(
        "{\n\t.reg .pred P;\n\t"
        "WL_%=:\n\t"
        "mbarrier.try_wait.parity.acquire.cta.shared::cta.b64 P, [%0], %1, 0x989680;\n\t"
        "@P bra.uni WD_%=;\n\t"
        "bra.uni WL_%=;\n\t"
        "WD_%=:\n\t}"
        :: "r"(mbar), "r"(parity) : "memory");
}
__device__ __forceinline__ void mbar_expect_tx(uint32_t mbar, uint32_t bytes) {
    asm volatile("mbarrier.arrive.expect_tx.shared.b64 _, [%0], %1;"
                 :: "r"(mbar), "r"(bytes) : "memory");
}
__device__ __forceinline__ void bulkcp(uint32_t dst, const void* src,
                                       uint32_t bytes, uint32_t mbar) {
    asm volatile(
        "cp.async.bulk.shared::cta.global.mbarrier::complete_tx::bytes "
        "[%0], [%1], %2, [%3];"
        :: "r"(dst), "l"(src), "r"(bytes), "r"(mbar) : "memory");
}
__device__ __forceinline__ size_t toff(int row, int col, int kcn) {
    return (size_t)((row >> 7) * kcn + (col >> 5)) * TILE_HW +
           (row & 127) * PADC + (col & 31);
}

// ---------------------------------------------------------------------------
// fp32 [4096,768] -> tiled bf16 hi/lo
// ---------------------------------------------------------------------------
__global__ void __launch_bounds__(256) convert_split(
    const float* __restrict__ in, __nv_bfloat16* __restrict__ hi,
    __nv_bfloat16* __restrict__ lo)
{
    const int i = blockIdx.x * 256 + threadIdx.x;
    const int e = 4 * i;
    const int row = e / DD, col = e - row * DD;
    float4 v = ((const float4*)in)[i];
    float f[4] = {v.x, v.y, v.z, v.w};
    __nv_bfloat16 h[4], l[4];
#pragma unroll
    for (int j = 0; j < 4; j++) {
        h[j] = __float2bfloat16(f[j]);
        l[j] = __float2bfloat16(f[j] - __bfloat162float(h[j]));
    }
    const size_t o = toff(row, col, DD / 32);
    *(uint2*)(hi + o) = *(uint2*)h;
    *(uint2*)(lo + o) = *(uint2*)l;
}

// ---------------------------------------------------------------------------
// W[K,N] fp32 -> tiled Wt[N,K] bf16 hi/lo
// ---------------------------------------------------------------------------
__global__ void __launch_bounds__(256) transpose_split(
    const float* __restrict__ W, __nv_bfloat16* __restrict__ Thi,
    __nv_bfloat16* __restrict__ Tlo, int K, int N)
{
    __shared__ float tile[32][33];
    const int k0 = blockIdx.y * 32, n0 = blockIdx.x * 32;
    const int tx = threadIdx.x, ty = threadIdx.y;   // (32, 8)
#pragma unroll
    for (int i = 0; i < 4; i++)
        tile[ty + 8 * i][tx] = W[(size_t)(k0 + ty + 8 * i) * N + n0 + tx];
    __syncthreads();
    const int kcn = K >> 5;
#pragma unroll
    for (int i = 0; i < 4; i++) {
        const float vv = tile[tx][ty + 8 * i];
        const __nv_bfloat16 h = __float2bfloat16(vv);
        const size_t o = toff(n0 + ty + 8 * i, k0 + tx, kcn);
        Thi[o] = h;
        Tlo[o] = __float2bfloat16(vv - __bfloat162float(h));
    }
}

// W[K,N] fp32 -> tiled Wt[N,K] fp16 hi/lo
__global__ void __launch_bounds__(256) transpose_split_h(
    const float* __restrict__ W, __half* __restrict__ Thi,
    __half* __restrict__ Tlo, int K, int N)
{
    __shared__ float tile[32][33];
    const int k0 = blockIdx.y * 32, n0 = blockIdx.x * 32;
    const int tx = threadIdx.x, ty = threadIdx.y;
#pragma unroll
    for (int i = 0; i < 4; i++)
        tile[ty + 8 * i][tx] = W[(size_t)(k0 + ty + 8 * i) * N + n0 + tx];
    __syncthreads();
    const int kcn = K >> 5;
#pragma unroll
    for (int i = 0; i < 4; i++) {
        const float vv = tile[tx][ty + 8 * i];
        const __half h = __float2half_rn(vv);
        const size_t o = toff(n0 + ty + 8 * i, k0 + tx, kcn);
        Thi[o] = h;
        Tlo[o] = __float2half_rn(vv - __half2float(h));
    }
}

// ---------------------------------------------------------------------------
// per-head V transpose: [s, hd] -> [hd, s] (bf16, linear)
// ---------------------------------------------------------------------------
__global__ void __launch_bounds__(256) vtrans(
    const __nv_bfloat16* __restrict__ in, __nv_bfloat16* __restrict__ out)
{
    __shared__ __nv_bfloat16 sm[64][72];
    const int s0 = blockIdx.x * 64;
    const size_t bh = blockIdx.y;
    const __nv_bfloat16* src = in + bh * SS * HDD;
    __nv_bfloat16* dst = out + bh * (size_t)HDD * SS;
    const int t = threadIdx.x;
    const int r = t >> 2, cq = (t & 3) * 16;
    *(uint4*)(&sm[r][cq])     = *(const uint4*)(src + (size_t)(s0 + r) * HDD + cq);
    *(uint4*)(&sm[r][cq + 8]) = *(const uint4*)(src + (size_t)(s0 + r) * HDD + cq + 8);
    __syncthreads();
    uint32_t w[8];
#pragma unroll
    for (int j = 0; j < 8; j++) {
        const __nv_bfloat16 a = sm[cq + 2 * j][r], b = sm[cq + 2 * j + 1][r];
        w[j] = ((uint32_t)(*(const uint16_t*)&b) << 16) | *(const uint16_t*)&a;
    }
#pragma unroll
    for (int j = 0; j < 4; j++)
        *(uint2*)(dst + (size_t)r * SS + s0 + cq + 4 * j) =
            make_uint2(w[2 * j], w[2 * j + 1]);
}

// ---------------------------------------------------------------------------
// bf16 3-pass GEMM (QKV / WO), bulk-DMA double buffer (R6 proven)
// ---------------------------------------------------------------------------
#define M_QKV 0
#define M_WO  1

struct Ptr3 {
    const __nv_bfloat16 *bh, *bl;
    const float* bias;
    __nv_bfloat16 *ch, *cl;
};
struct Qkv3 { Ptr3 p[3]; };

template <int MODE>
__global__ void __launch_bounds__(256) mma_gemm(
    const __nv_bfloat16* __restrict__ Ahi, const __nv_bfloat16* __restrict__ Alo,
    const __nv_bfloat16* __restrict__ Bhi_, const __nv_bfloat16* __restrict__ Blo_,
    const float* __restrict__ bias_, const float* __restrict__ res,
    float* __restrict__ Cf, Qkv3 qkv, int M, int N, int K)
{
    extern __shared__ char smem[];
    const uint32_t sb = smem_u32(smem);
    const uint32_t mbb = sb + 2 * STAGE_B;

    const int t    = threadIdx.x;
    const int lane = t & 31, wid = t >> 5;
    const int wm   = (wid & 3) * 32;
    const int wn   = (wid >> 2) * 64;
    const int bm   = blockIdx.y * 128, bn = blockIdx.x * 128;
    const int g    = lane >> 2, tig = lane & 3;

    const __nv_bfloat16* Bhi;
    const __nv_bfloat16* Blo;
    const float* bias;
    __nv_bfloat16 *Chi = nullptr, *Clo = nullptr;
    if (MODE == M_QKV) {
        const Ptr3& p = qkv.p[blockIdx.z];
        Bhi = p.bh; Blo = p.bl; bias = p.bias; Chi = p.ch; Clo = p.cl;
    } else {
        Bhi = Bhi_; Blo = Blo_; bias = bias_;
    }

    if (t == 0) { mbar_init(mbb, 1); mbar_init(mbb + 8, 1); }
    __syncthreads();

    float acc[2][8][4];
#pragma unroll
    for (int i = 0; i < 2; i++)
#pragma unroll
        for (int j = 0; j < 8; j++)
#pragma unroll
            for (int c = 0; c < 4; c++) acc[i][j][c] = 0.f;

    const int KCN = K >> 5;
    const int arb = bm >> 7, brb = bn >> 7;

    auto issue = [&](int c, int stage) {
        if (t == 0) {
            const uint32_t mbar = mbb + stage * 8;
            mbar_expect_tx(mbar, STAGE_B);
            const uint32_t d = sb + stage * STAGE_B;
            bulkcp(d,              Ahi + ((size_t)arb * KCN + c) * TILE_HW, TILE_B, mbar);
            bulkcp(d + TILE_B,     Alo + ((size_t)arb * KCN + c) * TILE_HW, TILE_B, mbar);
            bulkcp(d + 2 * TILE_B, Bhi + ((size_t)brb * KCN + c) * TILE_HW, TILE_B, mbar);
            bulkcp(d + 3 * TILE_B, Blo + ((size_t)brb * KCN + c) * TILE_HW, TILE_B, mbar);
        }
    };

    uint32_t ph[2] = {0, 0};
    issue(0, 0);

    const uint32_t lrow = (uint32_t)(lane & 15);
    const uint32_t lcol = (uint32_t)((lane >> 4) * 8);

    for (int c = 0; c < KCN; c++) {
        if (c + 1 < KCN) issue(c + 1, (c + 1) & 1);
        const int st = c & 1;
        mbar_wait(mbb + st * 8, ph[st]);
        ph[st] ^= 1;

        const uint32_t sbase = sb + st * STAGE_B;
        const uint32_t sAhi = sbase;
        const uint32_t sAlo = sbase + TILE_B;
        const uint32_t sBhi = sbase + 2 * TILE_B;
        const uint32_t sBlo = sbase + 3 * TILE_B;

#pragma unroll
        for (int kk = 0; kk < CH; kk += 16) {
            uint32_t ah[2][4], al[2][4];
            ldmx4(ah[0], sAhi + ((wm + lrow) * PADC + kk + lcol) * 2);
            ldmx4(ah[1], sAhi + ((wm + 16 + lrow) * PADC + kk + lcol) * 2);
            ldmx4(al[0], sAlo + ((wm + lrow) * PADC + kk + lcol) * 2);
            ldmx4(al[1], sAlo + ((wm + 16 + lrow) * PADC + kk + lcol) * 2);
#pragma unroll
            for (int p = 0; p < 4; p++) {
                uint32_t bh[4], bl[4];
                ldmx4(bh, sBhi + ((wn + 16 * p + lrow) * PADC + kk + lcol) * 2);
                ldmx4(bl, sBlo + ((wn + 16 * p + lrow) * PADC + kk + lcol) * 2);
#pragma unroll
                for (int q = 0; q < 2; q++) {
                    const int nt = 2 * p + q;
                    const uint32_t bh0 = bh[q], bh1 = bh[q + 2];
                    const uint32_t bl0 = bl[q], bl1 = bl[q + 2];
                    mma16816(acc[0][nt], ah[0], bh0, bh1);
                    mma16816(acc[1][nt], ah[1], bh0, bh1);
                    mma16816(acc[0][nt], ah[0], bl0, bl1);
                    mma16816(acc[1][nt], ah[1], bl0, bl1);
                    mma16816(acc[0][nt], al[0], bh0, bh1);
                    mma16816(acc[1][nt], al[1], bh0, bh1);
                }
            }
        }
        __syncthreads();
    }

#pragma unroll
    for (int mt = 0; mt < 2; mt++) {
#pragma unroll
        for (int nt = 0; nt < 8; nt++) {
#pragma unroll
            for (int half = 0; half < 2; half++) {
                const int grow = bm + wm + mt * 16 + g + half * 8;
                const int gcol = bn + wn + nt * 8 + 2 * tig;
                float v0 = acc[mt][nt][half * 2 + 0] + bias[gcol];
                float v1 = acc[mt][nt][half * 2 + 1] + bias[gcol + 1];
                if (MODE == M_QKV) {
                    const int b_ = grow >> 11, s_ = grow & 2047;
                    const int h_ = gcol >> 6,  hd = gcol & 63;
                    const size_t oo =
                        (((size_t)(b_ * HH + h_) * SS) + s_) * HDD + hd;
                    const float h0 = __bfloat162float(__float2bfloat16(v0));
                    const float h1 = __bfloat162float(__float2bfloat16(v1));
                    *(uint32_t*)(Chi + oo) = pack_bf16(h0, h1);
                    *(uint32_t*)(Clo + oo) = pack_bf16(v0 - h0, v1 - h1);
                } else {
                    const size_t o = (size_t)grow * N + gcol;
                    v0 += res[o];
                    v1 += res[o + 1];
                    *(float2*)(Cf + o) = make_float2(v0, v1);
                }
            }
        }
    }
}

// ---------------------------------------------------------------------------
// fp16 2-pass FF GEMM: A single fp16, B fp16 hi/lo. 3-stage bulk-DMA pipeline.
// MODE 0 = FF1 (relu, fp16 tiled out), MODE 1 = FF2 (residual, fp32 out).
// ---------------------------------------------------------------------------
template <int MODE>
__global__ void __launch_bounds__(256) ff_gemm(
    const __half* __restrict__ A,
    const __half* __restrict__ Bhi, const __half* __restrict__ Blo,
    const float* __restrict__ bias, const float* __restrict__ res,
    float* __restrict__ Cf, __half* __restrict__ Ch, int M, int N, int K)
{
    extern __shared__ char smem[];
    const uint32_t sb = smem_u32(smem);
    const uint32_t mbb = sb + 3 * FF_STAGE_B;

    const int t    = threadIdx.x;
    const int lane = t & 31, wid = t >> 5;
    const int wm   = (wid & 3) * 32;
    const int wn   = (wid >> 2) * 64;
    const int bm   = blockIdx.y * 128, bn = blockIdx.x * 128;
    const int g    = lane >> 2, tig = lane & 3;

    if (t == 0) { mbar_init(mbb, 1); mbar_init(mbb + 8, 1); mbar_init(mbb + 16, 1); }
    __syncthreads();

    float acc[2][8][4];
#pragma unroll
    for (int i = 0; i < 2; i++)
#pragma unroll
        for (int j = 0; j < 8; j++)
#pragma unroll
            for (int c = 0; c < 4; c++) acc[i][j][c] = 0.f;

    const int KCN = K >> 5;
    const int arb = bm >> 7, brb = bn >> 7;

    auto issue = [&](int c, int stage) {
        if (t == 0) {
            const uint32_t mbar = mbb + stage * 8;
            mbar_expect_tx(mbar, FF_STAGE_B);
            const uint32_t d = sb + stage * FF_STAGE_B;
            bulkcp(d,              A   + ((size_t)arb * KCN + c) * TILE_HW, TILE_B, mbar);
            bulkcp(d + TILE_B,     Bhi + ((size_t)brb * KCN + c) * TILE_HW, TILE_B, mbar);
            bulkcp(d + 2 * TILE_B, Blo + ((size_t)brb * KCN + c) * TILE_HW, TILE_B, mbar);
        }
    };

    uint32_t ph[3] = {0, 0, 0};
    issue(0, 0);
    if (KCN > 1) issue(1, 1);

    const uint32_t lrow = (uint32_t)(lane & 15);
    const uint32_t lcol = (uint32_t)((lane >> 4) * 8);

    for (int c = 0; c < KCN; c++) {
        if (c + 2 < KCN) issue(c + 2, (c + 2) % 3);
        const int st = c % 3;
        mbar_wait(mbb + st * 8, ph[st]);
        ph[st] ^= 1;

        const uint32_t sbase = sb + st * FF_STAGE_B;
        const uint32_t sA   = sbase;
        const uint32_t sBhi = sbase + TILE_B;
        const uint32_t sBlo = sbase + 2 * TILE_B;

#pragma unroll
        for (int kk = 0; kk < CH; kk += 16) {
            uint32_t a[2][4];
            ldmx4(a[0], sA + ((wm + lrow) * PADC + kk + lcol) * 2);
            ldmx4(a[1], sA + ((wm + 16 + lrow) * PADC + kk + lcol) * 2);
#pragma unroll
            for (int p = 0; p < 4; p++) {
                uint32_t bh[4], bl[4];
                ldmx4(bh, sBhi + ((wn + 16 * p + lrow) * PADC + kk + lcol) * 2);
                ldmx4(bl, sBlo + ((wn + 16 * p + lrow) * PADC + kk + lcol) * 2);
#pragma unroll
                for (int q = 0; q < 2; q++) {
                    const int nt = 2 * p + q;
                    const uint32_t bh0 = bh[q], bh1 = bh[q + 2];
                    const uint32_t bl0 = bl[q], bl1 = bl[q + 2];
                    mma16816h(acc[0][nt], a[0], bh0, bh1);
                    mma16816h(acc[1][nt], a[1], bh0, bh1);
                    mma16816h(acc[0][nt], a[0], bl0, bl1);
                    mma16816h(acc[1][nt], a[1], bl0, bl1);
                }
            }
        }
        __syncthreads();
    }

    const int okcn = N >> 5;
#pragma unroll
    for (int mt = 0; mt < 2; mt++) {
#pragma unroll
        for (int nt = 0; nt < 8; nt++) {
#pragma unroll
            for (int half = 0; half < 2; half++) {
                const int grow = bm + wm + mt * 16 + g + half * 8;
                const int gcol = bn + wn + nt * 8 + 2 * tig;
                float v0 = acc[mt][nt][half * 2 + 0] + bias[gcol];
                float v1 = acc[mt][nt][half * 2 + 1] + bias[gcol + 1];
                if (MODE == 0) {
                    v0 = fmaxf(v0, 0.f);
                    v1 = fmaxf(v1, 0.f);
                    *(uint32_t*)(Ch + toff(grow, gcol, okcn)) = pack_f16(v0, v1);
                } else {
                    const size_t o = (size_t)grow * N + gcol;
                    v0 += res[o];
                    v1 += res[o + 1];
                    *(float2*)(Cf + o) = make_float2(v0, v1);
                }
            }
        }
    }
}

// ---------------------------------------------------------------------------
// Tensor-core flash attention (unchanged; writes tiled bf16 hi/lo)
// ---------------------------------------------------------------------------
__global__ void __launch_bounds__(128) attn_tc(
    const float* __restrict__ alibi,
    const __nv_bfloat16* __restrict__ Qhi, const __nv_bfloat16* __restrict__ Qlo,
    const __nv_bfloat16* __restrict__ Khi, const __nv_bfloat16* __restrict__ Klo,
    const __nv_bfloat16* __restrict__ Vthi, const __nv_bfloat16* __restrict__ Vtlo,
    __nv_bfloat16* __restrict__ Ohi, __nv_bfloat16* __restrict__ Olo)
{
    __shared__ __nv_bfloat16 skh[64 * 72], skl[64 * 72];
    __shared__ __nv_bfloat16 svh[64 * 72], svl[64 * 72];

    const int t = threadIdx.x, lane = t & 31, wid = t >> 5;
    const int g = lane >> 2, tig = lane & 3;
    const int qt = (int)(gridDim.x - 1) - (int)blockIdx.x;
    const int h = blockIdx.y, b = blockIdx.z;
    const int q0 = qt * 128, wm = wid * 32;
    const size_t bh = (size_t)(b * HH + h);

    const __nv_bfloat16* qh = Qhi + (bh * SS + q0) * HDD;
    const __nv_bfloat16* ql = Qlo + (bh * SS + q0) * HDD;
    const __nv_bfloat16* kh = Khi + bh * SS * HDD;
    const __nv_bfloat16* kl = Klo + bh * SS * HDD;
    const __nv_bfloat16* vh = Vthi + bh * (size_t)HDD * SS;
    const __nv_bfloat16* vl = Vtlo + bh * (size_t)HDD * SS;
    const float* ab = alibi + (size_t)h * SS * SS;

    float o[2][8][4];
#pragma unroll
    for (int i = 0; i < 2; i++)
#pragma unroll
        for (int j = 0; j < 8; j++)
#pragma unroll
            for (int c = 0; c < 4; c++) o[i][j][c] = 0.f;
    float mrow[2][2] = {{-1e30f, -1e30f}, {-1e30f, -1e30f}};
    float lrow[2][2] = {{0.f, 0.f}, {0.f, 0.f}};

    const int nkt = 2 * qt + 2;
    for (int kt = 0; kt < nkt; kt++) {
        const int k0 = kt * 64;
        __syncthreads();
#pragma unroll
        for (int i = 0; i < 4; i++) {
            const int f = t + 128 * i;
            const int r = f >> 3, c8 = (f & 7) * 8;
            *(uint4*)(skh + r * 72 + c8) =
                *(const uint4*)(kh + (size_t)(k0 + r) * HDD + c8);
            *(uint4*)(skl + r * 72 + c8) =
                *(const uint4*)(kl + (size_t)(k0 + r) * HDD + c8);
            *(uint4*)(svh + r * 72 + c8) =
                *(const uint4*)(vh + (size_t)r * SS + k0 + c8);
            *(uint4*)(svl + r * 72 + c8) =
                *(const uint4*)(vl + (size_t)r * SS + k0 + c8);
        }
        __syncthreads();

        float sacc[2][8][4];
#pragma unroll
        for (int i = 0; i < 2; i++)
#pragma unroll
            for (int j = 0; j < 8; j++)
#pragma unroll
                for (int c = 0; c < 4; c++) sacc[i][j][c] = 0.f;

#pragma unroll
        for (int kc = 0; kc < 4; kc++) {
            uint32_t a[2][4];
#pragma unroll
            for (int mt = 0; mt < 2; mt++) {
                const int row = wm + mt * 16 + g;
                a[mt][0] = *(const uint32_t*)(qh + (size_t)row * HDD + kc * 16 + 2 * tig);
                a[mt][1] = *(const uint32_t*)(qh + (size_t)(row + 8) * HDD + kc * 16 + 2 * tig);
                a[mt][2] = *(const uint32_t*)(qh + (size_t)row * HDD + kc * 16 + 8 + 2 * tig);
                a[mt][3] = *(const uint32_t*)(qh + (size_t)(row + 8) * HDD + kc * 16 + 8 + 2 * tig);
            }
#pragma unroll
            for (int nt = 0; nt < 8; nt++) {
                const __nv_bfloat16* kr = skh + (8 * nt + g) * 72 + kc * 16;
                const uint32_t b0 = *(const uint32_t*)(kr + 2 * tig);
                const uint32_t b1 = *(const uint32_t*)(kr + 8 + 2 * tig);
                mma16816(sacc[0][nt], a[0], b0, b1);
                mma16816(sacc[1][nt], a[1], b0, b1);
            }
#pragma unroll
            for (int nt = 0; nt < 8; nt++) {
                const __nv_bfloat16* kr = skl + (8 * nt + g) * 72 + kc * 16;
                const uint32_t b0 = *(const uint32_t*)(kr + 2 * tig);
                const uint32_t b1 = *(const uint32_t*)(kr + 8 + 2 * tig);
                mma16816(sacc[0][nt], a[0], b0, b1);
                mma16816(sacc[1][nt], a[1], b0, b1);
            }
#pragma unroll
            for (int mt = 0; mt < 2; mt++) {
                const int row = wm + mt * 16 + g;
                a[mt][0] = *(const uint32_t*)(ql + (size_t)row * HDD + kc * 16 + 2 * tig);
                a[mt][1] = *(const uint32_t*)(ql + (size_t)(row + 8) * HDD + kc * 16 + 2 * tig);
                a[mt][2] = *(const uint32_t*)(ql + (size_t)row * HDD + kc * 16 + 8 + 2 * tig);
                a[mt][3] = *(const uint32_t*)(ql + (size_t)(row + 8) * HDD + kc * 16 + 8 + 2 * tig);
            }
#pragma unroll
            for (int nt = 0; nt < 8; nt++) {
                const __nv_bfloat16* kr = skh + (8 * nt + g) * 72 + kc * 16;
                const uint32_t b0 = *(const uint32_t*)(kr + 2 * tig);
                const uint32_t b1 = *(const uint32_t*)(kr + 8 + 2 * tig);
                mma16816(sacc[0][nt], a[0], b0, b1);
                mma16816(sacc[1][nt], a[1], b0, b1);
            }
        }

#pragma unroll
        for (int mt = 0; mt < 2; mt++) {
#pragma unroll
            for (int hf = 0; hf < 2; hf++) {
                const int rowg = q0 + wm + 16 * mt + g + 8 * hf;
                const float* arow = ab + (size_t)rowg * SS + k0;
                float mx = -1e30f;
#pragma unroll
                for (int nt = 0; nt < 8; nt++) {
                    const int col = k0 + 8 * nt + 2 * tig;
                    const float2 al2 = *(const float2*)(arow + 8 * nt + 2 * tig);
                    float s0 = fmaf(sacc[mt][nt][2 * hf + 0], 0.125f, al2.x);
                    float s1 = fmaf(sacc[mt][nt][2 * hf + 1], 0.125f, al2.y);
                    if (col > rowg)     s0 = -1e30f;
                    if (col + 1 > rowg) s1 = -1e30f;
                    sacc[mt][nt][2 * hf + 0] = s0;
                    sacc[mt][nt][2 * hf + 1] = s1;
                    mx = fmaxf(mx, fmaxf(s0, s1));
                }
                mx = fmaxf(mx, __shfl_xor_sync(0xffffffffu, mx, 1));
                mx = fmaxf(mx, __shfl_xor_sync(0xffffffffu, mx, 2));
                const float mn = fmaxf(mrow[mt][hf], mx);
                const float corr = __expf(mrow[mt][hf] - mn);
                mrow[mt][hf] = mn;
                lrow[mt][hf] *= corr;
#pragma unroll
                for (int nt = 0; nt < 8; nt++) {
                    o[mt][nt][2 * hf + 0] *= corr;
                    o[mt][nt][2 * hf + 1] *= corr;
                }
                float ls = 0.f;
#pragma unroll
                for (int nt = 0; nt < 8; nt++) {
                    const float p0 = __expf(sacc[mt][nt][2 * hf + 0] - mn);
                    const float p1 = __expf(sacc[mt][nt][2 * hf + 1] - mn);
                    sacc[mt][nt][2 * hf + 0] = p0;
                    sacc[mt][nt][2 * hf + 1] = p1;
                    ls += p0 + p1;
                }
                ls += __shfl_xor_sync(0xffffffffu, ls, 1);
                ls += __shfl_xor_sync(0xffffffffu, ls, 2);
                lrow[mt][hf] += ls;
            }
        }

#pragma unroll
        for (int kc = 0; kc < 4; kc++) {
            uint32_t aph[2][4], apl[2][4];
#pragma unroll
            for (int mt = 0; mt < 2; mt++) {
#pragma unroll
                for (int q2 = 0; q2 < 2; q2++) {
                    const float p0 = sacc[mt][2 * kc + q2][0];
                    const float p1 = sacc[mt][2 * kc + q2][1];
                    const float p2 = sacc[mt][2 * kc + q2][2];
                    const float p3 = sacc[mt][2 * kc + q2][3];
                    const float h0 = __bfloat162float(__float2bfloat16(p0));
                    const float h1 = __bfloat162float(__float2bfloat16(p1));
                    const float h2 = __bfloat162float(__float2bfloat16(p2));
                    const float h3 = __bfloat162float(__float2bfloat16(p3));
                    aph[mt][2 * q2 + 0] = pack_bf16(h0, h1);
                    aph[mt][2 * q2 + 1] = pack_bf16(h2, h3);
                    apl[mt][2 * q2 + 0] = pack_bf16(p0 - h0, p1 - h1);
                    apl[mt][2 * q2 + 1] = pack_bf16(p2 - h2, p3 - h3);
                }
            }
#pragma unroll
            for (int nt = 0; nt < 8; nt++) {
                const __nv_bfloat16* vrh = svh + (8 * nt + g) * 72 + kc * 16;
                const __nv_bfloat16* vrl = svl + (8 * nt + g) * 72 + kc * 16;
                const uint32_t bh0 = *(const uint32_t*)(vrh + 2 * tig);
                const uint32_t bh1 = *(const uint32_t*)(vrh + 8 + 2 * tig);
                const uint32_t bl0 = *(const uint32_t*)(vrl + 2 * tig);
                const uint32_t bl1 = *(const uint32_t*)(vrl + 8 + 2 * tig);
                mma16816(o[0][nt], aph[0], bh0, bh1);
                mma16816(o[1][nt], aph[1], bh0, bh1);
                mma16816(o[0][nt], apl[0], bh0, bh1);
                mma16816(o[1][nt], apl[1], bh0, bh1);
                mma16816(o[0][nt], aph[0], bl0, bl1);
                mma16816(o[1][nt], aph[1], bl0, bl1);
            }
        }
    }

#pragma unroll
    for (int mt = 0; mt < 2; mt++) {
#pragma unroll
        for (int hf = 0; hf < 2; hf++) {
            const float inv = 1.f / lrow[mt][hf];
            const int srow = q0 + wm + 16 * mt + g + 8 * hf;
            const int rowg = b * SS + srow;
#pragma unroll
            for (int nt = 0; nt < 8; nt++) {
                const int col = h * HDD + 8 * nt + 2 * tig;
                const float v0 = o[mt][nt][2 * hf + 0] * inv;
                const float v1 = o[mt][nt][2 * hf + 1] * inv;
                const float h0 = __bfloat162float(__float2bfloat16(v0));
                const float h1 = __bfloat162float(__float2bfloat16(v1));
                const size_t oo = toff(rowg, col, DD / 32);
                *(uint32_t*)(Ohi + oo) = pack_bf16(h0, h1);
                *(uint32_t*)(Olo + oo) = pack_bf16(v0 - h0, v1 - h1);
            }
        }
    }
}

// ---------------------------------------------------------------------------
// LayerNorm; SPLIT emits tiled fp16 single
// ---------------------------------------------------------------------------
template <bool SPLIT>
__global__ void __launch_bounds__(256) ln_kernel(
    const float* __restrict__ in, const float* __restrict__ gw,
    const float* __restrict__ bw, float* __restrict__ out,
    __half* __restrict__ oh)
{
    const int row = blockIdx.x;
    const int t   = threadIdx.x;
    const float* p = in + (size_t)row * DD;

    const float v0 = p[t], v1 = p[t + 256], v2 = p[t + 512];
    float s  = v0 + v1 + v2;
    float sq = fmaf(v0, v0, fmaf(v1, v1, v2 * v2));

#pragma unroll
    for (int off = 16; off; off >>= 1) {
        s  += __shfl_down_sync(0xffffffffu, s, off);
        sq += __shfl_down_sync(0xffffffffu, sq, off);
    }
    __shared__ float rs[8], rq[8];
    __shared__ float mean_s, inv_s;
    const int w = t >> 5, lane = t & 31;
    if (lane == 0) { rs[w] = s; rq[w] = sq; }
    __syncthreads();
    if (t == 0) {
        float S = 0.f, Q = 0.f;
#pragma unroll
        for (int i = 0; i < 8; i++) { S += rs[i]; Q += rq[i]; }
        const float mean = S * (1.f / 768.f);
        const float var  = Q * (1.f / 768.f) - mean * mean;
        mean_s = mean;
        inv_s  = rsqrtf(var + 1e-5f);
    }
    __syncthreads();
    const float mean = mean_s, inv = inv_s;
    float* po = out + (size_t)row * DD;
#pragma unroll
    for (int j = 0; j < 3; j++) {
        const int  c = t + 256 * j;
        const float vj = (j == 0) ? v0 : (j == 1) ? v1 : v2;
        const float r = fmaf((vj - mean) * inv, gw[c], bw[c]);
        po[c] = r;
        if (SPLIT) {
            oh[toff(row, c, DD / 32)] = __float2half_rn(r);
        }
    }
}

// ---------------------------------------------------------------------------
// Launcher
// ---------------------------------------------------------------------------
extern "C" void kernel_launch(void* const* d_in, const int* in_sizes, int n_in,
                              void* d_out, int out_size)
{
    (void)in_sizes; (void)n_in; (void)out_size;
    const float* x     = (const float*)d_in[0];
    const float* alibi = (const float*)d_in[1];
    const float* Wq = (const float*)d_in[2];  const float* bq = (const float*)d_in[3];
    const float* Wk = (const float*)d_in[4];  const float* bk = (const float*)d_in[5];
    const float* Wv = (const float*)d_in[6];  const float* bv = (const float*)d_in[7];
    const float* Wo = (const float*)d_in[8];  const float* bo = (const float*)d_in[9];
    const float* W1 = (const float*)d_in[10]; const float* b1 = (const float*)d_in[11];
    const float* W2 = (const float*)d_in[12]; const float* b2 = (const float*)d_in[13];
    const float* g1w = (const float*)d_in[14]; const float* be1 = (const float*)d_in[15];
    const float* g2w = (const float*)d_in[16]; const float* be2 = (const float*)d_in[17];
    float* out = (float*)d_out;

    float *r1, *y, *z;
    cudaGetSymbolAddress((void**)&r1, g_res1);
    cudaGetSymbolAddress((void**)&y,  g_y);
    cudaGetSymbolAddress((void**)&z,  g_z);

    __nv_bfloat16 *xhi, *xlo, *athi, *atlo;
    __half *yh, *h1h, *w1hh, *w1hl, *w2hh, *w2hl;
    __nv_bfloat16 *qhi, *qlo, *khi, *klo, *vhi, *vlo, *vthi, *vtlo;
    __nv_bfloat16 *wqh, *wql, *wkh, *wkl, *wvh, *wvl, *woh, *wol;
    cudaGetSymbolAddress((void**)&xhi,  g_xhi);  cudaGetSymbolAddress((void**)&xlo,  g_xlo);
    cudaGetSymbolAddress((void**)&athi, g_athi); cudaGetSymbolAddress((void**)&atlo, g_atlo);
    cudaGetSymbolAddress((void**)&yh,   g_yh);   cudaGetSymbolAddress((void**)&h1h,  g_h1h);
    cudaGetSymbolAddress((void**)&qhi,  g_qhi);  cudaGetSymbolAddress((void**)&qlo,  g_qlo);
    cudaGetSymbolAddress((void**)&khi,  g_khi);  cudaGetSymbolAddress((void**)&klo,  g_klo);
    cudaGetSymbolAddress((void**)&vhi,  g_vhi);  cudaGetSymbolAddress((void**)&vlo,  g_vlo);
    cudaGetSymbolAddress((void**)&vthi, g_vthi); cudaGetSymbolAddress((void**)&vtlo, g_vtlo);
    cudaGetSymbolAddress((void**)&wqh, g_wqThi); cudaGetSymbolAddress((void**)&wql, g_wqTlo);
    cudaGetSymbolAddress((void**)&wkh, g_wkThi); cudaGetSymbolAddress((void**)&wkl, g_wkTlo);
    cudaGetSymbolAddress((void**)&wvh, g_wvThi); cudaGetSymbolAddress((void**)&wvl, g_wvTlo);
    cudaGetSymbolAddress((void**)&woh, g_woThi); cudaGetSymbolAddress((void**)&wol, g_woTlo);
    cudaGetSymbolAddress((void**)&w1hh, g_w1Thi); cudaGetSymbolAddress((void**)&w1hl, g_w1Tlo);
    cudaGetSymbolAddress((void**)&w2hh, g_w2Thi); cudaGetSymbolAddress((void**)&w2hl, g_w2Tlo);

    cudaFuncSetAttribute(mma_gemm<M_QKV>, cudaFuncAttributeMaxDynamicSharedMemorySize, GEMM_SMEM);
    cudaFuncSetAttribute(mma_gemm<M_WO>,  cudaFuncAttributeMaxDynamicSharedMemorySize, GEMM_SMEM);
    cudaFuncSetAttribute(ff_gemm<0>, cudaFuncAttributeMaxDynamicSharedMemorySize, FF_SMEM);
    cudaFuncSetAttribute(ff_gemm<1>, cudaFuncAttributeMaxDynamicSharedMemorySize, FF_SMEM);

    const dim3 tb(32, 8);

    Qkv3 qkv;
    qkv.p[0] = {wqh, wql, bq, qhi, qlo};
    qkv.p[1] = {wkh, wkl, bk, khi, klo};
    qkv.p[2] = {wvh, wvl, bv, vhi, vlo};
    Qkv3 dummy = qkv;

    // prep for QKV
    convert_split<<<3072, 256>>>(x, xhi, xlo);
    transpose_split<<<dim3(24, 24), tb>>>(Wq, wqh, wql, DD, DD);
    transpose_split<<<dim3(24, 24), tb>>>(Wk, wkh, wkl, DD, DD);
    transpose_split<<<dim3(24, 24), tb>>>(Wv, wvh, wvl, DD, DD);
    transpose_split<<<dim3(24, 24), tb>>>(Wo, woh, wol, DD, DD);

    // fused QKV projections
    mma_gemm<M_QKV><<<dim3(6, 32, 3), 256, GEMM_SMEM>>>(
        xhi, xlo, nullptr, nullptr, nullptr, nullptr, nullptr, qkv, NROW, DD, DD);

    // remaining weight prep (fp16 for FF path)
    transpose_split_h<<<dim3(96, 24), tb>>>(W1, w1hh, w1hl, DD, DFF);
    transpose_split_h<<<dim3(24, 96), tb>>>(W2, w2hh, w2hl, DFF, DD);

    // V -> V^T per head
    vtrans<<<dim3(32, 24), 256>>>(vhi, vthi);
    vtrans<<<dim3(32, 24), 256>>>(vlo, vtlo);

    // tensor-core flash attention
    attn_tc<<<dim3(16, 12, 2), 128>>>(alibi, qhi, qlo, khi, klo,
                                      vthi, vtlo, athi, atlo);

    // output projection + residual, LN1 (emits fp16 y for FF path)
    mma_gemm<M_WO><<<dim3(6, 32), 256, GEMM_SMEM>>>(
        athi, atlo, woh, wol, bo, x, r1, dummy, NROW, DD, DD);
    ln_kernel<true><<<NROW, 256>>>(r1, g1w, be1, y, yh);

    // FFN (fp16 2-pass)
    ff_gemm<0><<<dim3(24, 32), 256, FF_SMEM>>>(
        yh, w1hh, w1hl, b1, nullptr, nullptr, h1h, NROW, DFF, DD);
    ff_gemm<1><<<dim3(6, 32), 256, FF_SMEM>>>(
        h1h, w2hh, w2hl, b2, y, z, nullptr, NROW, DD, DFF);
    ln_kernel<false><<<NROW, 256>>>(z, g2w, be2, out, nullptr);
}

// round 9
// speedup vs baseline: 5.1434x; 1.3528x over previous
#include <cuda_runtime.h>
#include <cuda_fp16.h>
#include <cstdint>
#include <cstddef>

// Problem constants
#define BB    2
#define SS    2048
#define DD    768
#define HH    12
#define HDD   64
#define DFF   3072
#define NROW  4096            // B*S

// GEMM tiling: 128x128 CTA tile, K chunks of 32, tiled global layout.
#define CH     32
#define PADC   40
#define TILE_HW 5120
#define TILE_B  10240
#define G_STAGE_B (3 * TILE_B)             // A + Bhi + Blo
#define GEMM_SMEM (3 * G_STAGE_B + 64)     // 3 stages + mbarriers

#define TSZ(R, K) ((size_t)(R) * (K) / 32 * 40)

// ---------------------------------------------------------------------------
// Scratch (device globals)
// ---------------------------------------------------------------------------
__device__ float g_res1[NROW * DD];
__device__ float g_y[NROW * DD];
__device__ float g_z[NROW * DD];

// tiled fp16 activations
__device__ __half g_xh[TSZ(NROW, DD)];
__device__ __half g_ath[TSZ(NROW, DD)];
__device__ __half g_yh[TSZ(NROW, DD)];
__device__ __half g_h1h[TSZ(NROW, DFF)];

// head-major fp16 q/k/v (linear) + per-head transposed V
__device__ __half g_qh[BB*HH*SS*HDD];
__device__ __half g_kh[BB*HH*SS*HDD];
__device__ __half g_vh[BB*HH*SS*HDD];
__device__ __half g_vt[BB*HH*SS*HDD];     // [bh][hd][s]

// tiled fp16 hi/lo transposed weights [N, K]
__device__ __half g_wqThi[TSZ(DD, DD)],  g_wqTlo[TSZ(DD, DD)];
__device__ __half g_wkThi[TSZ(DD, DD)],  g_wkTlo[TSZ(DD, DD)];
__device__ __half g_wvThi[TSZ(DD, DD)],  g_wvTlo[TSZ(DD, DD)];
__device__ __half g_woThi[TSZ(DD, DD)],  g_woTlo[TSZ(DD, DD)];
__device__ __half g_w1Thi[TSZ(DFF, DD)], g_w1Tlo[TSZ(DFF, DD)];
__device__ __half g_w2Thi[TSZ(DD, DFF)], g_w2Tlo[TSZ(DD, DFF)];

// ---------------------------------------------------------------------------
// helpers
// ---------------------------------------------------------------------------
__device__ __forceinline__ uint32_t smem_u32(const void* p) {
    uint32_t a;
    asm("{ .reg .u64 t; cvta.to.shared.u64 t, %1; cvt.u32.u64 %0, t; }"
        : "=r"(a) : "l"(p));
    return a;
}
__device__ __forceinline__ void mma16816h(float* d, const uint32_t* a,
                                          uint32_t b0, uint32_t b1) {
    asm volatile(
        "mma.sync.aligned.m16n8k16.row.col.f32.f16.f16.f32 "
        "{%0,%1,%2,%3}, {%4,%5,%6,%7}, {%8,%9}, {%0,%1,%2,%3};"
        : "+f"(d[0]), "+f"(d[1]), "+f"(d[2]), "+f"(d[3])
        : "r"(a[0]), "r"(a[1]), "r"(a[2]), "r"(a[3]), "r"(b0), "r"(b1));
}
__device__ __forceinline__ uint32_t pack_f16(float lo, float hi) {
    uint32_t r;
    asm("cvt.rn.f16x2.f32 %0, %1, %2;" : "=r"(r) : "f"(hi), "f"(lo));
    return r;
}
__device__ __forceinline__ void ldmx4(uint32_t* r, uint32_t addr) {
    asm volatile("ldmatrix.sync.aligned.m8n8.x4.shared.b16 {%0,%1,%2,%3}, [%4];"
                 : "=r"(r[0]), "=r"(r[1]), "=r"(r[2]), "=r"(r[3]) : "r"(addr));
}
__device__ __forceinline__ void mbar_init(uint32_t mbar, uint32_t cnt) {
    asm volatile("mbarrier.init.shared.b64 [%0], %1;" :: "r"(mbar), "r"(cnt) : "memory");
}
__device__ __forceinline__ void mbar_wait(uint32_t mbar, uint32_t parity) {
    asm volatile(
        "{\n\t.reg .pred P;\n\t"
        "WL_%=:\n\t"
        "mbarrier.try_wait.parity.acquire.cta.shared::cta.b64 P, [%0], %1, 0x989680;\n\t"
        "@P bra.uni WD_%=;\n\t"
        "bra.uni WL_%=;\n\t"
        "WD_%=:\n\t}"
        :: "r"(mbar), "r"(parity) : "memory");
}
__device__ __forceinline__ void mbar_expect_tx(uint32_t mbar, uint32_t bytes) {
    asm volatile("mbarrier.arrive.expect_tx.shared.b64 _, [%0], %1;"
                 :: "r"(mbar), "r"(bytes) : "memory");
}
__device__ __forceinline__ void bulkcp(uint32_t dst, const void* src,
                                       uint32_t bytes, uint32_t mbar) {
    asm volatile(
        "cp.async.bulk.shared::cta.global.mbarrier::complete_tx::bytes "
        "[%0], [%1], %2, [%3];"
        :: "r"(dst), "l"(src), "r"(bytes), "r"(mbar) : "memory");
}
__device__ __forceinline__ void cp16(uint32_t dst, const void* src) {
    asm volatile("cp.async.cg.shared.global [%0], [%1], 16;"
                 :: "r"(dst), "l"(src));
}
__device__ __forceinline__ void cp_commit() { asm volatile("cp.async.commit_group;"); }
__device__ __forceinline__ void cp_wait0()  { asm volatile("cp.async.wait_group 0;"); }
__device__ __forceinline__ void cp_wait1()  { asm volatile("cp.async.wait_group 1;"); }

__device__ __forceinline__ size_t toff(int row, int col, int kcn) {
    return (size_t)((row >> 7) * kcn + (col >> 5)) * TILE_HW +
           (row & 127) * PADC + (col & 31);
}

// ---------------------------------------------------------------------------
// fp32 [4096,768] -> tiled fp16
// ---------------------------------------------------------------------------
__global__ void __launch_bounds__(256) convert_h(
    const float* __restrict__ in, __half* __restrict__ oh)
{
    const int i = blockIdx.x * 256 + threadIdx.x;
    const int e = 4 * i;
    const int row = e / DD, col = e - row * DD;
    float4 v = ((const float4*)in)[i];
    const size_t o = toff(row, col, DD / 32);
    *(uint2*)(oh + o) = make_uint2(pack_f16(v.x, v.y), pack_f16(v.z, v.w));
}

// ---------------------------------------------------------------------------
// W[K,N] fp32 -> tiled Wt[N,K] fp16 hi/lo
// ---------------------------------------------------------------------------
__global__ void __launch_bounds__(256) transpose_split_h(
    const float* __restrict__ W, __half* __restrict__ Thi,
    __half* __restrict__ Tlo, int K, int N)
{
    __shared__ float tile[32][33];
    const int k0 = blockIdx.y * 32, n0 = blockIdx.x * 32;
    const int tx = threadIdx.x, ty = threadIdx.y;   // (32, 8)
#pragma unroll
    for (int i = 0; i < 4; i++)
        tile[ty + 8 * i][tx] = W[(size_t)(k0 + ty + 8 * i) * N + n0 + tx];
    __syncthreads();
    const int kcn = K >> 5;
#pragma unroll
    for (int i = 0; i < 4; i++) {
        const float vv = tile[tx][ty + 8 * i];
        const __half h = __float2half_rn(vv);
        const size_t o = toff(n0 + ty + 8 * i, k0 + tx, kcn);
        Thi[o] = h;
        Tlo[o] = __float2half_rn(vv - __half2float(h));
    }
}

// ---------------------------------------------------------------------------
// per-head V transpose: [s, hd] -> [hd, s] (fp16, linear)
// ---------------------------------------------------------------------------
__global__ void __launch_bounds__(256) vtrans_h(
    const __half* __restrict__ in, __half* __restrict__ out)
{
    __shared__ uint16_t sm[64][72];
    const int s0 = blockIdx.x * 64;
    const size_t bh = blockIdx.y;
    const uint16_t* src = (const uint16_t*)(in + bh * SS * HDD);
    uint16_t* dst = (uint16_t*)(out + bh * (size_t)HDD * SS);
    const int t = threadIdx.x;
    const int r = t >> 2, cq = (t & 3) * 16;
    *(uint4*)(&sm[r][cq])     = *(const uint4*)(src + (size_t)(s0 + r) * HDD + cq);
    *(uint4*)(&sm[r][cq + 8]) = *(const uint4*)(src + (size_t)(s0 + r) * HDD + cq + 8);
    __syncthreads();
    uint32_t w[8];
#pragma unroll
    for (int j = 0; j < 8; j++)
        w[j] = ((uint32_t)sm[cq + 2 * j + 1][r] << 16) | sm[cq + 2 * j][r];
#pragma unroll
    for (int j = 0; j < 4; j++)
        *(uint2*)(dst + (size_t)r * SS + s0 + cq + 4 * j) =
            make_uint2(w[2 * j], w[2 * j + 1]);
}

// ---------------------------------------------------------------------------
// fp16 2-pass GEMM: A single fp16, B fp16 hi/lo. 3-stage bulk-DMA pipeline.
// ---------------------------------------------------------------------------
#define M_QKV 0
#define M_WO  1
#define M_FF1 2
#define M_FF2 3

struct PtrQ {
    const __half *bh, *bl;
    const float* bias;
    __half* c;            // fp16 linear head-major
};
struct Qkv3 { PtrQ p[3]; };

template <int MODE>
__global__ void __launch_bounds__(256) gemm_h(
    const __half* __restrict__ A,
    const __half* __restrict__ Bhi_, const __half* __restrict__ Blo_,
    const float* __restrict__ bias_, const float* __restrict__ res,
    float* __restrict__ Cf, __half* __restrict__ Ch_,
    Qkv3 qkv, int M, int N, int K)
{
    extern __shared__ char smem[];
    const uint32_t sb = smem_u32(smem);
    const uint32_t mbb = sb + 3 * G_STAGE_B;

    const int t    = threadIdx.x;
    const int lane = t & 31, wid = t >> 5;
    const int wm   = (wid & 3) * 32;
    const int wn   = (wid >> 2) * 64;
    const int bm   = blockIdx.y * 128, bn = blockIdx.x * 128;
    const int g    = lane >> 2, tig = lane & 3;

    const __half* Bhi;
    const __half* Blo;
    const float* bias;
    __half* Ch = Ch_;
    if (MODE == M_QKV) {
        const PtrQ& p = qkv.p[blockIdx.z];
        Bhi = p.bh; Blo = p.bl; bias = p.bias; Ch = p.c;
    } else {
        Bhi = Bhi_; Blo = Blo_; bias = bias_;
    }

    if (t == 0) { mbar_init(mbb, 1); mbar_init(mbb + 8, 1); mbar_init(mbb + 16, 1); }
    __syncthreads();

    float acc[2][8][4];
#pragma unroll
    for (int i = 0; i < 2; i++)
#pragma unroll
        for (int j = 0; j < 8; j++)
#pragma unroll
            for (int c = 0; c < 4; c++) acc[i][j][c] = 0.f;

    const int KCN = K >> 5;
    const int arb = bm >> 7, brb = bn >> 7;

    auto issue = [&](int c, int stage) {
        if (t == 0) {
            const uint32_t mbar = mbb + stage * 8;
            mbar_expect_tx(mbar, G_STAGE_B);
            const uint32_t d = sb + stage * G_STAGE_B;
            bulkcp(d,              A   + ((size_t)arb * KCN + c) * TILE_HW, TILE_B, mbar);
            bulkcp(d + TILE_B,     Bhi + ((size_t)brb * KCN + c) * TILE_HW, TILE_B, mbar);
            bulkcp(d + 2 * TILE_B, Blo + ((size_t)brb * KCN + c) * TILE_HW, TILE_B, mbar);
        }
    };

    uint32_t ph[3] = {0, 0, 0};
    issue(0, 0);
    if (KCN > 1) issue(1, 1);

    const uint32_t lrow = (uint32_t)(lane & 15);
    const uint32_t lcol = (uint32_t)((lane >> 4) * 8);

    for (int c = 0; c < KCN; c++) {
        if (c + 2 < KCN) issue(c + 2, (c + 2) % 3);
        const int st = c % 3;
        mbar_wait(mbb + st * 8, ph[st]);
        ph[st] ^= 1;

        const uint32_t sbase = sb + st * G_STAGE_B;
        const uint32_t sA   = sbase;
        const uint32_t sBhi = sbase + TILE_B;
        const uint32_t sBlo = sbase + 2 * TILE_B;

#pragma unroll
        for (int kk = 0; kk < CH; kk += 16) {
            uint32_t a[2][4];
            ldmx4(a[0], sA + ((wm + lrow) * PADC + kk + lcol) * 2);
            ldmx4(a[1], sA + ((wm + 16 + lrow) * PADC + kk + lcol) * 2);
#pragma unroll
            for (int p = 0; p < 4; p++) {
                uint32_t bh[4], bl[4];
                ldmx4(bh, sBhi + ((wn + 16 * p + lrow) * PADC + kk + lcol) * 2);
                ldmx4(bl, sBlo + ((wn + 16 * p + lrow) * PADC + kk + lcol) * 2);
#pragma unroll
                for (int q = 0; q < 2; q++) {
                    const int nt = 2 * p + q;
                    mma16816h(acc[0][nt], a[0], bh[q], bh[q + 2]);
                    mma16816h(acc[1][nt], a[1], bh[q], bh[q + 2]);
                    mma16816h(acc[0][nt], a[0], bl[q], bl[q + 2]);
                    mma16816h(acc[1][nt], a[1], bl[q], bl[q + 2]);
                }
            }
        }
        __syncthreads();
    }

    const int okcn = N >> 5;
#pragma unroll
    for (int mt = 0; mt < 2; mt++) {
#pragma unroll
        for (int nt = 0; nt < 8; nt++) {
#pragma unroll
            for (int half = 0; half < 2; half++) {
                const int grow = bm + wm + mt * 16 + g + half * 8;
                const int gcol = bn + wn + nt * 8 + 2 * tig;
                float v0 = acc[mt][nt][half * 2 + 0] + bias[gcol];
                float v1 = acc[mt][nt][half * 2 + 1] + bias[gcol + 1];
                if (MODE == M_QKV) {
                    const int b_ = grow >> 11, s_ = grow & 2047;
                    const int h_ = gcol >> 6,  hd = gcol & 63;
                    *(uint32_t*)(Ch + (((size_t)(b_ * HH + h_) * SS) + s_) * HDD + hd) =
                        pack_f16(v0, v1);
                } else if (MODE == M_FF1) {
                    v0 = fmaxf(v0, 0.f);
                    v1 = fmaxf(v1, 0.f);
                    *(uint32_t*)(Ch + toff(grow, gcol, okcn)) = pack_f16(v0, v1);
                } else {
                    const size_t o = (size_t)grow * N + gcol;
                    v0 += res[o];
                    v1 += res[o + 1];
                    *(float2*)(Cf + o) = make_float2(v0, v1);
                }
            }
        }
    }
}

// ---------------------------------------------------------------------------
// fp16 1-pass tensor-core flash attention, cp.async double-buffered K/V.
// Block: (q-tile 128, h, b); 4 warps, warp = 32 q-rows x full 64 key-cols.
// ---------------------------------------------------------------------------
__global__ void __launch_bounds__(128) attn_tc(
    const float* __restrict__ alibi,
    const __half* __restrict__ Q, const __half* __restrict__ K,
    const __half* __restrict__ Vt, __half* __restrict__ O)
{
    __shared__ __half sk[2][64 * 72];
    __shared__ __half sv[2][64 * 72];

    const int t = threadIdx.x, lane = t & 31, wid = t >> 5;
    const int g = lane >> 2, tig = lane & 3;
    const int qt = (int)(gridDim.x - 1) - (int)blockIdx.x;
    const int h = blockIdx.y, b = blockIdx.z;
    const int q0 = qt * 128, wm = wid * 32;
    const size_t bh = (size_t)(b * HH + h);

    const __half* qb = Q + (bh * SS + q0) * HDD;
    const __half* kb = K + bh * SS * HDD;
    const __half* vb = Vt + bh * (size_t)HDD * SS;
    const float* ab = alibi + (size_t)h * SS * SS;

    // preload Q fragments (loop-invariant): 32 regs
    uint32_t qf[4][2][4];
#pragma unroll
    for (int kc = 0; kc < 4; kc++)
#pragma unroll
        for (int mt = 0; mt < 2; mt++) {
            const int row = wm + mt * 16 + g;
            qf[kc][mt][0] = *(const uint32_t*)(qb + (size_t)row * HDD + kc * 16 + 2 * tig);
            qf[kc][mt][1] = *(const uint32_t*)(qb + (size_t)(row + 8) * HDD + kc * 16 + 2 * tig);
            qf[kc][mt][2] = *(const uint32_t*)(qb + (size_t)row * HDD + kc * 16 + 8 + 2 * tig);
            qf[kc][mt][3] = *(const uint32_t*)(qb + (size_t)(row + 8) * HDD + kc * 16 + 8 + 2 * tig);
        }

    float o[2][8][4];
#pragma unroll
    for (int i = 0; i < 2; i++)
#pragma unroll
        for (int j = 0; j < 8; j++)
#pragma unroll
            for (int c = 0; c < 4; c++) o[i][j][c] = 0.f;
    float mrow[2][2] = {{-1e30f, -1e30f}, {-1e30f, -1e30f}};
    float lrow[2][2] = {{0.f, 0.f}, {0.f, 0.f}};

    const int nkt = 2 * qt + 2;

    // FIXED: full-tile coverage — 512 chunks of 16B (was 256 in R8: NaN bug)
    auto prefetch = [&](int kt, int st) {
        const int k0 = kt * 64;
#pragma unroll
        for (int i = 0; i < 4; i++) {
            const int idx = t + 128 * i;          // 0..511
            const int r = idx >> 3, c = (idx & 7) * 8;
            cp16(smem_u32(&sk[st][r * 72 + c]), kb + (size_t)(k0 + r) * HDD + c);
            cp16(smem_u32(&sv[st][r * 72 + c]), vb + (size_t)r * SS + k0 + c);
        }
        cp_commit();
    };

    prefetch(0, 0);

    for (int kt = 0; kt < nkt; kt++) {
        const int k0 = kt * 64;
        const int st = kt & 1;
        if (kt + 1 < nkt) { prefetch(kt + 1, st ^ 1); cp_wait1(); }
        else              { cp_wait0(); }
        __syncthreads();

        // ---- S = Q@K^T (1 pass) ----
        float sacc[2][8][4];
#pragma unroll
        for (int i = 0; i < 2; i++)
#pragma unroll
            for (int j = 0; j < 8; j++)
#pragma unroll
                for (int c = 0; c < 4; c++) sacc[i][j][c] = 0.f;

#pragma unroll
        for (int kc = 0; kc < 4; kc++)
#pragma unroll
            for (int nt = 0; nt < 8; nt++) {
                const __half* kr = &sk[st][(8 * nt + g) * 72 + kc * 16];
                const uint32_t b0 = *(const uint32_t*)(kr + 2 * tig);
                const uint32_t b1 = *(const uint32_t*)(kr + 8 + 2 * tig);
                mma16816h(sacc[0][nt], qf[kc][0], b0, b1);
                mma16816h(sacc[1][nt], qf[kc][1], b0, b1);
            }

        // ---- alibi + causal + online softmax ----
#pragma unroll
        for (int mt = 0; mt < 2; mt++)
#pragma unroll
            for (int hf = 0; hf < 2; hf++) {
                const int rowg = q0 + wm + 16 * mt + g + 8 * hf;
                const float* arow = ab + (size_t)rowg * SS + k0;
                float mx = -1e30f;
#pragma unroll
                for (int nt = 0; nt < 8; nt++) {
                    const int col = k0 + 8 * nt + 2 * tig;
                    const float2 al2 = *(const float2*)(arow + 8 * nt + 2 * tig);
                    float s0 = fmaf(sacc[mt][nt][2 * hf + 0], 0.125f, al2.x);
                    float s1 = fmaf(sacc[mt][nt][2 * hf + 1], 0.125f, al2.y);
                    if (col > rowg)     s0 = -1e30f;
                    if (col + 1 > rowg) s1 = -1e30f;
                    sacc[mt][nt][2 * hf + 0] = s0;
                    sacc[mt][nt][2 * hf + 1] = s1;
                    mx = fmaxf(mx, fmaxf(s0, s1));
                }
                mx = fmaxf(mx, __shfl_xor_sync(0xffffffffu, mx, 1));
                mx = fmaxf(mx, __shfl_xor_sync(0xffffffffu, mx, 2));
                const float mn = fmaxf(mrow[mt][hf], mx);
                const float corr = __expf(mrow[mt][hf] - mn);
                mrow[mt][hf] = mn;
                lrow[mt][hf] *= corr;
#pragma unroll
                for (int nt = 0; nt < 8; nt++) {
                    o[mt][nt][2 * hf + 0] *= corr;
                    o[mt][nt][2 * hf + 1] *= corr;
                }
                float ls = 0.f;
#pragma unroll
                for (int nt = 0; nt < 8; nt++) {
                    const float p0 = __expf(sacc[mt][nt][2 * hf + 0] - mn);
                    const float p1 = __expf(sacc[mt][nt][2 * hf + 1] - mn);
                    sacc[mt][nt][2 * hf + 0] = p0;
                    sacc[mt][nt][2 * hf + 1] = p1;
                    ls += p0 + p1;
                }
                ls += __shfl_xor_sync(0xffffffffu, ls, 1);
                ls += __shfl_xor_sync(0xffffffffu, ls, 2);
                lrow[mt][hf] += ls;
            }

        // ---- O += P@V (1 pass, P fp16 from regs) ----
#pragma unroll
        for (int kc = 0; kc < 4; kc++) {
            uint32_t ap[2][4];
#pragma unroll
            for (int mt = 0; mt < 2; mt++)
#pragma unroll
                for (int q2 = 0; q2 < 2; q2++) {
                    const float* pp = sacc[mt][2 * kc + q2];
                    ap[mt][2 * q2 + 0] = pack_f16(pp[0], pp[1]);
                    ap[mt][2 * q2 + 1] = pack_f16(pp[2], pp[3]);
                }
#pragma unroll
            for (int nt = 0; nt < 8; nt++) {
                const __half* vr = &sv[st][(8 * nt + g) * 72 + kc * 16];
                const uint32_t b0 = *(const uint32_t*)(vr + 2 * tig);
                const uint32_t b1 = *(const uint32_t*)(vr + 8 + 2 * tig);
                mma16816h(o[0][nt], ap[0], b0, b1);
                mma16816h(o[1][nt], ap[1], b0, b1);
            }
        }
        __syncthreads();
    }

    // ---- epilogue: normalize, write tiled fp16 [b*S+s, D] ----
#pragma unroll
    for (int mt = 0; mt < 2; mt++)
#pragma unroll
        for (int hf = 0; hf < 2; hf++) {
            const float inv = 1.f / lrow[mt][hf];
            const int rowg = b * SS + q0 + wm + 16 * mt + g + 8 * hf;
#pragma unroll
            for (int nt = 0; nt < 8; nt++) {
                const int col = h * HDD + 8 * nt + 2 * tig;
                *(uint32_t*)(O + toff(rowg, col, DD / 32)) =
                    pack_f16(o[mt][nt][2 * hf + 0] * inv,
                             o[mt][nt][2 * hf + 1] * inv);
            }
        }
}

// ---------------------------------------------------------------------------
// LayerNorm; SPLIT emits tiled fp16
// ---------------------------------------------------------------------------
template <bool SPLIT>
__global__ void __launch_bounds__(256) ln_kernel(
    const float* __restrict__ in, const float* __restrict__ gw,
    const float* __restrict__ bw, float* __restrict__ out,
    __half* __restrict__ oh)
{
    const int row = blockIdx.x;
    const int t   = threadIdx.x;
    const float* p = in + (size_t)row * DD;

    const float v0 = p[t], v1 = p[t + 256], v2 = p[t + 512];
    float s  = v0 + v1 + v2;
    float sq = fmaf(v0, v0, fmaf(v1, v1, v2 * v2));

#pragma unroll
    for (int off = 16; off; off >>= 1) {
        s  += __shfl_down_sync(0xffffffffu, s, off);
        sq += __shfl_down_sync(0xffffffffu, sq, off);
    }
    __shared__ float rs[8], rq[8];
    __shared__ float mean_s, inv_s;
    const int w = t >> 5, lane = t & 31;
    if (lane == 0) { rs[w] = s; rq[w] = sq; }
    __syncthreads();
    if (t == 0) {
        float S = 0.f, Q = 0.f;
#pragma unroll
        for (int i = 0; i < 8; i++) { S += rs[i]; Q += rq[i]; }
        const float mean = S * (1.f / 768.f);
        const float var  = Q * (1.f / 768.f) - mean * mean;
        mean_s = mean;
        inv_s  = rsqrtf(var + 1e-5f);
    }
    __syncthreads();
    const float mean = mean_s, inv = inv_s;
    float* po = out + (size_t)row * DD;
#pragma unroll
    for (int j = 0; j < 3; j++) {
        const int  c = t + 256 * j;
        const float vj = (j == 0) ? v0 : (j == 1) ? v1 : v2;
        const float r = fmaf((vj - mean) * inv, gw[c], bw[c]);
        po[c] = r;
        if (SPLIT) oh[toff(row, c, DD / 32)] = __float2half_rn(r);
    }
}

// ---------------------------------------------------------------------------
// Launcher
// ---------------------------------------------------------------------------
extern "C" void kernel_launch(void* const* d_in, const int* in_sizes, int n_in,
                              void* d_out, int out_size)
{
    (void)in_sizes; (void)n_in; (void)out_size;
    const float* x     = (const float*)d_in[0];
    const float* alibi = (const float*)d_in[1];
    const float* Wq = (const float*)d_in[2];  const float* bq = (const float*)d_in[3];
    const float* Wk = (const float*)d_in[4];  const float* bk = (const float*)d_in[5];
    const float* Wv = (const float*)d_in[6];  const float* bv = (const float*)d_in[7];
    const float* Wo = (const float*)d_in[8];  const float* bo = (const float*)d_in[9];
    const float* W1 = (const float*)d_in[10]; const float* b1 = (const float*)d_in[11];
    const float* W2 = (const float*)d_in[12]; const float* b2 = (const float*)d_in[13];
    const float* g1w = (const float*)d_in[14]; const float* be1 = (const float*)d_in[15];
    const float* g2w = (const float*)d_in[16]; const float* be2 = (const float*)d_in[17];
    float* out = (float*)d_out;

    float *r1, *y, *z;
    cudaGetSymbolAddress((void**)&r1, g_res1);
    cudaGetSymbolAddress((void**)&y,  g_y);
    cudaGetSymbolAddress((void**)&z,  g_z);

    __half *xh, *ath, *yh, *h1h, *qh, *kh, *vh, *vt;
    __half *wqh, *wql, *wkh, *wkl, *wvh, *wvl, *woh, *wol, *w1h, *w1l, *w2h, *w2l;
    cudaGetSymbolAddress((void**)&xh,  g_xh);
    cudaGetSymbolAddress((void**)&ath, g_ath);
    cudaGetSymbolAddress((void**)&yh,  g_yh);
    cudaGetSymbolAddress((void**)&h1h, g_h1h);
    cudaGetSymbolAddress((void**)&qh,  g_qh);
    cudaGetSymbolAddress((void**)&kh,  g_kh);
    cudaGetSymbolAddress((void**)&vh,  g_vh);
    cudaGetSymbolAddress((void**)&vt,  g_vt);
    cudaGetSymbolAddress((void**)&wqh, g_wqThi); cudaGetSymbolAddress((void**)&wql, g_wqTlo);
    cudaGetSymbolAddress((void**)&wkh, g_wkThi); cudaGetSymbolAddress((void**)&wkl, g_wkTlo);
    cudaGetSymbolAddress((void**)&wvh, g_wvThi); cudaGetSymbolAddress((void**)&wvl, g_wvTlo);
    cudaGetSymbolAddress((void**)&woh, g_woThi); cudaGetSymbolAddress((void**)&wol, g_woTlo);
    cudaGetSymbolAddress((void**)&w1h, g_w1Thi); cudaGetSymbolAddress((void**)&w1l, g_w1Tlo);
    cudaGetSymbolAddress((void**)&w2h, g_w2Thi); cudaGetSymbolAddress((void**)&w2l, g_w2Tlo);

    cudaFuncSetAttribute(gemm_h<M_QKV>, cudaFuncAttributeMaxDynamicSharedMemorySize, GEMM_SMEM);
    cudaFuncSetAttribute(gemm_h<M_WO>,  cudaFuncAttributeMaxDynamicSharedMemorySize, GEMM_SMEM);
    cudaFuncSetAttribute(gemm_h<M_FF1>, cudaFuncAttributeMaxDynamicSharedMemorySize, GEMM_SMEM);
    cudaFuncSetAttribute(gemm_h<M_FF2>, cudaFuncAttributeMaxDynamicSharedMemorySize, GEMM_SMEM);

    const dim3 tb(32, 8);

    Qkv3 qkv;
    qkv.p[0] = {wqh, wql, bq, qh};
    qkv.p[1] = {wkh, wkl, bk, kh};
    qkv.p[2] = {wvh, wvl, bv, vh};
    Qkv3 dummy = qkv;

    // launches 1-5 (prep), #6 = QKV gemm for ncu capture
    convert_h<<<3072, 256>>>(x, xh);
    transpose_split_h<<<dim3(24, 24), tb>>>(Wq, wqh, wql, DD, DD);
    transpose_split_h<<<dim3(24, 24), tb>>>(Wk, wkh, wkl, DD, DD);
    transpose_split_h<<<dim3(24, 24), tb>>>(Wv, wvh, wvl, DD, DD);
    transpose_split_h<<<dim3(24, 24), tb>>>(Wo, woh, wol, DD, DD);

    gemm_h<M_QKV><<<dim3(6, 32, 3), 256, GEMM_SMEM>>>(
        xh, nullptr, nullptr, nullptr, nullptr, nullptr, nullptr,
        qkv, NROW, DD, DD);

    transpose_split_h<<<dim3(96, 24), tb>>>(W1, w1h, w1l, DD, DFF);
    transpose_split_h<<<dim3(24, 96), tb>>>(W2, w2h, w2l, DFF, DD);

    vtrans_h<<<dim3(32, 24), 256>>>(vh, vt);

    attn_tc<<<dim3(16, 12, 2), 128>>>(alibi, qh, kh, vt, ath);

    gemm_h<M_WO><<<dim3(6, 32), 256, GEMM_SMEM>>>(
        ath, woh, wol, bo, x, r1, nullptr, dummy, NROW, DD, DD);
    ln_kernel<true><<<NROW, 256>>>(r1, g1w, be1, y, yh);

    gemm_h<M_FF1><<<dim3(24, 32), 256, GEMM_SMEM>>>(
        yh, w1h, w1l, b1, nullptr, nullptr, h1h, dummy, NROW, DFF, DD);
    gemm_h<M_FF2><<<dim3(6, 32), 256, GEMM_SMEM>>>(
        h1h, w2h, w2l, b2, y, z, nullptr, dummy, NROW, DD, DFF);
    ln_kernel<false><<<NROW, 256>>>(z, g2w, be2, out, nullptr);
}

// round 10
// speedup vs baseline: 7.0944x; 1.3793x over previous
#include <cuda_runtime.h>
#include <cuda_fp16.h>
#include <cstdint>
#include <cstddef>

// Problem constants
#define BB    2
#define SS    2048
#define DD    768
#define HH    12
#define HDD   64
#define DFF   3072
#define NROW  4096            // B*S

// GEMM tiling: 128x128 CTA tile, K chunks of 32, tiled global layout.
#define CH     32
#define PADC   40
#define TILE_HW 5120
#define TILE_B  10240
#define G_STAGE_B (2 * TILE_B)             // A + B (single-pass fp16)
#define GEMM_SMEM (3 * G_STAGE_B + 64)     // 3 stages + mbarriers

#define TSZ(R, K) ((size_t)(R) * (K) / 32 * 40)

// ---------------------------------------------------------------------------
// Scratch (device globals)
// ---------------------------------------------------------------------------
__device__ float g_res1[NROW * DD];
__device__ float g_y[NROW * DD];
__device__ float g_z[NROW * DD];

// tiled fp16 activations
__device__ __half g_xh[TSZ(NROW, DD)];
__device__ __half g_ath[TSZ(NROW, DD)];
__device__ __half g_yh[TSZ(NROW, DD)];
__device__ __half g_h1h[TSZ(NROW, DFF)];

// head-major fp16 q/k/v (linear) + per-head transposed V
__device__ __half g_qh[BB*HH*SS*HDD];
__device__ __half g_kh[BB*HH*SS*HDD];
__device__ __half g_vh[BB*HH*SS*HDD];
__device__ __half g_vt[BB*HH*SS*HDD];     // [bh][hd][s]

// tiled fp16 transposed weights [N, K] (single precision level)
__device__ __half g_wqT[TSZ(DD, DD)];
__device__ __half g_wkT[TSZ(DD, DD)];
__device__ __half g_wvT[TSZ(DD, DD)];
__device__ __half g_woT[TSZ(DD, DD)];
__device__ __half g_w1T[TSZ(DFF, DD)];
__device__ __half g_w2T[TSZ(DD, DFF)];

// ---------------------------------------------------------------------------
// helpers
// ---------------------------------------------------------------------------
__device__ __forceinline__ uint32_t smem_u32(const void* p) {
    uint32_t a;
    asm("{ .reg .u64 t; cvta.to.shared.u64 t, %1; cvt.u32.u64 %0, t; }"
        : "=r"(a) : "l"(p));
    return a;
}
__device__ __forceinline__ void mma16816h(float* d, const uint32_t* a,
                                          uint32_t b0, uint32_t b1) {
    asm volatile(
        "mma.sync.aligned.m16n8k16.row.col.f32.f16.f16.f32 "
        "{%0,%1,%2,%3}, {%4,%5,%6,%7}, {%8,%9}, {%0,%1,%2,%3};"
        : "+f"(d[0]), "+f"(d[1]), "+f"(d[2]), "+f"(d[3])
        : "r"(a[0]), "r"(a[1]), "r"(a[2]), "r"(a[3]), "r"(b0), "r"(b1));
}
__device__ __forceinline__ uint32_t pack_f16(float lo, float hi) {
    uint32_t r;
    asm("cvt.rn.f16x2.f32 %0, %1, %2;" : "=r"(r) : "f"(hi), "f"(lo));
    return r;
}
__device__ __forceinline__ void ldmx4(uint32_t* r, uint32_t addr) {
    asm volatile("ldmatrix.sync.aligned.m8n8.x4.shared.b16 {%0,%1,%2,%3}, [%4];"
                 : "=r"(r[0]), "=r"(r[1]), "=r"(r[2]), "=r"(r[3]) : "r"(addr));
}
__device__ __forceinline__ void mbar_init(uint32_t mbar, uint32_t cnt) {
    asm volatile("mbarrier.init.shared.b64 [%0], %1;" :: "r"(mbar), "r"(cnt) : "memory");
}
__device__ __forceinline__ void mbar_wait(uint32_t mbar, uint32_t parity) {
    asm volatile(
        "{\n\t.reg .pred P;\n\t"
        "WL_%=:\n\t"
        "mbarrier.try_wait.parity.acquire.cta.shared::cta.b64 P, [%0], %1, 0x989680;\n\t"
        "@P bra.uni WD_%=;\n\t"
        "bra.uni WL_%=;\n\t"
        "WD_%=:\n\t}"
        :: "r"(mbar), "r"(parity) : "memory");
}
__device__ __forceinline__ void mbar_expect_tx(uint32_t mbar, uint32_t bytes) {
    asm volatile("mbarrier.arrive.expect_tx.shared.b64 _, [%0], %1;"
                 :: "r"(mbar), "r"(bytes) : "memory");
}
__device__ __forceinline__ void bulkcp(uint32_t dst, const void* src,
                                       uint32_t bytes, uint32_t mbar) {
    asm volatile(
        "cp.async.bulk.shared::cta.global.mbarrier::complete_tx::bytes "
        "[%0], [%1], %2, [%3];"
        :: "r"(dst), "l"(src), "r"(bytes), "r"(mbar) : "memory");
}
__device__ __forceinline__ void cp16(uint32_t dst, const void* src) {
    asm volatile("cp.async.cg.shared.global [%0], [%1], 16;"
                 :: "r"(dst), "l"(src));
}
__device__ __forceinline__ void cp_commit() { asm volatile("cp.async.commit_group;"); }
__device__ __forceinline__ void cp_wait0()  { asm volatile("cp.async.wait_group 0;"); }
__device__ __forceinline__ void cp_wait1()  { asm volatile("cp.async.wait_group 1;"); }

__device__ __forceinline__ size_t toff(int row, int col, int kcn) {
    return (size_t)((row >> 7) * kcn + (col >> 5)) * TILE_HW +
           (row & 127) * PADC + (col & 31);
}

// ---------------------------------------------------------------------------
// fp32 [4096,768] -> tiled fp16
// ---------------------------------------------------------------------------
__global__ void __launch_bounds__(256) convert_h(
    const float* __restrict__ in, __half* __restrict__ oh)
{
    const int i = blockIdx.x * 256 + threadIdx.x;
    const int e = 4 * i;
    const int row = e / DD, col = e - row * DD;
    float4 v = ((const float4*)in)[i];
    const size_t o = toff(row, col, DD / 32);
    *(uint2*)(oh + o) = make_uint2(pack_f16(v.x, v.y), pack_f16(v.z, v.w));
}

// ---------------------------------------------------------------------------
// W[K,N] fp32 -> tiled Wt[N,K] fp16 (single)
// ---------------------------------------------------------------------------
__global__ void __launch_bounds__(256) transpose_h(
    const float* __restrict__ W, __half* __restrict__ T, int K, int N)
{
    __shared__ float tile[32][33];
    const int k0 = blockIdx.y * 32, n0 = blockIdx.x * 32;
    const int tx = threadIdx.x, ty = threadIdx.y;   // (32, 8)
#pragma unroll
    for (int i = 0; i < 4; i++)
        tile[ty + 8 * i][tx] = W[(size_t)(k0 + ty + 8 * i) * N + n0 + tx];
    __syncthreads();
    const int kcn = K >> 5;
#pragma unroll
    for (int i = 0; i < 4; i++)
        T[toff(n0 + ty + 8 * i, k0 + tx, kcn)] =
            __float2half_rn(tile[tx][ty + 8 * i]);
}

// ---------------------------------------------------------------------------
// per-head V transpose: [s, hd] -> [hd, s] (fp16, linear)
// ---------------------------------------------------------------------------
__global__ void __launch_bounds__(256) vtrans_h(
    const __half* __restrict__ in, __half* __restrict__ out)
{
    __shared__ uint16_t sm[64][72];
    const int s0 = blockIdx.x * 64;
    const size_t bh = blockIdx.y;
    const uint16_t* src = (const uint16_t*)(in + bh * SS * HDD);
    uint16_t* dst = (uint16_t*)(out + bh * (size_t)HDD * SS);
    const int t = threadIdx.x;
    const int r = t >> 2, cq = (t & 3) * 16;
    *(uint4*)(&sm[r][cq])     = *(const uint4*)(src + (size_t)(s0 + r) * HDD + cq);
    *(uint4*)(&sm[r][cq + 8]) = *(const uint4*)(src + (size_t)(s0 + r) * HDD + cq + 8);
    __syncthreads();
    uint32_t w[8];
#pragma unroll
    for (int j = 0; j < 8; j++)
        w[j] = ((uint32_t)sm[cq + 2 * j + 1][r] << 16) | sm[cq + 2 * j][r];
#pragma unroll
    for (int j = 0; j < 4; j++)
        *(uint2*)(dst + (size_t)r * SS + s0 + cq + 4 * j) =
            make_uint2(w[2 * j], w[2 * j + 1]);
}

// ---------------------------------------------------------------------------
// fp16 1-pass GEMM: A fp16, B fp16. 3-stage bulk-DMA pipeline.
// ---------------------------------------------------------------------------
#define M_QKV 0
#define M_WO  1
#define M_FF1 2
#define M_FF2 3

struct PtrQ {
    const __half* b;
    const float* bias;
    __half* c;            // fp16 linear head-major
};
struct Qkv3 { PtrQ p[3]; };

template <int MODE>
__global__ void __launch_bounds__(256) gemm_h(
    const __half* __restrict__ A, const __half* __restrict__ B_,
    const float* __restrict__ bias_, const float* __restrict__ res,
    float* __restrict__ Cf, __half* __restrict__ Ch_,
    Qkv3 qkv, int M, int N, int K)
{
    extern __shared__ char smem[];
    const uint32_t sb = smem_u32(smem);
    const uint32_t mbb = sb + 3 * G_STAGE_B;

    const int t    = threadIdx.x;
    const int lane = t & 31, wid = t >> 5;
    const int wm   = (wid & 3) * 32;
    const int wn   = (wid >> 2) * 64;
    const int bm   = blockIdx.y * 128, bn = blockIdx.x * 128;
    const int g    = lane >> 2, tig = lane & 3;

    const __half* B;
    const float* bias;
    __half* Ch = Ch_;
    if (MODE == M_QKV) {
        const PtrQ& p = qkv.p[blockIdx.z];
        B = p.b; bias = p.bias; Ch = p.c;
    } else {
        B = B_; bias = bias_;
    }

    if (t == 0) { mbar_init(mbb, 1); mbar_init(mbb + 8, 1); mbar_init(mbb + 16, 1); }
    __syncthreads();

    float acc[2][8][4];
#pragma unroll
    for (int i = 0; i < 2; i++)
#pragma unroll
        for (int j = 0; j < 8; j++)
#pragma unroll
            for (int c = 0; c < 4; c++) acc[i][j][c] = 0.f;

    const int KCN = K >> 5;
    const int arb = bm >> 7, brb = bn >> 7;

    auto issue = [&](int c, int stage) {
        if (t == 0) {
            const uint32_t mbar = mbb + stage * 8;
            mbar_expect_tx(mbar, G_STAGE_B);
            const uint32_t d = sb + stage * G_STAGE_B;
            bulkcp(d,          A + ((size_t)arb * KCN + c) * TILE_HW, TILE_B, mbar);
            bulkcp(d + TILE_B, B + ((size_t)brb * KCN + c) * TILE_HW, TILE_B, mbar);
        }
    };

    uint32_t ph[3] = {0, 0, 0};
    issue(0, 0);
    if (KCN > 1) issue(1, 1);

    const uint32_t lrow = (uint32_t)(lane & 15);
    const uint32_t lcol = (uint32_t)((lane >> 4) * 8);

    for (int c = 0; c < KCN; c++) {
        if (c + 2 < KCN) issue(c + 2, (c + 2) % 3);
        const int st = c % 3;
        mbar_wait(mbb + st * 8, ph[st]);
        ph[st] ^= 1;

        const uint32_t sA = sb + st * G_STAGE_B;
        const uint32_t sB = sA + TILE_B;

#pragma unroll
        for (int kk = 0; kk < CH; kk += 16) {
            uint32_t a[2][4];
            ldmx4(a[0], sA + ((wm + lrow) * PADC + kk + lcol) * 2);
            ldmx4(a[1], sA + ((wm + 16 + lrow) * PADC + kk + lcol) * 2);
#pragma unroll
            for (int p = 0; p < 4; p++) {
                uint32_t bf[4];
                ldmx4(bf, sB + ((wn + 16 * p + lrow) * PADC + kk + lcol) * 2);
#pragma unroll
                for (int q = 0; q < 2; q++) {
                    const int nt = 2 * p + q;
                    mma16816h(acc[0][nt], a[0], bf[q], bf[q + 2]);
                    mma16816h(acc[1][nt], a[1], bf[q], bf[q + 2]);
                }
            }
        }
        __syncthreads();
    }

    const int okcn = N >> 5;
#pragma unroll
    for (int mt = 0; mt < 2; mt++) {
#pragma unroll
        for (int nt = 0; nt < 8; nt++) {
#pragma unroll
            for (int half = 0; half < 2; half++) {
                const int grow = bm + wm + mt * 16 + g + half * 8;
                const int gcol = bn + wn + nt * 8 + 2 * tig;
                float v0 = acc[mt][nt][half * 2 + 0] + bias[gcol];
                float v1 = acc[mt][nt][half * 2 + 1] + bias[gcol + 1];
                if (MODE == M_QKV) {
                    const int b_ = grow >> 11, s_ = grow & 2047;
                    const int h_ = gcol >> 6,  hd = gcol & 63;
                    *(uint32_t*)(Ch + (((size_t)(b_ * HH + h_) * SS) + s_) * HDD + hd) =
                        pack_f16(v0, v1);
                } else if (MODE == M_FF1) {
                    v0 = fmaxf(v0, 0.f);
                    v1 = fmaxf(v1, 0.f);
                    *(uint32_t*)(Ch + toff(grow, gcol, okcn)) = pack_f16(v0, v1);
                } else {
                    const size_t o = (size_t)grow * N + gcol;
                    v0 += res[o];
                    v1 += res[o + 1];
                    *(float2*)(Cf + o) = make_float2(v0, v1);
                }
            }
        }
    }
}

// ---------------------------------------------------------------------------
// fp16 1-pass tensor-core flash attention, cp.async double-buffered K/V.
// ---------------------------------------------------------------------------
__global__ void __launch_bounds__(128) attn_tc(
    const float* __restrict__ alibi,
    const __half* __restrict__ Q, const __half* __restrict__ K,
    const __half* __restrict__ Vt, __half* __restrict__ O)
{
    __shared__ __half sk[2][64 * 72];
    __shared__ __half sv[2][64 * 72];

    const int t = threadIdx.x, lane = t & 31, wid = t >> 5;
    const int g = lane >> 2, tig = lane & 3;
    const int qt = (int)(gridDim.x - 1) - (int)blockIdx.x;
    const int h = blockIdx.y, b = blockIdx.z;
    const int q0 = qt * 128, wm = wid * 32;
    const size_t bh = (size_t)(b * HH + h);

    const __half* qb = Q + (bh * SS + q0) * HDD;
    const __half* kb = K + bh * SS * HDD;
    const __half* vb = Vt + bh * (size_t)HDD * SS;
    const float* ab = alibi + (size_t)h * SS * SS;

    uint32_t qf[4][2][4];
#pragma unroll
    for (int kc = 0; kc < 4; kc++)
#pragma unroll
        for (int mt = 0; mt < 2; mt++) {
            const int row = wm + mt * 16 + g;
            qf[kc][mt][0] = *(const uint32_t*)(qb + (size_t)row * HDD + kc * 16 + 2 * tig);
            qf[kc][mt][1] = *(const uint32_t*)(qb + (size_t)(row + 8) * HDD + kc * 16 + 2 * tig);
            qf[kc][mt][2] = *(const uint32_t*)(qb + (size_t)row * HDD + kc * 16 + 8 + 2 * tig);
            qf[kc][mt][3] = *(const uint32_t*)(qb + (size_t)(row + 8) * HDD + kc * 16 + 8 + 2 * tig);
        }

    float o[2][8][4];
#pragma unroll
    for (int i = 0; i < 2; i++)
#pragma unroll
        for (int j = 0; j < 8; j++)
#pragma unroll
            for (int c = 0; c < 4; c++) o[i][j][c] = 0.f;
    float mrow[2][2] = {{-1e30f, -1e30f}, {-1e30f, -1e30f}};
    float lrow[2][2] = {{0.f, 0.f}, {0.f, 0.f}};

    const int nkt = 2 * qt + 2;

    auto prefetch = [&](int kt, int st) {
        const int k0 = kt * 64;
#pragma unroll
        for (int i = 0; i < 4; i++) {
            const int idx = t + 128 * i;          // 0..511
            const int r = idx >> 3, c = (idx & 7) * 8;
            cp16(smem_u32(&sk[st][r * 72 + c]), kb + (size_t)(k0 + r) * HDD + c);
            cp16(smem_u32(&sv[st][r * 72 + c]), vb + (size_t)r * SS + k0 + c);
        }
        cp_commit();
    };

    prefetch(0, 0);

    for (int kt = 0; kt < nkt; kt++) {
        const int k0 = kt * 64;
        const int st = kt & 1;
        if (kt + 1 < nkt) { prefetch(kt + 1, st ^ 1); cp_wait1(); }
        else              { cp_wait0(); }
        __syncthreads();

        float sacc[2][8][4];
#pragma unroll
        for (int i = 0; i < 2; i++)
#pragma unroll
            for (int j = 0; j < 8; j++)
#pragma unroll
                for (int c = 0; c < 4; c++) sacc[i][j][c] = 0.f;

#pragma unroll
        for (int kc = 0; kc < 4; kc++)
#pragma unroll
            for (int nt = 0; nt < 8; nt++) {
                const __half* kr = &sk[st][(8 * nt + g) * 72 + kc * 16];
                const uint32_t b0 = *(const uint32_t*)(kr + 2 * tig);
                const uint32_t b1 = *(const uint32_t*)(kr + 8 + 2 * tig);
                mma16816h(sacc[0][nt], qf[kc][0], b0, b1);
                mma16816h(sacc[1][nt], qf[kc][1], b0, b1);
            }

#pragma unroll
        for (int mt = 0; mt < 2; mt++)
#pragma unroll
            for (int hf = 0; hf < 2; hf++) {
                const int rowg = q0 + wm + 16 * mt + g + 8 * hf;
                const float* arow = ab + (size_t)rowg * SS + k0;
                float mx = -1e30f;
#pragma unroll
                for (int nt = 0; nt < 8; nt++) {
                    const int col = k0 + 8 * nt + 2 * tig;
                    const float2 al2 = *(const float2*)(arow + 8 * nt + 2 * tig);
                    float s0 = fmaf(sacc[mt][nt][2 * hf + 0], 0.125f, al2.x);
                    float s1 = fmaf(sacc[mt][nt][2 * hf + 1], 0.125f, al2.y);
                    if (col > rowg)     s0 = -1e30f;
                    if (col + 1 > rowg) s1 = -1e30f;
                    sacc[mt][nt][2 * hf + 0] = s0;
                    sacc[mt][nt][2 * hf + 1] = s1;
                    mx = fmaxf(mx, fmaxf(s0, s1));
                }
                mx = fmaxf(mx, __shfl_xor_sync(0xffffffffu, mx, 1));
                mx = fmaxf(mx, __shfl_xor_sync(0xffffffffu, mx, 2));
                const float mn = fmaxf(mrow[mt][hf], mx);
                const float corr = __expf(mrow[mt][hf] - mn);
                mrow[mt][hf] = mn;
                lrow[mt][hf] *= corr;
#pragma unroll
                for (int nt = 0; nt < 8; nt++) {
                    o[mt][nt][2 * hf + 0] *= corr;
                    o[mt][nt][2 * hf + 1] *= corr;
                }
                float ls = 0.f;
#pragma unroll
                for (int nt = 0; nt < 8; nt++) {
                    const float p0 = __expf(sacc[mt][nt][2 * hf + 0] - mn);
                    const float p1 = __expf(sacc[mt][nt][2 * hf + 1] - mn);
                    sacc[mt][nt][2 * hf + 0] = p0;
                    sacc[mt][nt][2 * hf + 1] = p1;
                    ls += p0 + p1;
                }
                ls += __shfl_xor_sync(0xffffffffu, ls, 1);
                ls += __shfl_xor_sync(0xffffffffu, ls, 2);
                lrow[mt][hf] += ls;
            }

#pragma unroll
        for (int kc = 0; kc < 4; kc++) {
            uint32_t ap[2][4];
#pragma unroll
            for (int mt = 0; mt < 2; mt++)
#pragma unroll
                for (int q2 = 0; q2 < 2; q2++) {
                    const float* pp = sacc[mt][2 * kc + q2];
                    ap[mt][2 * q2 + 0] = pack_f16(pp[0], pp[1]);
                    ap[mt][2 * q2 + 1] = pack_f16(pp[2], pp[3]);
                }
#pragma unroll
            for (int nt = 0; nt < 8; nt++) {
                const __half* vr = &sv[st][(8 * nt + g) * 72 + kc * 16];
                const uint32_t b0 = *(const uint32_t*)(vr + 2 * tig);
                const uint32_t b1 = *(const uint32_t*)(vr + 8 + 2 * tig);
                mma16816h(o[0][nt], ap[0], b0, b1);
                mma16816h(o[1][nt], ap[1], b0, b1);
            }
        }
        __syncthreads();
    }

#pragma unroll
    for (int mt = 0; mt < 2; mt++)
#pragma unroll
        for (int hf = 0; hf < 2; hf++) {
            const float inv = 1.f / lrow[mt][hf];
            const int rowg = b * SS + q0 + wm + 16 * mt + g + 8 * hf;
#pragma unroll
            for (int nt = 0; nt < 8; nt++) {
                const int col = h * HDD + 8 * nt + 2 * tig;
                *(uint32_t*)(O + toff(rowg, col, DD / 32)) =
                    pack_f16(o[mt][nt][2 * hf + 0] * inv,
                             o[mt][nt][2 * hf + 1] * inv);
            }
        }
}

// ---------------------------------------------------------------------------
// LayerNorm; SPLIT emits tiled fp16
// ---------------------------------------------------------------------------
template <bool SPLIT>
__global__ void __launch_bounds__(256) ln_kernel(
    const float* __restrict__ in, const float* __restrict__ gw,
    const float* __restrict__ bw, float* __restrict__ out,
    __half* __restrict__ oh)
{
    const int row = blockIdx.x;
    const int t   = threadIdx.x;
    const float* p = in + (size_t)row * DD;

    const float v0 = p[t], v1 = p[t + 256], v2 = p[t + 512];
    float s  = v0 + v1 + v2;
    float sq = fmaf(v0, v0, fmaf(v1, v1, v2 * v2));

#pragma unroll
    for (int off = 16; off; off >>= 1) {
        s  += __shfl_down_sync(0xffffffffu, s, off);
        sq += __shfl_down_sync(0xffffffffu, sq, off);
    }
    __shared__ float rs[8], rq[8];
    __shared__ float mean_s, inv_s;
    const int w = t >> 5, lane = t & 31;
    if (lane == 0) { rs[w] = s; rq[w] = sq; }
    __syncthreads();
    if (t == 0) {
        float S = 0.f, Q = 0.f;
#pragma unroll
        for (int i = 0; i < 8; i++) { S += rs[i]; Q += rq[i]; }
        const float mean = S * (1.f / 768.f);
        const float var  = Q * (1.f / 768.f) - mean * mean;
        mean_s = mean;
        inv_s  = rsqrtf(var + 1e-5f);
    }
    __syncthreads();
    const float mean = mean_s, inv = inv_s;
    float* po = out + (size_t)row * DD;
#pragma unroll
    for (int j = 0; j < 3; j++) {
        const int  c = t + 256 * j;
        const float vj = (j == 0) ? v0 : (j == 1) ? v1 : v2;
        const float r = fmaf((vj - mean) * inv, gw[c], bw[c]);
        po[c] = r;
        if (SPLIT) oh[toff(row, c, DD / 32)] = __float2half_rn(r);
    }
}

// ---------------------------------------------------------------------------
// Launcher
// ---------------------------------------------------------------------------
extern "C" void kernel_launch(void* const* d_in, const int* in_sizes, int n_in,
                              void* d_out, int out_size)
{
    (void)in_sizes; (void)n_in; (void)out_size;
    const float* x     = (const float*)d_in[0];
    const float* alibi = (const float*)d_in[1];
    const float* Wq = (const float*)d_in[2];  const float* bq = (const float*)d_in[3];
    const float* Wk = (const float*)d_in[4];  const float* bk = (const float*)d_in[5];
    const float* Wv = (const float*)d_in[6];  const float* bv = (const float*)d_in[7];
    const float* Wo = (const float*)d_in[8];  const float* bo = (const float*)d_in[9];
    const float* W1 = (const float*)d_in[10]; const float* b1 = (const float*)d_in[11];
    const float* W2 = (const float*)d_in[12]; const float* b2 = (const float*)d_in[13];
    const float* g1w = (const float*)d_in[14]; const float* be1 = (const float*)d_in[15];
    const float* g2w = (const float*)d_in[16]; const float* be2 = (const float*)d_in[17];
    float* out = (float*)d_out;

    float *r1, *y, *z;
    cudaGetSymbolAddress((void**)&r1, g_res1);
    cudaGetSymbolAddress((void**)&y,  g_y);
    cudaGetSymbolAddress((void**)&z,  g_z);

    __half *xh, *ath, *yh, *h1h, *qh, *kh, *vh, *vt;
    __half *wq, *wk, *wv, *wo, *w1, *w2;
    cudaGetSymbolAddress((void**)&xh,  g_xh);
    cudaGetSymbolAddress((void**)&ath, g_ath);
    cudaGetSymbolAddress((void**)&yh,  g_yh);
    cudaGetSymbolAddress((void**)&h1h, g_h1h);
    cudaGetSymbolAddress((void**)&qh,  g_qh);
    cudaGetSymbolAddress((void**)&kh,  g_kh);
    cudaGetSymbolAddress((void**)&vh,  g_vh);
    cudaGetSymbolAddress((void**)&vt,  g_vt);
    cudaGetSymbolAddress((void**)&wq, g_wqT);
    cudaGetSymbolAddress((void**)&wk, g_wkT);
    cudaGetSymbolAddress((void**)&wv, g_wvT);
    cudaGetSymbolAddress((void**)&wo, g_woT);
    cudaGetSymbolAddress((void**)&w1, g_w1T);
    cudaGetSymbolAddress((void**)&w2, g_w2T);

    cudaFuncSetAttribute(gemm_h<M_QKV>, cudaFuncAttributeMaxDynamicSharedMemorySize, GEMM_SMEM);
    cudaFuncSetAttribute(gemm_h<M_WO>,  cudaFuncAttributeMaxDynamicSharedMemorySize, GEMM_SMEM);
    cudaFuncSetAttribute(gemm_h<M_FF1>, cudaFuncAttributeMaxDynamicSharedMemorySize, GEMM_SMEM);
    cudaFuncSetAttribute(gemm_h<M_FF2>, cudaFuncAttributeMaxDynamicSharedMemorySize, GEMM_SMEM);

    const dim3 tb(32, 8);

    Qkv3 qkv;
    qkv.p[0] = {wq, bq, qh};
    qkv.p[1] = {wk, bk, kh};
    qkv.p[2] = {wv, bv, vh};
    Qkv3 dummy = qkv;

    // launches 1-5 (prep), #6 = QKV gemm for ncu capture
    convert_h<<<3072, 256>>>(x, xh);
    transpose_h<<<dim3(24, 24), tb>>>(Wq, wq, DD, DD);
    transpose_h<<<dim3(24, 24), tb>>>(Wk, wk, DD, DD);
    transpose_h<<<dim3(24, 24), tb>>>(Wv, wv, DD, DD);
    transpose_h<<<dim3(24, 24), tb>>>(Wo, wo, DD, DD);

    gemm_h<M_QKV><<<dim3(6, 32, 3), 256, GEMM_SMEM>>>(
        xh, nullptr, nullptr, nullptr, nullptr, nullptr,
        qkv, NROW, DD, DD);

    transpose_h<<<dim3(96, 24), tb>>>(W1, w1, DD, DFF);
    transpose_h<<<dim3(24, 96), tb>>>(W2, w2, DFF, DD);

    vtrans_h<<<dim3(32, 24), 256>>>(vh, vt);

    attn_tc<<<dim3(16, 12, 2), 128>>>(alibi, qh, kh, vt, ath);

    gemm_h<M_WO><<<dim3(6, 32), 256, GEMM_SMEM>>>(
        ath, wo, bo, x, r1, nullptr, dummy, NROW, DD, DD);
    ln_kernel<true><<<NROW, 256>>>(r1, g1w, be1, y, yh);

    gemm_h<M_FF1><<<dim3(24, 32), 256, GEMM_SMEM>>>(
        yh, w1, b1, nullptr, nullptr, h1h, dummy, NROW, DFF, DD);
    gemm_h<M_FF2><<<dim3(6, 32), 256, GEMM_SMEM>>>(
        h1h, w2, b2, y, z, nullptr, dummy, NROW, DD, DFF);
    ln_kernel<false><<<NROW, 256>>>(z, g2w, be2, out, nullptr);
}